// round 2
// baseline (speedup 1.0000x reference)
#include <cuda_runtime.h>
#include <math.h>

#define CDIV(a,b) (((a)+(b)-1)/(b))

// Problem constants
constexpr int cN0 = 120000;
constexpr int cN1 = 20000;
constexpr int cN2 = 6000;
constexpr int cN3 = 1600;
constexpr int cB  = 64;
constexpr int cE1 = 480000;
constexpr int cE2 = 144000;
constexpr int cE3 = 38400;

// ---------------- scratch pool (no cudaMalloc allowed) ----------------
constexpr int AL64(int x) { return (x + 63) & ~63; }
constexpr int O_H1   = 0;
constexpr int O_AGG1 = O_H1   + AL64(cN1);
constexpr int O_DEG1 = O_AGG1 + cN1 * 64;
constexpr int O_X1   = O_DEG1 + AL64(cN1);
constexpr int O_H2   = O_X1   + cN1 * 64;
constexpr int O_AGG2 = O_H2   + cN2 * 64;
constexpr int O_DEG2 = O_AGG2 + cN2 * 64;
constexpr int O_X2   = O_DEG2 + AL64(cN2);
constexpr int O_H3   = O_X2   + cN2 * 64;
constexpr int O_AGG3 = O_H3   + cN3 * 64;
constexpr int O_DEG3 = O_AGG3 + cN3 * 128;
constexpr int O_X3   = O_DEG3 + AL64(cN3);
constexpr int O_H4   = O_X3   + cN3 * 128;
constexpr int POOLN  = O_H4   + 512 * 128;

__device__ float4 g_pool4[(POOLN + 3) / 4];
__device__ __forceinline__ float* pool() { return (float*)g_pool4; }

// ---------------- helpers ----------------
__device__ __forceinline__ void atomicMaxFloat(float* addr, float val) {
    if (val >= 0.0f)
        atomicMax((int*)addr, __float_as_int(val));
    else
        atomicMin((unsigned int*)addr, __float_as_uint(val));
}

__device__ __forceinline__ void redAdd4(float* addr, float a, float b, float c, float d) {
    asm volatile("red.global.add.v4.f32 [%0], {%1,%2,%3,%4};"
                 :: "l"(addr), "f"(a), "f"(b), "f"(c), "f"(d) : "memory");
}

__device__ __forceinline__ float eluf(float v) {
    return v > 0.0f ? v : expm1f(v);
}

// ---------------- generic kernels ----------------
__global__ void fill_pool_kernel(int off, float v, int n) {
    int t = blockIdx.x * blockDim.x + threadIdx.x;
    if (t < n) pool()[off + t] = v;
}

// finalize seg-max (-inf -> 0) and zero agg/deg buffers in one pass
__global__ void prep_kernel(int hoff, int hn, int aggoff, int aggn, int degoff, int degn) {
    int t = blockIdx.x * blockDim.x + threadIdx.x;
    float* P = pool();
    if (t < hn) {
        float v = P[hoff + t];
        if (!isfinite(v)) P[hoff + t] = 0.0f;
    }
    if (t < aggn) P[aggoff + t] = 0.0f;
    if (t < degn) P[degoff + t] = 0.0f;
}

__global__ void segmax_x0_kernel(const float* __restrict__ x, const int* __restrict__ cl) {
    int t = blockIdx.x * blockDim.x + threadIdx.x;
    if (t >= cN0) return;
    atomicMaxFloat(pool() + O_H1 + cl[t], x[t]);
}

__global__ void segmax_pool_kernel(int xoff, const int* __restrict__ cl, int outoff,
                                   int ntot, int shift) {
    int t = blockIdx.x * blockDim.x + threadIdx.x;
    if (t >= ntot) return;
    int n = t >> shift;
    int o = t & ((1 << shift) - 1);
    float* P = pool();
    atomicMaxFloat(P + outoff + (cl[n] << shift) + o, P[xoff + t]);
}

// ---------------- spline basis ----------------
// p = pseudo*4; lo = clip(floor(p),0,3); f = p-lo
// basis_s = prod_d (bit_d ? f_d : 1-f_d);  k_s = (lo0+b0) + 5(lo1+b1) + 25(lo2+b2)
__device__ __forceinline__ void load_pseudo(const float* __restrict__ ps, int e,
                                            float g0[2], float g1[2], float g2[2], int& kbase) {
    float p0 = ps[e * 3 + 0] * 4.0f;
    float p1 = ps[e * 3 + 1] * 4.0f;
    float p2 = ps[e * 3 + 2] * 4.0f;
    float lo0 = fmaxf(fminf(floorf(p0), 3.0f), 0.0f);
    float lo1 = fmaxf(fminf(floorf(p1), 3.0f), 0.0f);
    float lo2 = fmaxf(fminf(floorf(p2), 3.0f), 0.0f);
    float f0 = p0 - lo0, f1 = p1 - lo1, f2 = p2 - lo2;
    g0[0] = 1.0f - f0; g0[1] = f0;
    g1[0] = 1.0f - f1; g1[1] = f1;
    g2[0] = 1.0f - f2; g2[1] = f2;
    kbase = (int)lo0 + 5 * (int)lo1 + 25 * (int)lo2;
}

// ---------------- layer 1: in=1, out=64 ; 16 lanes per edge, float4 ----------------
__global__ void edge_conv_l1(const int* __restrict__ edge, const float* __restrict__ ps,
                             const float* __restrict__ W /*125x64*/) {
    int t = blockIdx.x * blockDim.x + threadIdx.x;
    int e = t >> 4;
    if (e >= cE1) return;
    int l16 = t & 15;
    float g0[2], g1[2], g2[2]; int kb;
    load_pseudo(ps, e, g0, g1, g2, kb);
    float a0 = 0.0f, a1 = 0.0f, a2 = 0.0f, a3 = 0.0f;
#pragma unroll
    for (int s = 0; s < 8; s++) {
        float basis = g0[s & 1] * g1[(s >> 1) & 1] * g2[s >> 2];
        int k = kb + (s & 1) + 5 * ((s >> 1) & 1) + 25 * (s >> 2);
        float4 w = *(const float4*)(W + k * 64 + 4 * l16);
        a0 = fmaf(basis, w.x, a0);
        a1 = fmaf(basis, w.y, a1);
        a2 = fmaf(basis, w.z, a2);
        a3 = fmaf(basis, w.w, a3);
    }
    int src = edge[e];
    int dst = edge[cE1 + e];
    float* P = pool();
    float xs = P[O_H1 + src];
    redAdd4(P + O_AGG1 + dst * 64 + 4 * l16, a0 * xs, a1 * xs, a2 * xs, a3 * xs);
    if (l16 == 0) atomicAdd(P + O_DEG1 + dst, 1.0f);
}

__global__ void node_l1(const float* __restrict__ root /*1x64*/, const float* __restrict__ bias) {
    int t = blockIdx.x * blockDim.x + threadIdx.x;
    if (t >= cN1 * 64) return;
    int n = t >> 6, o = t & 63;
    float* P = pool();
    float acc = bias[o] + P[O_AGG1 + t] / fmaxf(P[O_DEG1 + n], 1.0f) + P[O_H1 + n] * root[o];
    P[O_X1 + t] = eluf(acc);
}

// ---------------- layer 2: in=64, out=64 ; warp per edge, half-warp row split ----------------
__global__ void edge_conv_64_64(const int* __restrict__ edge, int E,
                                const float* __restrict__ ps,
                                const float* __restrict__ W /*125x64x64*/,
                                int xoff, int aggoff, int degoff) {
    __shared__ float sx[8][64];
    int gw = (blockIdx.x * blockDim.x + threadIdx.x) >> 5;
    if (gw >= E) return;
    int lane = threadIdx.x & 31;
    int wl = threadIdx.x >> 5;
    int half = lane >> 4;
    int l16 = lane & 15;
    float* P = pool();

    float g0[2], g1[2], g2[2]; int kb;
    load_pseudo(ps, gw, g0, g1, g2, kb);
    int src = edge[gw];
    int dst = edge[E + gw];

    float2 xv = ((const float2*)(P + xoff + src * 64))[lane];
    sx[wl][2 * lane]     = xv.x;
    sx[wl][2 * lane + 1] = xv.y;
    __syncwarp();

    float acc0 = 0.0f, acc1 = 0.0f, acc2 = 0.0f, acc3 = 0.0f;
    for (int s = 0; s < 8; s++) {
        float basis = g0[s & 1] * g1[(s >> 1) & 1] * g2[s >> 2];
        int k = kb + (s & 1) + 5 * ((s >> 1) & 1) + 25 * (s >> 2);
        const float4* wk = (const float4*)(W + k * 4096) + l16;
        float t0 = 0.0f, t1 = 0.0f, t2 = 0.0f, t3 = 0.0f;
#pragma unroll
        for (int ii = 0; ii < 32; ii++) {
            int row = 2 * ii + half;
            float xr = sx[wl][row];
            float4 w = wk[row * 16];
            t0 = fmaf(xr, w.x, t0);
            t1 = fmaf(xr, w.y, t1);
            t2 = fmaf(xr, w.z, t2);
            t3 = fmaf(xr, w.w, t3);
        }
        acc0 = fmaf(basis, t0, acc0);
        acc1 = fmaf(basis, t1, acc1);
        acc2 = fmaf(basis, t2, acc2);
        acc3 = fmaf(basis, t3, acc3);
    }
    // combine even/odd row halves (lane L <- lane L+16)
    acc0 += __shfl_xor_sync(0xffffffffu, acc0, 16);
    acc1 += __shfl_xor_sync(0xffffffffu, acc1, 16);
    acc2 += __shfl_xor_sync(0xffffffffu, acc2, 16);
    acc3 += __shfl_xor_sync(0xffffffffu, acc3, 16);
    if (half == 0)
        redAdd4(P + aggoff + dst * 64 + 4 * l16, acc0, acc1, acc2, acc3);
    if (lane == 0) atomicAdd(P + degoff + dst, 1.0f);
}

// ---------------- layer 3: in=64, out=128 ; warp per edge, float4 lanes ----------------
__global__ void edge_conv_64_128(const int* __restrict__ edge, int E,
                                 const float* __restrict__ ps,
                                 const float* __restrict__ W /*125x64x128*/,
                                 int xoff, int aggoff, int degoff) {
    __shared__ float sx[8][64];
    int gw = (blockIdx.x * blockDim.x + threadIdx.x) >> 5;
    if (gw >= E) return;
    int lane = threadIdx.x & 31;
    int wl = threadIdx.x >> 5;
    float* P = pool();

    float g0[2], g1[2], g2[2]; int kb;
    load_pseudo(ps, gw, g0, g1, g2, kb);
    int src = edge[gw];
    int dst = edge[E + gw];

    float2 xv = ((const float2*)(P + xoff + src * 64))[lane];
    sx[wl][2 * lane]     = xv.x;
    sx[wl][2 * lane + 1] = xv.y;
    __syncwarp();

    float acc0 = 0.0f, acc1 = 0.0f, acc2 = 0.0f, acc3 = 0.0f;
    for (int s = 0; s < 8; s++) {
        float basis = g0[s & 1] * g1[(s >> 1) & 1] * g2[s >> 2];
        int k = kb + (s & 1) + 5 * ((s >> 1) & 1) + 25 * (s >> 2);
        const float4* wk = (const float4*)(W + k * 8192) + lane;
        float t0 = 0.0f, t1 = 0.0f, t2 = 0.0f, t3 = 0.0f;
#pragma unroll 16
        for (int i = 0; i < 64; i++) {
            float xr = sx[wl][i];
            float4 w = wk[i * 32];
            t0 = fmaf(xr, w.x, t0);
            t1 = fmaf(xr, w.y, t1);
            t2 = fmaf(xr, w.z, t2);
            t3 = fmaf(xr, w.w, t3);
        }
        acc0 = fmaf(basis, t0, acc0);
        acc1 = fmaf(basis, t1, acc1);
        acc2 = fmaf(basis, t2, acc2);
        acc3 = fmaf(basis, t3, acc3);
    }
    redAdd4(P + aggoff + dst * 128 + 4 * lane, acc0, acc1, acc2, acc3);
    if (lane == 0) atomicAdd(P + degoff + dst, 1.0f);
}

// ---------------- node update: out = elu(agg/deg + h @ root + b), din=64 ----------------
__global__ void node_dense(int hoff, int aggoff, int degoff, int xoff,
                           const float* __restrict__ root, const float* __restrict__ bias,
                           int ntot, int shift) {
    int t = blockIdx.x * blockDim.x + threadIdx.x;
    if (t >= ntot) return;
    int n = t >> shift;
    int o = t & ((1 << shift) - 1);
    float* P = pool();
    const float* h = P + hoff + n * 64;
    float acc = bias[o] + P[aggoff + t] / fmaxf(P[degoff + n], 1.0f);
#pragma unroll 16
    for (int i = 0; i < 64; i++)
        acc = fmaf(h[i], root[(i << shift) + o], acc);
    P[xoff + t] = eluf(acc);
}

// ---------------- final MLP + log_softmax, one block per batch row ----------------
__global__ void fc_kernel(const float* __restrict__ w1, const float* __restrict__ b1,
                          const float* __restrict__ w2, const float* __restrict__ b2,
                          float* __restrict__ out) {
    __shared__ float xrow[1024];
    __shared__ float hrow[256];
    __shared__ float logits[10];
    __shared__ float red[2];
    int b = blockIdx.x;
    int t = threadIdx.x;  // 256 threads
    float* P = pool();
    for (int i = t; i < 1024; i += 256) xrow[i] = P[O_H4 + b * 1024 + i];
    __syncthreads();

    float acc = b1[t];
#pragma unroll 8
    for (int i = 0; i < 1024; i++)
        acc = fmaf(xrow[i], w1[i * 256 + t], acc);
    hrow[t] = eluf(acc);
    __syncthreads();

    if (t < 10) {
        float a = b2[t];
#pragma unroll 8
        for (int i = 0; i < 256; i++)
            a = fmaf(hrow[i], w2[i * 10 + t], a);
        logits[t] = a;
    }
    __syncthreads();
    if (t == 0) {
        float m = logits[0];
        for (int j = 1; j < 10; j++) m = fmaxf(m, logits[j]);
        float s = 0.0f;
        for (int j = 0; j < 10; j++) s += expf(logits[j] - m);
        red[0] = m;
        red[1] = logf(s);
    }
    __syncthreads();
    if (t < 10) out[b * 10 + t] = logits[t] - red[0] - red[1];
}

// ---------------- host ----------------
extern "C" void kernel_launch(void* const* d_in, const int* in_sizes, int n_in,
                              void* d_out, int out_size) {
    const float* x0      = (const float*)d_in[0];
    const int*   cl0     = (const int*)  d_in[1];
    const int*   edge1   = (const int*)  d_in[2];
    const float* pseudo1 = (const float*)d_in[3];
    const float* W1      = (const float*)d_in[4];
    const float* root1   = (const float*)d_in[5];
    const float* b1      = (const float*)d_in[6];
    const int*   cl1     = (const int*)  d_in[7];
    const int*   edge2   = (const int*)  d_in[8];
    const float* pseudo2 = (const float*)d_in[9];
    const float* W2      = (const float*)d_in[10];
    const float* root2   = (const float*)d_in[11];
    const float* b2      = (const float*)d_in[12];
    const int*   cl2     = (const int*)  d_in[13];
    const int*   edge3   = (const int*)  d_in[14];
    const float* pseudo3 = (const float*)d_in[15];
    const float* W3      = (const float*)d_in[16];
    const float* root3   = (const float*)d_in[17];
    const float* b3      = (const float*)d_in[18];
    const int*   cl3     = (const int*)  d_in[19];
    const float* fc1w    = (const float*)d_in[20];
    const float* fc1b    = (const float*)d_in[21];
    const float* fc2w    = (const float*)d_in[22];
    const float* fc2b    = (const float*)d_in[23];
    float* out = (float*)d_out;

    const int TB = 256;
    const float NEGINF = -INFINITY;

    // ---- stage 0: seg_max(x0, cluster0) -> h1 (N1,1) ----
    fill_pool_kernel<<<CDIV(cN1, TB), TB>>>(O_H1, NEGINF, cN1);
    segmax_x0_kernel<<<CDIV(cN0, TB), TB>>>(x0, cl0);
    prep_kernel<<<CDIV(cN1 * 64, TB), TB>>>(O_H1, cN1, O_AGG1, cN1 * 64, O_DEG1, cN1);

    // ---- layer 1 conv ----
    edge_conv_l1<<<CDIV(cE1 * 16, TB), TB>>>(edge1, pseudo1, W1);
    node_l1<<<CDIV(cN1 * 64, TB), TB>>>(root1, b1);

    // ---- stage 1: seg_max(x1, cluster1) -> h2 (N2,64) ----
    fill_pool_kernel<<<CDIV(cN2 * 64, TB), TB>>>(O_H2, NEGINF, cN2 * 64);
    segmax_pool_kernel<<<CDIV(cN1 * 64, TB), TB>>>(O_X1, cl1, O_H2, cN1 * 64, 6);
    prep_kernel<<<CDIV(cN2 * 64, TB), TB>>>(O_H2, cN2 * 64, O_AGG2, cN2 * 64, O_DEG2, cN2);

    // ---- layer 2 conv ----
    edge_conv_64_64<<<CDIV(cE2 * 32, TB), TB>>>(edge2, cE2, pseudo2, W2, O_H2, O_AGG2, O_DEG2);
    node_dense<<<CDIV(cN2 * 64, TB), TB>>>(O_H2, O_AGG2, O_DEG2, O_X2, root2, b2, cN2 * 64, 6);

    // ---- stage 2: seg_max(x2, cluster2) -> h3 (N3,64) ----
    fill_pool_kernel<<<CDIV(cN3 * 64, TB), TB>>>(O_H3, NEGINF, cN3 * 64);
    segmax_pool_kernel<<<CDIV(cN2 * 64, TB), TB>>>(O_X2, cl2, O_H3, cN2 * 64, 6);
    prep_kernel<<<CDIV(cN3 * 128, TB), TB>>>(O_H3, cN3 * 64, O_AGG3, cN3 * 128, O_DEG3, cN3);

    // ---- layer 3 conv ----
    edge_conv_64_128<<<CDIV(cE3 * 32, TB), TB>>>(edge3, cE3, pseudo3, W3, O_H3, O_AGG3, O_DEG3);
    node_dense<<<CDIV(cN3 * 128, TB), TB>>>(O_H3, O_AGG3, O_DEG3, O_X3, root3, b3, cN3 * 128, 7);

    // ---- stage 3: seg_max(x3, cluster3) -> h4 (512,128) ----
    fill_pool_kernel<<<CDIV(512 * 128, TB), TB>>>(O_H4, NEGINF, 512 * 128);
    segmax_pool_kernel<<<CDIV(cN3 * 128, TB), TB>>>(O_X3, cl3, O_H4, cN3 * 128, 7);
    prep_kernel<<<CDIV(512 * 128, TB), TB>>>(O_H4, 512 * 128, 0, 0, 0, 0);

    // ---- MLP head ----
    fc_kernel<<<cB, 256>>>(fc1w, fc1b, fc2w, fc2b, out);
}

// round 3
// speedup vs baseline: 2.3080x; 2.3080x over previous
#include <cuda_runtime.h>
#include <math.h>

#define CDIV(a,b) (((a)+(b)-1)/(b))

// Problem constants
constexpr int cN0 = 120000;
constexpr int cN1 = 20000;
constexpr int cN2 = 6000;
constexpr int cN3 = 1600;
constexpr int cB  = 64;
constexpr int cE1 = 480000;
constexpr int cE2 = 144000;
constexpr int cE3 = 38400;
constexpr int cK  = 125;

// ---------------- scratch pool (no cudaMalloc allowed) ----------------
constexpr int AL64(int x) { return (x + 63) & ~63; }
constexpr int O_H1   = 0;
constexpr int O_AGG1 = O_H1   + AL64(cN1);
constexpr int O_DEG1 = O_AGG1 + cN1 * 64;
constexpr int O_X1   = O_DEG1 + AL64(cN1);
constexpr int O_H2   = O_X1   + cN1 * 64;
constexpr int O_AGG2 = O_H2   + cN2 * 64;
constexpr int O_DEG2 = O_AGG2 + cN2 * 64;
constexpr int O_X2   = O_DEG2 + AL64(cN2);
constexpr int O_H3   = O_X2   + cN2 * 64;
constexpr int O_AGG3 = O_H3   + cN3 * 64;
constexpr int O_DEG3 = O_AGG3 + cN3 * 128;
constexpr int O_X3   = O_DEG3 + AL64(cN3);
constexpr int O_H4   = O_X3   + cN3 * 128;
constexpr int POOLN  = O_H4   + 512 * 128;

__device__ float4 g_pool4[(POOLN + 3) / 4];
__device__ __forceinline__ float* pool() { return (float*)g_pool4; }

// big XW scratch: XW2[k][n][64] and XW3[k][n][128]
__device__ float4 g_xw2_4[(cK * cN2 * 64) / 4];
__device__ float4 g_xw3_4[(cK * cN3 * 128) / 4];

// ---------------- helpers ----------------
__device__ __forceinline__ void atomicMaxFloat(float* addr, float val) {
    if (val >= 0.0f)
        atomicMax((int*)addr, __float_as_int(val));
    else
        atomicMin((unsigned int*)addr, __float_as_uint(val));
}

__device__ __forceinline__ void redAdd4(float* addr, float a, float b, float c, float d) {
    asm volatile("red.global.add.v4.f32 [%0], {%1,%2,%3,%4};"
                 :: "l"(addr), "f"(a), "f"(b), "f"(c), "f"(d) : "memory");
}
__device__ __forceinline__ void redAdd2(float* addr, float a, float b) {
    asm volatile("red.global.add.v2.f32 [%0], {%1,%2};"
                 :: "l"(addr), "f"(a), "f"(b) : "memory");
}

__device__ __forceinline__ unsigned long long pk2(float x, float y) {
    unsigned long long r;
    asm("mov.b64 %0, {%1,%2};" : "=l"(r) : "f"(x), "f"(y));
    return r;
}
__device__ __forceinline__ void upk2(unsigned long long v, float& x, float& y) {
    asm("mov.b64 {%0,%1}, %2;" : "=f"(x), "=f"(y) : "l"(v));
}
#define FMA2(d, a, b) asm("fma.rn.f32x2 %0, %1, %2, %0;" : "+l"(d) : "l"(a), "l"(b))

__device__ __forceinline__ float eluf(float v) {
    return v > 0.0f ? v : expm1f(v);
}

// ---------------- generic kernels ----------------
__global__ void fill_pool_kernel(int off, float v, int n) {
    int t = blockIdx.x * blockDim.x + threadIdx.x;
    if (t < n) pool()[off + t] = v;
}

__global__ void prep_kernel(int hoff, int hn, int aggoff, int aggn, int degoff, int degn) {
    int t = blockIdx.x * blockDim.x + threadIdx.x;
    float* P = pool();
    if (t < hn) {
        float v = P[hoff + t];
        if (!isfinite(v)) P[hoff + t] = 0.0f;
    }
    if (t < aggn) P[aggoff + t] = 0.0f;
    if (t < degn) P[degoff + t] = 0.0f;
}

__global__ void segmax_x0_kernel(const float* __restrict__ x, const int* __restrict__ cl) {
    int t = blockIdx.x * blockDim.x + threadIdx.x;
    if (t >= cN0) return;
    atomicMaxFloat(pool() + O_H1 + cl[t], x[t]);
}

__global__ void segmax_pool_kernel(int xoff, const int* __restrict__ cl, int outoff,
                                   int ntot, int shift) {
    int t = blockIdx.x * blockDim.x + threadIdx.x;
    if (t >= ntot) return;
    int n = t >> shift;
    int o = t & ((1 << shift) - 1);
    float* P = pool();
    atomicMaxFloat(P + outoff + (cl[n] << shift) + o, P[xoff + t]);
}

// ---------------- spline basis ----------------
__device__ __forceinline__ void load_pseudo(const float* __restrict__ ps, int e,
                                            float g0[2], float g1[2], float g2[2], int& kbase) {
    float p0 = ps[e * 3 + 0] * 4.0f;
    float p1 = ps[e * 3 + 1] * 4.0f;
    float p2 = ps[e * 3 + 2] * 4.0f;
    float lo0 = fmaxf(fminf(floorf(p0), 3.0f), 0.0f);
    float lo1 = fmaxf(fminf(floorf(p1), 3.0f), 0.0f);
    float lo2 = fmaxf(fminf(floorf(p2), 3.0f), 0.0f);
    float f0 = p0 - lo0, f1 = p1 - lo1, f2 = p2 - lo2;
    g0[0] = 1.0f - f0; g0[1] = f0;
    g1[0] = 1.0f - f1; g1[1] = f1;
    g2[0] = 1.0f - f2; g2[1] = f2;
    kbase = (int)lo0 + 5 * (int)lo1 + 25 * (int)lo2;
}

// ---------------- layer 1: in=1, out=64 ; 16 lanes per edge, float4 ----------------
__global__ void edge_conv_l1(const int* __restrict__ edge, const float* __restrict__ ps,
                             const float* __restrict__ W /*125x64*/) {
    int t = blockIdx.x * blockDim.x + threadIdx.x;
    int e = t >> 4;
    if (e >= cE1) return;
    int l16 = t & 15;
    float g0[2], g1[2], g2[2]; int kb;
    load_pseudo(ps, e, g0, g1, g2, kb);
    float a0 = 0.0f, a1 = 0.0f, a2 = 0.0f, a3 = 0.0f;
#pragma unroll
    for (int s = 0; s < 8; s++) {
        float basis = g0[s & 1] * g1[(s >> 1) & 1] * g2[s >> 2];
        int k = kb + (s & 1) + 5 * ((s >> 1) & 1) + 25 * (s >> 2);
        float4 w = *(const float4*)(W + k * 64 + 4 * l16);
        a0 = fmaf(basis, w.x, a0);
        a1 = fmaf(basis, w.y, a1);
        a2 = fmaf(basis, w.z, a2);
        a3 = fmaf(basis, w.w, a3);
    }
    int src = edge[e];
    int dst = edge[cE1 + e];
    float* P = pool();
    float xs = P[O_H1 + src];
    redAdd4(P + O_AGG1 + dst * 64 + 4 * l16, a0 * xs, a1 * xs, a2 * xs, a3 * xs);
    if (l16 == 0) atomicAdd(P + O_DEG1 + dst, 1.0f);
}

__global__ void node_l1(const float* __restrict__ root /*1x64*/, const float* __restrict__ bias) {
    int t = blockIdx.x * blockDim.x + threadIdx.x;
    if (t >= cN1 * 64) return;
    int n = t >> 6, o = t & 63;
    float* P = pool();
    float acc = bias[o] + P[O_AGG1 + t] / fmaxf(P[O_DEG1 + n], 1.0f) + P[O_H1 + n] * root[o];
    P[O_X1 + t] = eluf(acc);
}

// ---------------- batched GEMM: XW[k] = X (Nn x 64) @ W[k] (64 x OT) ----------------
// grid: (CDIV(Nn,MT), 125), 256 threads.
// CT = OT/4 col-threads, RT = 256/CT row-threads, each thread: 8 rows x 4 cols.
// A tile stored TRANSPOSED in smem so ld.shared.v2.u64 yields row-pairs pre-packed
// for fma.rn.f32x2.
template<int MT, int OT>
__global__ void gemm_xw(int xoff, const float* __restrict__ W, float* __restrict__ XW, int Nn) {
    constexpr int CT = OT / 4;
    constexpr int RT = 256 / CT;
    static_assert(MT == RT * 8, "tile shape");
    __shared__ float As[64 * MT];
    __shared__ float Bs[64 * OT];

    int tid = threadIdx.x;
    int k   = blockIdx.y;
    int m0  = blockIdx.x * MT;
    const float* Xg = pool() + xoff;

    // load A tile transposed: As[kk][m] = X[m0+m][kk]
    for (int idx = tid; idx < MT * 16; idx += 256) {
        int m = idx >> 4;
        int q = idx & 15;
        float4 v = make_float4(0.f, 0.f, 0.f, 0.f);
        if (m0 + m < Nn) v = *(const float4*)(Xg + (m0 + m) * 64 + q * 4);
        As[(q * 4 + 0) * MT + m] = v.x;
        As[(q * 4 + 1) * MT + m] = v.y;
        As[(q * 4 + 2) * MT + m] = v.z;
        As[(q * 4 + 3) * MT + m] = v.w;
    }
    // load B = W[k] (64 x OT), same layout
    {
        const float4* Wk = (const float4*)(W + k * 64 * OT);
        float4* B4 = (float4*)Bs;
        for (int idx = tid; idx < (64 * OT) / 4; idx += 256) B4[idx] = Wk[idx];
    }
    __syncthreads();

    int tx = tid % CT;          // col group: cols [tx*4, tx*4+4)
    int ty = tid / CT;          // rows [ty*8, ty*8+8)

    unsigned long long acc[4][4];
#pragma unroll
    for (int i = 0; i < 4; i++)
#pragma unroll
        for (int j = 0; j < 4; j++) acc[i][j] = 0ull;

#pragma unroll 4
    for (int kk = 0; kk < 64; kk++) {
        const ulonglong2* ap = (const ulonglong2*)&As[kk * MT + ty * 8];
        ulonglong2 a01 = ap[0];
        ulonglong2 a23 = ap[1];
        float4 b = *(const float4*)&Bs[kk * OT + tx * 4];
        unsigned long long b0 = pk2(b.x, b.x);
        unsigned long long b1 = pk2(b.y, b.y);
        unsigned long long b2 = pk2(b.z, b.z);
        unsigned long long b3 = pk2(b.w, b.w);
        FMA2(acc[0][0], a01.x, b0); FMA2(acc[0][1], a01.x, b1);
        FMA2(acc[0][2], a01.x, b2); FMA2(acc[0][3], a01.x, b3);
        FMA2(acc[1][0], a01.y, b0); FMA2(acc[1][1], a01.y, b1);
        FMA2(acc[1][2], a01.y, b2); FMA2(acc[1][3], a01.y, b3);
        FMA2(acc[2][0], a23.x, b0); FMA2(acc[2][1], a23.x, b1);
        FMA2(acc[2][2], a23.x, b2); FMA2(acc[2][3], a23.x, b3);
        FMA2(acc[3][0], a23.y, b0); FMA2(acc[3][1], a23.y, b1);
        FMA2(acc[3][2], a23.y, b2); FMA2(acc[3][3], a23.y, b3);
    }

    // epilogue: unpack row pairs, store float4 per row
    float* Ck = XW + (size_t)k * Nn * OT;
#pragma unroll
    for (int rp = 0; rp < 4; rp++) {
        float lo0, hi0, lo1, hi1, lo2, hi2, lo3, hi3;
        upk2(acc[rp][0], lo0, hi0);
        upk2(acc[rp][1], lo1, hi1);
        upk2(acc[rp][2], lo2, hi2);
        upk2(acc[rp][3], lo3, hi3);
        int m = m0 + ty * 8 + 2 * rp;
        if (m < Nn)
            *(float4*)(Ck + (size_t)m * OT + tx * 4) = make_float4(lo0, lo1, lo2, lo3);
        if (m + 1 < Nn)
            *(float4*)(Ck + (size_t)(m + 1) * OT + tx * 4) = make_float4(hi0, hi1, hi2, hi3);
    }
}

// ---------------- gather layer2: warp per edge, 2 outputs/lane ----------------
__global__ void gather_64(const int* __restrict__ edge, int E, const float* __restrict__ ps,
                          const float* __restrict__ XW, int Nn, int aggoff, int degoff) {
    int gw = (blockIdx.x * blockDim.x + threadIdx.x) >> 5;
    if (gw >= E) return;
    int lane = threadIdx.x & 31;
    float g0[2], g1[2], g2[2]; int kb;
    load_pseudo(ps, gw, g0, g1, g2, kb);
    int src = edge[gw];
    int dst = edge[E + gw];
    float ax = 0.0f, ay = 0.0f;
#pragma unroll
    for (int s = 0; s < 8; s++) {
        float basis = g0[s & 1] * g1[(s >> 1) & 1] * g2[s >> 2];
        int k = kb + (s & 1) + 5 * ((s >> 1) & 1) + 25 * (s >> 2);
        float2 v = *((const float2*)(XW + ((size_t)k * Nn + src) * 64) + lane);
        ax = fmaf(basis, v.x, ax);
        ay = fmaf(basis, v.y, ay);
    }
    float* P = pool();
    redAdd2(P + aggoff + dst * 64 + 2 * lane, ax, ay);
    if (lane == 0) atomicAdd(P + degoff + dst, 1.0f);
}

// ---------------- gather layer3: warp per edge, 4 outputs/lane ----------------
__global__ void gather_128(const int* __restrict__ edge, int E, const float* __restrict__ ps,
                           const float* __restrict__ XW, int Nn, int aggoff, int degoff) {
    int gw = (blockIdx.x * blockDim.x + threadIdx.x) >> 5;
    if (gw >= E) return;
    int lane = threadIdx.x & 31;
    float g0[2], g1[2], g2[2]; int kb;
    load_pseudo(ps, gw, g0, g1, g2, kb);
    int src = edge[gw];
    int dst = edge[E + gw];
    float a0 = 0.0f, a1 = 0.0f, a2 = 0.0f, a3 = 0.0f;
#pragma unroll
    for (int s = 0; s < 8; s++) {
        float basis = g0[s & 1] * g1[(s >> 1) & 1] * g2[s >> 2];
        int k = kb + (s & 1) + 5 * ((s >> 1) & 1) + 25 * (s >> 2);
        float4 v = *((const float4*)(XW + ((size_t)k * Nn + src) * 128) + lane);
        a0 = fmaf(basis, v.x, a0);
        a1 = fmaf(basis, v.y, a1);
        a2 = fmaf(basis, v.z, a2);
        a3 = fmaf(basis, v.w, a3);
    }
    float* P = pool();
    redAdd4(P + aggoff + dst * 128 + 4 * lane, a0, a1, a2, a3);
    if (lane == 0) atomicAdd(P + degoff + dst, 1.0f);
}

// ---------------- node update: out = elu(agg/deg + h @ root + b), din=64 ----------------
__global__ void node_dense(int hoff, int aggoff, int degoff, int xoff,
                           const float* __restrict__ root, const float* __restrict__ bias,
                           int ntot, int shift) {
    int t = blockIdx.x * blockDim.x + threadIdx.x;
    if (t >= ntot) return;
    int n = t >> shift;
    int o = t & ((1 << shift) - 1);
    float* P = pool();
    const float* h = P + hoff + n * 64;
    float acc = bias[o] + P[aggoff + t] / fmaxf(P[degoff + n], 1.0f);
#pragma unroll 16
    for (int i = 0; i < 64; i++)
        acc = fmaf(h[i], root[(i << shift) + o], acc);
    P[xoff + t] = eluf(acc);
}

// ---------------- final MLP + log_softmax, one block per batch row ----------------
__global__ void fc_kernel(const float* __restrict__ w1, const float* __restrict__ b1,
                          const float* __restrict__ w2, const float* __restrict__ b2,
                          float* __restrict__ out) {
    __shared__ float xrow[1024];
    __shared__ float hrow[256];
    __shared__ float logits[10];
    __shared__ float red[2];
    int b = blockIdx.x;
    int t = threadIdx.x;  // 256 threads
    float* P = pool();
    for (int i = t; i < 1024; i += 256) xrow[i] = P[O_H4 + b * 1024 + i];
    __syncthreads();

    float acc = b1[t];
#pragma unroll 8
    for (int i = 0; i < 1024; i++)
        acc = fmaf(xrow[i], w1[i * 256 + t], acc);
    hrow[t] = eluf(acc);
    __syncthreads();

    if (t < 10) {
        float a = b2[t];
#pragma unroll 8
        for (int i = 0; i < 256; i++)
            a = fmaf(hrow[i], w2[i * 10 + t], a);
        logits[t] = a;
    }
    __syncthreads();
    if (t == 0) {
        float m = logits[0];
        for (int j = 1; j < 10; j++) m = fmaxf(m, logits[j]);
        float s = 0.0f;
        for (int j = 0; j < 10; j++) s += expf(logits[j] - m);
        red[0] = m;
        red[1] = logf(s);
    }
    __syncthreads();
    if (t < 10) out[b * 10 + t] = logits[t] - red[0] - red[1];
}

// ---------------- host ----------------
extern "C" void kernel_launch(void* const* d_in, const int* in_sizes, int n_in,
                              void* d_out, int out_size) {
    const float* x0      = (const float*)d_in[0];
    const int*   cl0     = (const int*)  d_in[1];
    const int*   edge1   = (const int*)  d_in[2];
    const float* pseudo1 = (const float*)d_in[3];
    const float* W1      = (const float*)d_in[4];
    const float* root1   = (const float*)d_in[5];
    const float* b1      = (const float*)d_in[6];
    const int*   cl1     = (const int*)  d_in[7];
    const int*   edge2   = (const int*)  d_in[8];
    const float* pseudo2 = (const float*)d_in[9];
    const float* W2      = (const float*)d_in[10];
    const float* root2   = (const float*)d_in[11];
    const float* b2      = (const float*)d_in[12];
    const int*   cl2     = (const int*)  d_in[13];
    const int*   edge3   = (const int*)  d_in[14];
    const float* pseudo3 = (const float*)d_in[15];
    const float* W3      = (const float*)d_in[16];
    const float* root3   = (const float*)d_in[17];
    const float* b3      = (const float*)d_in[18];
    const int*   cl3     = (const int*)  d_in[19];
    const float* fc1w    = (const float*)d_in[20];
    const float* fc1b    = (const float*)d_in[21];
    const float* fc2w    = (const float*)d_in[22];
    const float* fc2b    = (const float*)d_in[23];
    float* out = (float*)d_out;

    const int TB = 256;
    const float NEGINF = -INFINITY;

    float* xw2;
    float* xw3;
    cudaGetSymbolAddress((void**)&xw2, g_xw2_4);
    cudaGetSymbolAddress((void**)&xw3, g_xw3_4);

    // ---- stage 0: seg_max(x0, cluster0) -> h1 (N1,1) ----
    fill_pool_kernel<<<CDIV(cN1, TB), TB>>>(O_H1, NEGINF, cN1);
    segmax_x0_kernel<<<CDIV(cN0, TB), TB>>>(x0, cl0);
    prep_kernel<<<CDIV(cN1 * 64, TB), TB>>>(O_H1, cN1, O_AGG1, cN1 * 64, O_DEG1, cN1);

    // ---- layer 1 conv ----
    edge_conv_l1<<<CDIV(cE1 * 16, TB), TB>>>(edge1, pseudo1, W1);
    node_l1<<<CDIV(cN1 * 64, TB), TB>>>(root1, b1);

    // ---- stage 1: seg_max(x1, cluster1) -> h2 (N2,64) ----
    fill_pool_kernel<<<CDIV(cN2 * 64, TB), TB>>>(O_H2, NEGINF, cN2 * 64);
    segmax_pool_kernel<<<CDIV(cN1 * 64, TB), TB>>>(O_X1, cl1, O_H2, cN1 * 64, 6);
    prep_kernel<<<CDIV(cN2 * 64, TB), TB>>>(O_H2, cN2 * 64, O_AGG2, cN2 * 64, O_DEG2, cN2);

    // ---- layer 2: batched GEMM + gather ----
    {
        dim3 g(CDIV(cN2, 128), cK);
        gemm_xw<128, 64><<<g, 256>>>(O_H2, W2, xw2, cN2);
    }
    gather_64<<<CDIV(cE2 * 32, TB), TB>>>(edge2, cE2, pseudo2, xw2, cN2, O_AGG2, O_DEG2);
    node_dense<<<CDIV(cN2 * 64, TB), TB>>>(O_H2, O_AGG2, O_DEG2, O_X2, root2, b2, cN2 * 64, 6);

    // ---- stage 2: seg_max(x2, cluster2) -> h3 (N3,64) ----
    fill_pool_kernel<<<CDIV(cN3 * 64, TB), TB>>>(O_H3, NEGINF, cN3 * 64);
    segmax_pool_kernel<<<CDIV(cN2 * 64, TB), TB>>>(O_X2, cl2, O_H3, cN2 * 64, 6);
    prep_kernel<<<CDIV(cN3 * 128, TB), TB>>>(O_H3, cN3 * 64, O_AGG3, cN3 * 128, O_DEG3, cN3);

    // ---- layer 3: batched GEMM + gather ----
    {
        dim3 g(CDIV(cN3, 64), cK);
        gemm_xw<64, 128><<<g, 256>>>(O_H3, W3, xw3, cN3);
    }
    gather_128<<<CDIV(cE3 * 32, TB), TB>>>(edge3, cE3, pseudo3, xw3, cN3, O_AGG3, O_DEG3);
    node_dense<<<CDIV(cN3 * 128, TB), TB>>>(O_H3, O_AGG3, O_DEG3, O_X3, root3, b3, cN3 * 128, 7);

    // ---- stage 3: seg_max(x3, cluster3) -> h4 (512,128) ----
    fill_pool_kernel<<<CDIV(512 * 128, TB), TB>>>(O_H4, NEGINF, 512 * 128);
    segmax_pool_kernel<<<CDIV(cN3 * 128, TB), TB>>>(O_X3, cl3, O_H4, cN3 * 128, 7);
    prep_kernel<<<CDIV(512 * 128, TB), TB>>>(O_H4, 512 * 128, 0, 0, 0, 0);

    // ---- MLP head ----
    fc_kernel<<<cB, 256>>>(fc1w, fc1b, fc2w, fc2b, out);
}

// round 4
// speedup vs baseline: 2.3572x; 1.0213x over previous
#include <cuda_runtime.h>
#include <math.h>

#define CDIV(a,b) (((a)+(b)-1)/(b))

// Problem constants
constexpr int cN0 = 120000;
constexpr int cN1 = 20000;
constexpr int cN2 = 6000;
constexpr int cN3 = 1600;
constexpr int cB  = 64;
constexpr int cE1 = 480000;
constexpr int cE2 = 144000;
constexpr int cE3 = 38400;
constexpr int cK  = 125;

// ---------------- scratch pool (no cudaMalloc allowed) ----------------
constexpr int AL64(int x) { return (x + 63) & ~63; }
constexpr int O_H1   = 0;
constexpr int O_C1   = O_H1   + AL64(cN1);      // c[dst][128] (125 used)
constexpr int O_DEG1 = O_C1   + cN1 * 128;
constexpr int O_X1   = O_DEG1 + AL64(cN1);
constexpr int O_H2   = O_X1   + cN1 * 64;
constexpr int O_AGG2 = O_H2   + cN2 * 64;
constexpr int O_DEG2 = O_AGG2 + cN2 * 64;
constexpr int O_X2   = O_DEG2 + AL64(cN2);
constexpr int O_H3   = O_X2   + cN2 * 64;
constexpr int O_AGG3 = O_H3   + cN3 * 64;
constexpr int O_DEG3 = O_AGG3 + cN3 * 128;
constexpr int O_X3   = O_DEG3 + AL64(cN3);
constexpr int O_H4   = O_X3   + cN3 * 128;
constexpr int POOLN  = O_H4   + 512 * 128;

__device__ float4 g_pool4[(POOLN + 3) / 4];
__device__ __forceinline__ float* pool() { return (float*)g_pool4; }

// big XW scratch: XW2[k][n][64] and XW3[k][n][128]
__device__ float4 g_xw2_4[(cK * cN2 * 64) / 4];
__device__ float4 g_xw3_4[(cK * cN3 * 128) / 4];

// ---------------- helpers ----------------
__device__ __forceinline__ void atomicMaxFloat(float* addr, float val) {
    if (val >= 0.0f)
        atomicMax((int*)addr, __float_as_int(val));
    else
        atomicMin((unsigned int*)addr, __float_as_uint(val));
}

__device__ __forceinline__ void redAdd4(float* addr, float a, float b, float c, float d) {
    asm volatile("red.global.add.v4.f32 [%0], {%1,%2,%3,%4};"
                 :: "l"(addr), "f"(a), "f"(b), "f"(c), "f"(d) : "memory");
}
__device__ __forceinline__ void redAdd2(float* addr, float a, float b) {
    asm volatile("red.global.add.v2.f32 [%0], {%1,%2};"
                 :: "l"(addr), "f"(a), "f"(b) : "memory");
}

__device__ __forceinline__ unsigned long long pk2(float x, float y) {
    unsigned long long r;
    asm("mov.b64 %0, {%1,%2};" : "=l"(r) : "f"(x), "f"(y));
    return r;
}
__device__ __forceinline__ void upk2(unsigned long long v, float& x, float& y) {
    asm("mov.b64 {%0,%1}, %2;" : "=f"(x), "=f"(y) : "l"(v));
}
#define FMA2(d, a, b) asm("fma.rn.f32x2 %0, %1, %2, %0;" : "+l"(d) : "l"(a), "l"(b))

__device__ __forceinline__ float eluf(float v) {
    return v > 0.0f ? v : expm1f(v);
}
__device__ __forceinline__ float fixf(float v) {
    return isfinite(v) ? v : 0.0f;
}
__device__ __forceinline__ float4 fix4(float4 v) {
    v.x = fixf(v.x); v.y = fixf(v.y); v.z = fixf(v.z); v.w = fixf(v.w);
    return v;
}

// ---------------- one-shot init: -inf seg-max buffers, zero accumulators ----------------
__global__ void init_all() {
    float* P = pool();
    const float NI = -INFINITY;
    int t = blockIdx.x * blockDim.x + threadIdx.x;
    int stride = gridDim.x * blockDim.x;
    for (int i = t; i < cN1; i += stride) P[O_H1 + i] = NI;
    for (int i = t; i < cN2 * 64; i += stride) P[O_H2 + i] = NI;
    for (int i = t; i < cN3 * 64; i += stride) P[O_H3 + i] = NI;
    for (int i = t; i < 512 * 128; i += stride) P[O_H4 + i] = NI;
    for (int i = t; i < cN1 * 128; i += stride) P[O_C1 + i] = 0.0f;
    for (int i = t; i < cN1; i += stride) P[O_DEG1 + i] = 0.0f;
    for (int i = t; i < cN2 * 64; i += stride) P[O_AGG2 + i] = 0.0f;
    for (int i = t; i < cN2; i += stride) P[O_DEG2 + i] = 0.0f;
    for (int i = t; i < cN3 * 128; i += stride) P[O_AGG3 + i] = 0.0f;
    for (int i = t; i < cN3; i += stride) P[O_DEG3 + i] = 0.0f;
}

__global__ void segmax_x0_kernel(const float* __restrict__ x, const int* __restrict__ cl) {
    int t = blockIdx.x * blockDim.x + threadIdx.x;
    if (t >= cN0) return;
    atomicMaxFloat(pool() + O_H1 + cl[t], x[t]);
}

__global__ void segmax_pool_kernel(int xoff, const int* __restrict__ cl, int outoff,
                                   int ntot, int shift) {
    int t = blockIdx.x * blockDim.x + threadIdx.x;
    if (t >= ntot) return;
    int n = t >> shift;
    int o = t & ((1 << shift) - 1);
    float* P = pool();
    atomicMaxFloat(P + outoff + (cl[n] << shift) + o, P[xoff + t]);
}

// ---------------- spline basis ----------------
__device__ __forceinline__ void load_pseudo(const float* __restrict__ ps, int e,
                                            float g0[2], float g1[2], float g2[2], int& kbase) {
    float p0 = ps[e * 3 + 0] * 4.0f;
    float p1 = ps[e * 3 + 1] * 4.0f;
    float p2 = ps[e * 3 + 2] * 4.0f;
    float lo0 = fmaxf(fminf(floorf(p0), 3.0f), 0.0f);
    float lo1 = fmaxf(fminf(floorf(p1), 3.0f), 0.0f);
    float lo2 = fmaxf(fminf(floorf(p2), 3.0f), 0.0f);
    float f0 = p0 - lo0, f1 = p1 - lo1, f2 = p2 - lo2;
    g0[0] = 1.0f - f0; g0[1] = f0;
    g1[0] = 1.0f - f1; g1[1] = f1;
    g2[0] = 1.0f - f2; g2[1] = f2;
    kbase = (int)lo0 + 5 * (int)lo1 + 25 * (int)lo2;
}

// ---------------- layer 1 scatter: c[dst][k] += basis * x_src ----------------
__global__ void l1_scatter(const int* __restrict__ edge, const float* __restrict__ ps) {
    int e = blockIdx.x * blockDim.x + threadIdx.x;
    if (e >= cE1) return;
    float g0[2], g1[2], g2[2]; int kb;
    load_pseudo(ps, e, g0, g1, g2, kb);
    int src = edge[e];
    int dst = edge[cE1 + e];
    float* P = pool();
    float xs = fixf(P[O_H1 + src]);
    float* c = P + O_C1 + dst * 128 + kb;
#pragma unroll
    for (int s = 0; s < 8; s++) {
        float basis = g0[s & 1] * g1[(s >> 1) & 1] * g2[s >> 2];
        int ko = (s & 1) + 5 * ((s >> 1) & 1) + 25 * (s >> 2);
        atomicAdd(c + ko, basis * xs);
    }
    atomicAdd(P + O_DEG1 + dst, 1.0f);
}

// ---------------- layer 1 GEMM + fused node update ----------------
// X1 = elu( (C1 @ W1)/deg + h1*root + b ),  C1: N1 x 128 (K=125 padded), W1: 125x64
__global__ void l1_gemm(const float* __restrict__ W1, const float* __restrict__ root1,
                        const float* __restrict__ b1) {
    __shared__ float As[64 * 64];   // [kk][m] transposed
    __shared__ float Bs[64 * 64];   // [kk][o]
    int tid = threadIdx.x;
    int m0  = blockIdx.x * 64;
    float* P = pool();

    int tx = tid % 16;          // cols tx*4 .. +3
    int ty = tid / 16;          // rows ty*4 .. +3

    unsigned long long acc[2][4];
#pragma unroll
    for (int i = 0; i < 2; i++)
#pragma unroll
        for (int j = 0; j < 4; j++) acc[i][j] = 0ull;

    for (int ch = 0; ch < 2; ch++) {
        __syncthreads();
        // A tile: As[kk][m] = C1[(m0+m)*128 + ch*64 + kk]
        for (int idx = tid; idx < 64 * 16; idx += 256) {
            int m = idx >> 4;
            int q = idx & 15;
            float4 v = make_float4(0.f, 0.f, 0.f, 0.f);
            if (m0 + m < cN1) v = *(const float4*)(P + O_C1 + (m0 + m) * 128 + ch * 64 + q * 4);
            As[(q * 4 + 0) * 64 + m] = v.x;
            As[(q * 4 + 1) * 64 + m] = v.y;
            As[(q * 4 + 2) * 64 + m] = v.z;
            As[(q * 4 + 3) * 64 + m] = v.w;
        }
        // B tile: Bs[kk][o] = W1[(ch*64+kk)*64 + o] (rows >=125 zero)
        for (int idx = tid; idx < 64 * 16; idx += 256) {
            int kk = idx >> 4;
            int o4 = idx & 15;
            int g = ch * 64 + kk;
            float4 v = make_float4(0.f, 0.f, 0.f, 0.f);
            if (g < cK) v = *(const float4*)(W1 + g * 64 + o4 * 4);
            *(float4*)&Bs[kk * 64 + o4 * 4] = v;
        }
        __syncthreads();

#pragma unroll 4
        for (int kk = 0; kk < 64; kk++) {
            ulonglong2 a01 = *(const ulonglong2*)&As[kk * 64 + ty * 4];
            float4 b = *(const float4*)&Bs[kk * 64 + tx * 4];
            unsigned long long b0 = pk2(b.x, b.x);
            unsigned long long b1v = pk2(b.y, b.y);
            unsigned long long b2 = pk2(b.z, b.z);
            unsigned long long b3 = pk2(b.w, b.w);
            FMA2(acc[0][0], a01.x, b0); FMA2(acc[0][1], a01.x, b1v);
            FMA2(acc[0][2], a01.x, b2); FMA2(acc[0][3], a01.x, b3);
            FMA2(acc[1][0], a01.y, b0); FMA2(acc[1][1], a01.y, b1v);
            FMA2(acc[1][2], a01.y, b2); FMA2(acc[1][3], a01.y, b3);
        }
    }

    // epilogue
    float4 rt4 = *(const float4*)(root1 + tx * 4);
    float4 bb4 = *(const float4*)(b1 + tx * 4);
#pragma unroll
    for (int rp = 0; rp < 2; rp++) {
        float lo0, hi0, lo1, hi1, lo2, hi2, lo3, hi3;
        upk2(acc[rp][0], lo0, hi0);
        upk2(acc[rp][1], lo1, hi1);
        upk2(acc[rp][2], lo2, hi2);
        upk2(acc[rp][3], lo3, hi3);
        int m = m0 + ty * 4 + 2 * rp;
        if (m < cN1) {
            float invd = 1.0f / fmaxf(P[O_DEG1 + m], 1.0f);
            float h = fixf(P[O_H1 + m]);
            float4 r;
            r.x = eluf(lo0 * invd + h * rt4.x + bb4.x);
            r.y = eluf(lo1 * invd + h * rt4.y + bb4.y);
            r.z = eluf(lo2 * invd + h * rt4.z + bb4.z);
            r.w = eluf(lo3 * invd + h * rt4.w + bb4.w);
            *(float4*)(P + O_X1 + m * 64 + tx * 4) = r;
        }
        if (m + 1 < cN1) {
            float invd = 1.0f / fmaxf(P[O_DEG1 + m + 1], 1.0f);
            float h = fixf(P[O_H1 + m + 1]);
            float4 r;
            r.x = eluf(hi0 * invd + h * rt4.x + bb4.x);
            r.y = eluf(hi1 * invd + h * rt4.y + bb4.y);
            r.z = eluf(hi2 * invd + h * rt4.z + bb4.z);
            r.w = eluf(hi3 * invd + h * rt4.w + bb4.w);
            *(float4*)(P + O_X1 + (m + 1) * 64 + tx * 4) = r;
        }
    }
}

// ---------------- batched GEMM: XW[k] = fix(X) (Nn x 64) @ W[k] (64 x OT) ----------------
template<int MT, int OT>
__global__ void gemm_xw(int xoff, const float* __restrict__ W, float* __restrict__ XW, int Nn) {
    constexpr int CT = OT / 4;
    constexpr int RT = 256 / CT;
    static_assert(MT == RT * 8, "tile shape");
    __shared__ float As[64 * MT];
    __shared__ float Bs[64 * OT];

    int tid = threadIdx.x;
    int k   = blockIdx.y;
    int m0  = blockIdx.x * MT;
    const float* Xg = pool() + xoff;

    // load A tile transposed (with -inf -> 0 fix): As[kk][m] = fix(X[m0+m][kk])
    for (int idx = tid; idx < MT * 16; idx += 256) {
        int m = idx >> 4;
        int q = idx & 15;
        float4 v = make_float4(0.f, 0.f, 0.f, 0.f);
        if (m0 + m < Nn) v = fix4(*(const float4*)(Xg + (m0 + m) * 64 + q * 4));
        As[(q * 4 + 0) * MT + m] = v.x;
        As[(q * 4 + 1) * MT + m] = v.y;
        As[(q * 4 + 2) * MT + m] = v.z;
        As[(q * 4 + 3) * MT + m] = v.w;
    }
    {
        const float4* Wk = (const float4*)(W + k * 64 * OT);
        float4* B4 = (float4*)Bs;
        for (int idx = tid; idx < (64 * OT) / 4; idx += 256) B4[idx] = Wk[idx];
    }
    __syncthreads();

    int tx = tid % CT;
    int ty = tid / CT;

    unsigned long long acc[4][4];
#pragma unroll
    for (int i = 0; i < 4; i++)
#pragma unroll
        for (int j = 0; j < 4; j++) acc[i][j] = 0ull;

#pragma unroll 4
    for (int kk = 0; kk < 64; kk++) {
        const ulonglong2* ap = (const ulonglong2*)&As[kk * MT + ty * 8];
        ulonglong2 a01 = ap[0];
        ulonglong2 a23 = ap[1];
        float4 b = *(const float4*)&Bs[kk * OT + tx * 4];
        unsigned long long b0 = pk2(b.x, b.x);
        unsigned long long b1 = pk2(b.y, b.y);
        unsigned long long b2 = pk2(b.z, b.z);
        unsigned long long b3 = pk2(b.w, b.w);
        FMA2(acc[0][0], a01.x, b0); FMA2(acc[0][1], a01.x, b1);
        FMA2(acc[0][2], a01.x, b2); FMA2(acc[0][3], a01.x, b3);
        FMA2(acc[1][0], a01.y, b0); FMA2(acc[1][1], a01.y, b1);
        FMA2(acc[1][2], a01.y, b2); FMA2(acc[1][3], a01.y, b3);
        FMA2(acc[2][0], a23.x, b0); FMA2(acc[2][1], a23.x, b1);
        FMA2(acc[2][2], a23.x, b2); FMA2(acc[2][3], a23.x, b3);
        FMA2(acc[3][0], a23.y, b0); FMA2(acc[3][1], a23.y, b1);
        FMA2(acc[3][2], a23.y, b2); FMA2(acc[3][3], a23.y, b3);
    }

    float* Ck = XW + (size_t)k * Nn * OT;
#pragma unroll
    for (int rp = 0; rp < 4; rp++) {
        float lo0, hi0, lo1, hi1, lo2, hi2, lo3, hi3;
        upk2(acc[rp][0], lo0, hi0);
        upk2(acc[rp][1], lo1, hi1);
        upk2(acc[rp][2], lo2, hi2);
        upk2(acc[rp][3], lo3, hi3);
        int m = m0 + ty * 8 + 2 * rp;
        if (m < Nn)
            *(float4*)(Ck + (size_t)m * OT + tx * 4) = make_float4(lo0, lo1, lo2, lo3);
        if (m + 1 < Nn)
            *(float4*)(Ck + (size_t)(m + 1) * OT + tx * 4) = make_float4(hi0, hi1, hi2, hi3);
    }
}

// ---------------- gather layer2: warp per edge, 2 outputs/lane ----------------
__global__ void gather_64(const int* __restrict__ edge, int E, const float* __restrict__ ps,
                          const float* __restrict__ XW, int Nn, int aggoff, int degoff) {
    int gw = (blockIdx.x * blockDim.x + threadIdx.x) >> 5;
    if (gw >= E) return;
    int lane = threadIdx.x & 31;
    float g0[2], g1[2], g2[2]; int kb;
    load_pseudo(ps, gw, g0, g1, g2, kb);
    int src = edge[gw];
    int dst = edge[E + gw];
    float ax = 0.0f, ay = 0.0f;
#pragma unroll
    for (int s = 0; s < 8; s++) {
        float basis = g0[s & 1] * g1[(s >> 1) & 1] * g2[s >> 2];
        int k = kb + (s & 1) + 5 * ((s >> 1) & 1) + 25 * (s >> 2);
        float2 v = *((const float2*)(XW + ((size_t)k * Nn + src) * 64) + lane);
        ax = fmaf(basis, v.x, ax);
        ay = fmaf(basis, v.y, ay);
    }
    float* P = pool();
    redAdd2(P + aggoff + dst * 64 + 2 * lane, ax, ay);
    if (lane == 0) atomicAdd(P + degoff + dst, 1.0f);
}

// ---------------- gather layer3: warp per edge, 4 outputs/lane ----------------
__global__ void gather_128(const int* __restrict__ edge, int E, const float* __restrict__ ps,
                           const float* __restrict__ XW, int Nn, int aggoff, int degoff) {
    int gw = (blockIdx.x * blockDim.x + threadIdx.x) >> 5;
    if (gw >= E) return;
    int lane = threadIdx.x & 31;
    float g0[2], g1[2], g2[2]; int kb;
    load_pseudo(ps, gw, g0, g1, g2, kb);
    int src = edge[gw];
    int dst = edge[E + gw];
    float a0 = 0.0f, a1 = 0.0f, a2 = 0.0f, a3 = 0.0f;
#pragma unroll
    for (int s = 0; s < 8; s++) {
        float basis = g0[s & 1] * g1[(s >> 1) & 1] * g2[s >> 2];
        int k = kb + (s & 1) + 5 * ((s >> 1) & 1) + 25 * (s >> 2);
        float4 v = *((const float4*)(XW + ((size_t)k * Nn + src) * 128) + lane);
        a0 = fmaf(basis, v.x, a0);
        a1 = fmaf(basis, v.y, a1);
        a2 = fmaf(basis, v.z, a2);
        a3 = fmaf(basis, v.w, a3);
    }
    float* P = pool();
    redAdd4(P + aggoff + dst * 128 + 4 * lane, a0, a1, a2, a3);
    if (lane == 0) atomicAdd(P + degoff + dst, 1.0f);
}

// ---------------- node update: out = elu(agg/deg + fix(h) @ root + b), din=64 ----------------
__global__ void node_dense(int hoff, int aggoff, int degoff, int xoff,
                           const float* __restrict__ root, const float* __restrict__ bias,
                           int ntot, int shift) {
    int t = blockIdx.x * blockDim.x + threadIdx.x;
    if (t >= ntot) return;
    int n = t >> shift;
    int o = t & ((1 << shift) - 1);
    float* P = pool();
    const float* h = P + hoff + n * 64;
    float acc = bias[o] + P[aggoff + t] / fmaxf(P[degoff + n], 1.0f);
#pragma unroll 16
    for (int i = 0; i < 64; i++)
        acc = fmaf(fixf(h[i]), root[(i << shift) + o], acc);
    P[xoff + t] = eluf(acc);
}

// ---------------- final MLP + log_softmax, one block per batch row ----------------
__global__ void fc_kernel(const float* __restrict__ w1, const float* __restrict__ b1,
                          const float* __restrict__ w2, const float* __restrict__ b2,
                          float* __restrict__ out) {
    __shared__ float xrow[1024];
    __shared__ float hrow[256];
    __shared__ float logits[10];
    __shared__ float red[2];
    int b = blockIdx.x;
    int t = threadIdx.x;  // 256 threads
    float* P = pool();
    for (int i = t; i < 1024; i += 256) xrow[i] = fixf(P[O_H4 + b * 1024 + i]);
    __syncthreads();

    float acc = b1[t];
#pragma unroll 8
    for (int i = 0; i < 1024; i++)
        acc = fmaf(xrow[i], w1[i * 256 + t], acc);
    hrow[t] = eluf(acc);
    __syncthreads();

    if (t < 10) {
        float a = b2[t];
#pragma unroll 8
        for (int i = 0; i < 256; i++)
            a = fmaf(hrow[i], w2[i * 10 + t], a);
        logits[t] = a;
    }
    __syncthreads();
    if (t == 0) {
        float m = logits[0];
        for (int j = 1; j < 10; j++) m = fmaxf(m, logits[j]);
        float s = 0.0f;
        for (int j = 0; j < 10; j++) s += expf(logits[j] - m);
        red[0] = m;
        red[1] = logf(s);
    }
    __syncthreads();
    if (t < 10) out[b * 10 + t] = logits[t] - red[0] - red[1];
}

// ---------------- host ----------------
extern "C" void kernel_launch(void* const* d_in, const int* in_sizes, int n_in,
                              void* d_out, int out_size) {
    const float* x0      = (const float*)d_in[0];
    const int*   cl0     = (const int*)  d_in[1];
    const int*   edge1   = (const int*)  d_in[2];
    const float* pseudo1 = (const float*)d_in[3];
    const float* W1      = (const float*)d_in[4];
    const float* root1   = (const float*)d_in[5];
    const float* b1      = (const float*)d_in[6];
    const int*   cl1     = (const int*)  d_in[7];
    const int*   edge2   = (const int*)  d_in[8];
    const float* pseudo2 = (const float*)d_in[9];
    const float* W2      = (const float*)d_in[10];
    const float* root2   = (const float*)d_in[11];
    const float* b2      = (const float*)d_in[12];
    const int*   cl2     = (const int*)  d_in[13];
    const int*   edge3   = (const int*)  d_in[14];
    const float* pseudo3 = (const float*)d_in[15];
    const float* W3      = (const float*)d_in[16];
    const float* root3   = (const float*)d_in[17];
    const float* b3      = (const float*)d_in[18];
    const int*   cl3     = (const int*)  d_in[19];
    const float* fc1w    = (const float*)d_in[20];
    const float* fc1b    = (const float*)d_in[21];
    const float* fc2w    = (const float*)d_in[22];
    const float* fc2b    = (const float*)d_in[23];
    float* out = (float*)d_out;

    const int TB = 256;

    float* xw2;
    float* xw3;
    cudaGetSymbolAddress((void**)&xw2, g_xw2_4);
    cudaGetSymbolAddress((void**)&xw3, g_xw3_4);

    // 1: init everything (seg-max -inf fills + accumulator zeros)
    init_all<<<1024, TB>>>();
    // 2: seg_max(x0, cluster0) -> H1
    segmax_x0_kernel<<<CDIV(cN0, TB), TB>>>(x0, cl0);
    // 3: layer-1 scatter into c[dst][k]
    l1_scatter<<<CDIV(cE1, TB), TB>>>(edge1, pseudo1);
    // 4: layer-1 GEMM + fused node update -> X1
    l1_gemm<<<CDIV(cN1, 64), 256>>>(W1, root1, b1);
    // 5: seg_max(X1, cluster1) -> H2
    segmax_pool_kernel<<<CDIV(cN1 * 64, TB), TB>>>(O_X1, cl1, O_H2, cN1 * 64, 6);
    // 6: layer-2 batched GEMM (ncu -s 5 lands here)
    {
        dim3 g(CDIV(cN2, 128), cK);
        gemm_xw<128, 64><<<g, 256>>>(O_H2, W2, xw2, cN2);
    }
    // 7: layer-2 gather
    gather_64<<<CDIV(cE2 * 32, TB), TB>>>(edge2, cE2, pseudo2, xw2, cN2, O_AGG2, O_DEG2);
    // 8: layer-2 node update -> X2
    node_dense<<<CDIV(cN2 * 64, TB), TB>>>(O_H2, O_AGG2, O_DEG2, O_X2, root2, b2, cN2 * 64, 6);
    // 9: seg_max(X2, cluster2) -> H3
    segmax_pool_kernel<<<CDIV(cN2 * 64, TB), TB>>>(O_X2, cl2, O_H3, cN2 * 64, 6);
    // 10: layer-3 batched GEMM
    {
        dim3 g(CDIV(cN3, 64), cK);
        gemm_xw<64, 128><<<g, 256>>>(O_H3, W3, xw3, cN3);
    }
    // 11: layer-3 gather
    gather_128<<<CDIV(cE3 * 32, TB), TB>>>(edge3, cE3, pseudo3, xw3, cN3, O_AGG3, O_DEG3);
    // 12: layer-3 node update -> X3
    node_dense<<<CDIV(cN3 * 128, TB), TB>>>(O_H3, O_AGG3, O_DEG3, O_X3, root3, b3, cN3 * 128, 7);
    // 13: seg_max(X3, cluster3) -> H4
    segmax_pool_kernel<<<CDIV(cN3 * 128, TB), TB>>>(O_X3, cl3, O_H4, cN3 * 128, 7);
    // 14: MLP head + log_softmax
    fc_kernel<<<cB, 256>>>(fc1w, fc1b, fc2w, fc2b, out);
}

// round 6
// speedup vs baseline: 2.5167x; 1.0676x over previous
#include <cuda_runtime.h>
#include <cuda_fp16.h>
#include <math.h>
#include <stdint.h>

#define CDIV(a,b) (((a)+(b)-1)/(b))

// Problem constants
constexpr int cN0 = 120000;
constexpr int cN1 = 20000;
constexpr int cN2 = 6000;
constexpr int cN3 = 1600;
constexpr int cB  = 64;
constexpr int cE1 = 480000;
constexpr int cE2 = 144000;
constexpr int cE3 = 38400;
constexpr int cK  = 125;

// ---------------- scratch pool (no cudaMalloc allowed) ----------------
constexpr int AL64(int x) { return (x + 63) & ~63; }
constexpr int O_H1   = 0;
constexpr int O_C1   = O_H1   + AL64(cN1);      // c[dst][128] (125 used)
constexpr int O_DEG1 = O_C1   + cN1 * 128;
constexpr int O_H2   = O_DEG1 + AL64(cN1);
constexpr int O_AGG2 = O_H2   + cN2 * 64;
constexpr int O_DEG2 = O_AGG2 + cN2 * 64;
constexpr int O_H3   = O_DEG2 + AL64(cN2);
constexpr int O_AGG3 = O_H3   + cN3 * 64;
constexpr int O_DEG3 = O_AGG3 + cN3 * 128;
constexpr int O_H4   = O_DEG3 + AL64(cN3);
constexpr int POOLN  = O_H4   + 512 * 128;

__device__ float4 g_pool4[(POOLN + 3) / 4];
__device__ __forceinline__ float* pool() { return (float*)g_pool4; }

// XW scratch in f16: XW2h[k][n][64], XW3h[k][n][128]
__device__ uint4 g_xw2h4[(size_t)cK * cN2 * 64 * 2 / 16];   // 96 MB
__device__ uint4 g_xw3h4[(size_t)cK * cN3 * 128 * 2 / 16];  // 51.2 MB

// ---------------- helpers ----------------
__device__ __forceinline__ void atomicMaxFloat(float* addr, float val) {
    if (val >= 0.0f)
        atomicMax((int*)addr, __float_as_int(val));
    else
        atomicMin((unsigned int*)addr, __float_as_uint(val));
}
__device__ __forceinline__ void redAdd4(float* addr, float a, float b, float c, float d) {
    asm volatile("red.global.add.v4.f32 [%0], {%1,%2,%3,%4};"
                 :: "l"(addr), "f"(a), "f"(b), "f"(c), "f"(d) : "memory");
}
__device__ __forceinline__ void redAdd2(float* addr, float a, float b) {
    asm volatile("red.global.add.v2.f32 [%0], {%1,%2};"
                 :: "l"(addr), "f"(a), "f"(b) : "memory");
}
__device__ __forceinline__ unsigned long long pk2(float x, float y) {
    unsigned long long r;
    asm("mov.b64 %0, {%1,%2};" : "=l"(r) : "f"(x), "f"(y));
    return r;
}
__device__ __forceinline__ void upk2(unsigned long long v, float& x, float& y) {
    asm("mov.b64 {%0,%1}, %2;" : "=f"(x), "=f"(y) : "l"(v));
}
#define FMA2(d, a, b) asm("fma.rn.f32x2 %0, %1, %2, %0;" : "+l"(d) : "l"(a), "l"(b))

__device__ __forceinline__ float eluf(float v) { return v > 0.0f ? v : expm1f(v); }
__device__ __forceinline__ float fixf(float v) { return isfinite(v) ? v : 0.0f; }
__device__ __forceinline__ float4 fix4(float4 v) {
    v.x = fixf(v.x); v.y = fixf(v.y); v.z = fixf(v.z); v.w = fixf(v.w);
    return v;
}
__device__ __forceinline__ uint32_t h2u(__half2 h) {
    return *(const uint32_t*)&h;
}

// ---------------- init: -inf seg-max buffers, zero accumulators ----------------
__global__ void init_all() {
    float* P = pool();
    const float NI = -INFINITY;
    int t = blockIdx.x * blockDim.x + threadIdx.x;
    int stride = gridDim.x * blockDim.x;
    for (int i = t; i < cN1; i += stride) P[O_H1 + i] = NI;
    for (int i = t; i < cN2 * 64; i += stride) P[O_H2 + i] = NI;
    for (int i = t; i < cN3 * 64; i += stride) P[O_H3 + i] = NI;
    for (int i = t; i < 512 * 128; i += stride) P[O_H4 + i] = NI;
    for (int i = t; i < cN1 * 128; i += stride) P[O_C1 + i] = 0.0f;
    for (int i = t; i < cN1; i += stride) P[O_DEG1 + i] = 0.0f;
    for (int i = t; i < cN2 * 64; i += stride) P[O_AGG2 + i] = 0.0f;
    for (int i = t; i < cN2; i += stride) P[O_DEG2 + i] = 0.0f;
    for (int i = t; i < cN3 * 128; i += stride) P[O_AGG3 + i] = 0.0f;
    for (int i = t; i < cN3; i += stride) P[O_DEG3 + i] = 0.0f;
}

__global__ void segmax_x0_kernel(const float* __restrict__ x, const int* __restrict__ cl) {
    int t = blockIdx.x * blockDim.x + threadIdx.x;
    if (t >= cN0) return;
    atomicMaxFloat(pool() + O_H1 + cl[t], x[t]);
}

// ---------------- spline basis ----------------
__device__ __forceinline__ void load_pseudo(const float* __restrict__ ps, int e,
                                            float g0[2], float g1[2], float g2[2], int& kbase) {
    float p0 = ps[e * 3 + 0] * 4.0f;
    float p1 = ps[e * 3 + 1] * 4.0f;
    float p2 = ps[e * 3 + 2] * 4.0f;
    float lo0 = fmaxf(fminf(floorf(p0), 3.0f), 0.0f);
    float lo1 = fmaxf(fminf(floorf(p1), 3.0f), 0.0f);
    float lo2 = fmaxf(fminf(floorf(p2), 3.0f), 0.0f);
    float f0 = p0 - lo0, f1 = p1 - lo1, f2 = p2 - lo2;
    g0[0] = 1.0f - f0; g0[1] = f0;
    g1[0] = 1.0f - f1; g1[1] = f1;
    g2[0] = 1.0f - f2; g2[1] = f2;
    kbase = (int)lo0 + 5 * (int)lo1 + 25 * (int)lo2;
}

// ---------------- layer 1 scatter: c[dst][k] += basis * x_src ----------------
__global__ void l1_scatter(const int* __restrict__ edge, const float* __restrict__ ps) {
    int e = blockIdx.x * blockDim.x + threadIdx.x;
    if (e >= cE1) return;
    float g0[2], g1[2], g2[2]; int kb;
    load_pseudo(ps, e, g0, g1, g2, kb);
    int src = edge[e];
    int dst = edge[cE1 + e];
    float* P = pool();
    float xs = fixf(P[O_H1 + src]);
    float* c = P + O_C1 + dst * 128 + kb;
#pragma unroll
    for (int s = 0; s < 8; s++) {
        float basis = g0[s & 1] * g1[(s >> 1) & 1] * g2[s >> 2];
        int ko = (s & 1) + 5 * ((s >> 1) & 1) + 25 * (s >> 2);
        atomicAdd(c + ko, basis * xs);
    }
    atomicAdd(P + O_DEG1 + dst, 1.0f);
}

// ---------------- layer 1 GEMM + fused node update + fused seg-max -> H2 ----------------
// X1 = elu( (C1 @ W1)/deg + h1*root + b ); H2[cl1[m]] = max(H2, X1[m])
__global__ void l1_gemm(const float* __restrict__ W1, const float* __restrict__ root1,
                        const float* __restrict__ b1, const int* __restrict__ cl1) {
    __shared__ float As[64 * 64];   // [kk][m] transposed
    __shared__ float Bs[64 * 64];   // [kk][o]
    int tid = threadIdx.x;
    int m0  = blockIdx.x * 64;
    float* P = pool();

    int tx = tid % 16;          // cols tx*4 .. +3
    int ty = tid / 16;          // rows ty*4 .. +3 (2 pairs)

    unsigned long long acc[2][4];
#pragma unroll
    for (int i = 0; i < 2; i++)
#pragma unroll
        for (int j = 0; j < 4; j++) acc[i][j] = 0ull;

    for (int ch = 0; ch < 2; ch++) {
        __syncthreads();
        // A tile: As[kk][m] = C1[(m0+m)*128 + ch*64 + kk]
        for (int idx = tid; idx < 64 * 16; idx += 256) {
            int m = idx >> 4;
            int q = idx & 15;
            float4 v = make_float4(0.f, 0.f, 0.f, 0.f);
            if (m0 + m < cN1) v = *(const float4*)(P + O_C1 + (m0 + m) * 128 + ch * 64 + q * 4);
            As[(q * 4 + 0) * 64 + m] = v.x;
            As[(q * 4 + 1) * 64 + m] = v.y;
            As[(q * 4 + 2) * 64 + m] = v.z;
            As[(q * 4 + 3) * 64 + m] = v.w;
        }
        // B tile: Bs[kk][o] = W1[(ch*64+kk)*64 + o] (rows >=125 zero)
        for (int idx = tid; idx < 64 * 16; idx += 256) {
            int kk = idx >> 4;
            int o4 = idx & 15;
            int g = ch * 64 + kk;
            float4 v = make_float4(0.f, 0.f, 0.f, 0.f);
            if (g < cK) v = *(const float4*)(W1 + g * 64 + o4 * 4);
            *(float4*)&Bs[kk * 64 + o4 * 4] = v;
        }
        __syncthreads();

#pragma unroll 4
        for (int kk = 0; kk < 64; kk++) {
            ulonglong2 a01 = *(const ulonglong2*)&As[kk * 64 + ty * 4];
            float4 b = *(const float4*)&Bs[kk * 64 + tx * 4];
            unsigned long long b0 = pk2(b.x, b.x);
            unsigned long long b1v = pk2(b.y, b.y);
            unsigned long long b2 = pk2(b.z, b.z);
            unsigned long long b3 = pk2(b.w, b.w);
            FMA2(acc[0][0], a01.x, b0); FMA2(acc[0][1], a01.x, b1v);
            FMA2(acc[0][2], a01.x, b2); FMA2(acc[0][3], a01.x, b3);
            FMA2(acc[1][0], a01.y, b0); FMA2(acc[1][1], a01.y, b1v);
            FMA2(acc[1][2], a01.y, b2); FMA2(acc[1][3], a01.y, b3);
        }
    }

    // fused epilogue: node update + seg-max scatter into H2
    float4 rt4 = *(const float4*)(root1 + tx * 4);
    float4 bb4 = *(const float4*)(b1 + tx * 4);
#pragma unroll
    for (int rp = 0; rp < 2; rp++) {
        float lo0, hi0, lo1, hi1, lo2, hi2, lo3, hi3;
        upk2(acc[rp][0], lo0, hi0);
        upk2(acc[rp][1], lo1, hi1);
        upk2(acc[rp][2], lo2, hi2);
        upk2(acc[rp][3], lo3, hi3);
#pragma unroll
        for (int rr = 0; rr < 2; rr++) {
            int m = m0 + ty * 4 + 2 * rp + rr;
            if (m >= cN1) continue;
            float v0 = rr ? hi0 : lo0, v1 = rr ? hi1 : lo1;
            float v2 = rr ? hi2 : lo2, v3 = rr ? hi3 : lo3;
            float invd = 1.0f / fmaxf(P[O_DEG1 + m], 1.0f);
            float h = fixf(P[O_H1 + m]);
            float* dst = P + O_H2 + (cl1[m] << 6) + tx * 4;
            atomicMaxFloat(dst + 0, eluf(v0 * invd + h * rt4.x + bb4.x));
            atomicMaxFloat(dst + 1, eluf(v1 * invd + h * rt4.y + bb4.y));
            atomicMaxFloat(dst + 2, eluf(v2 * invd + h * rt4.z + bb4.z));
            atomicMaxFloat(dst + 3, eluf(v3 * invd + h * rt4.w + bb4.w));
        }
    }
}

// ---------------- batched GEMM: XWh[k] = f16( fix(X) (Nn x 64) @ W[k] (64 x OT) ) ----------------
template<int MT, int OT>
__global__ void gemm_xw(int xoff, const float* __restrict__ W, __half2* __restrict__ XWh, int Nn) {
    constexpr int CT = OT / 4;
    constexpr int RT = 256 / CT;
    static_assert(MT == RT * 8, "tile shape");
    __shared__ float As[64 * MT];
    __shared__ float Bs[64 * OT];

    int tid = threadIdx.x;
    int k   = blockIdx.y;
    int m0  = blockIdx.x * MT;
    const float* Xg = pool() + xoff;

    for (int idx = tid; idx < MT * 16; idx += 256) {
        int m = idx >> 4;
        int q = idx & 15;
        float4 v = make_float4(0.f, 0.f, 0.f, 0.f);
        if (m0 + m < Nn) v = fix4(*(const float4*)(Xg + (m0 + m) * 64 + q * 4));
        As[(q * 4 + 0) * MT + m] = v.x;
        As[(q * 4 + 1) * MT + m] = v.y;
        As[(q * 4 + 2) * MT + m] = v.z;
        As[(q * 4 + 3) * MT + m] = v.w;
    }
    {
        const float4* Wk = (const float4*)(W + k * 64 * OT);
        float4* B4 = (float4*)Bs;
        for (int idx = tid; idx < (64 * OT) / 4; idx += 256) B4[idx] = Wk[idx];
    }
    __syncthreads();

    int tx = tid % CT;
    int ty = tid / CT;

    unsigned long long acc[4][4];
#pragma unroll
    for (int i = 0; i < 4; i++)
#pragma unroll
        for (int j = 0; j < 4; j++) acc[i][j] = 0ull;

#pragma unroll 4
    for (int kk = 0; kk < 64; kk++) {
        const ulonglong2* ap = (const ulonglong2*)&As[kk * MT + ty * 8];
        ulonglong2 a01 = ap[0];
        ulonglong2 a23 = ap[1];
        float4 b = *(const float4*)&Bs[kk * OT + tx * 4];
        unsigned long long b0 = pk2(b.x, b.x);
        unsigned long long b1 = pk2(b.y, b.y);
        unsigned long long b2 = pk2(b.z, b.z);
        unsigned long long b3 = pk2(b.w, b.w);
        FMA2(acc[0][0], a01.x, b0); FMA2(acc[0][1], a01.x, b1);
        FMA2(acc[0][2], a01.x, b2); FMA2(acc[0][3], a01.x, b3);
        FMA2(acc[1][0], a01.y, b0); FMA2(acc[1][1], a01.y, b1);
        FMA2(acc[1][2], a01.y, b2); FMA2(acc[1][3], a01.y, b3);
        FMA2(acc[2][0], a23.x, b0); FMA2(acc[2][1], a23.x, b1);
        FMA2(acc[2][2], a23.x, b2); FMA2(acc[2][3], a23.x, b3);
        FMA2(acc[3][0], a23.y, b0); FMA2(acc[3][1], a23.y, b1);
        FMA2(acc[3][2], a23.y, b2); FMA2(acc[3][3], a23.y, b3);
    }

    // epilogue: convert to f16 pairs, 8-byte store per row
    __half2* Ck = XWh + (size_t)k * Nn * (OT / 2);
#pragma unroll
    for (int rp = 0; rp < 4; rp++) {
        float lo0, hi0, lo1, hi1, lo2, hi2, lo3, hi3;
        upk2(acc[rp][0], lo0, hi0);
        upk2(acc[rp][1], lo1, hi1);
        upk2(acc[rp][2], lo2, hi2);
        upk2(acc[rp][3], lo3, hi3);
        int m = m0 + ty * 8 + 2 * rp;
        if (m < Nn) {
            uint2 u = make_uint2(h2u(__floats2half2_rn(lo0, lo1)),
                                 h2u(__floats2half2_rn(lo2, lo3)));
            *(uint2*)(Ck + (size_t)m * (OT / 2) + tx * 2) = u;
        }
        if (m + 1 < Nn) {
            uint2 u = make_uint2(h2u(__floats2half2_rn(hi0, hi1)),
                                 h2u(__floats2half2_rn(hi2, hi3)));
            *(uint2*)(Ck + (size_t)(m + 1) * (OT / 2) + tx * 2) = u;
        }
    }
}

// ---------------- gather layer2: warp per edge, f16 XW ----------------
__global__ void gather_64(const int* __restrict__ edge, int E, const float* __restrict__ ps,
                          const __half2* __restrict__ XWh, int Nn, int aggoff, int degoff) {
    int gw = (blockIdx.x * blockDim.x + threadIdx.x) >> 5;
    if (gw >= E) return;
    int lane = threadIdx.x & 31;
    float g0[2], g1[2], g2[2]; int kb;
    load_pseudo(ps, gw, g0, g1, g2, kb);
    int src = edge[gw];
    int dst = edge[E + gw];
    float ax = 0.0f, ay = 0.0f;
#pragma unroll
    for (int s = 0; s < 8; s++) {
        float basis = g0[s & 1] * g1[(s >> 1) & 1] * g2[s >> 2];
        int k = kb + (s & 1) + 5 * ((s >> 1) & 1) + 25 * (s >> 2);
        __half2 h = XWh[((size_t)k * Nn + src) * 32 + lane];
        float2 v = __half22float2(h);
        ax = fmaf(basis, v.x, ax);
        ay = fmaf(basis, v.y, ay);
    }
    float* P = pool();
    redAdd2(P + aggoff + dst * 64 + 2 * lane, ax, ay);
    if (lane == 0) atomicAdd(P + degoff + dst, 1.0f);
}

// ---------------- gather layer3: warp per edge, f16 XW ----------------
__global__ void gather_128(const int* __restrict__ edge, int E, const float* __restrict__ ps,
                           const __half2* __restrict__ XWh, int Nn, int aggoff, int degoff) {
    int gw = (blockIdx.x * blockDim.x + threadIdx.x) >> 5;
    if (gw >= E) return;
    int lane = threadIdx.x & 31;
    float g0[2], g1[2], g2[2]; int kb;
    load_pseudo(ps, gw, g0, g1, g2, kb);
    int src = edge[gw];
    int dst = edge[E + gw];
    float a0 = 0.0f, a1 = 0.0f, a2 = 0.0f, a3 = 0.0f;
#pragma unroll
    for (int s = 0; s < 8; s++) {
        float basis = g0[s & 1] * g1[(s >> 1) & 1] * g2[s >> 2];
        int k = kb + (s & 1) + 5 * ((s >> 1) & 1) + 25 * (s >> 2);
        uint2 u = *((const uint2*)(XWh + ((size_t)k * Nn + src) * 64) + lane);
        float2 v0 = __half22float2(*(const __half2*)&u.x);
        float2 v1 = __half22float2(*(const __half2*)&u.y);
        a0 = fmaf(basis, v0.x, a0);
        a1 = fmaf(basis, v0.y, a1);
        a2 = fmaf(basis, v1.x, a2);
        a3 = fmaf(basis, v1.y, a3);
    }
    float* P = pool();
    redAdd4(P + aggoff + dst * 128 + 4 * lane, a0, a1, a2, a3);
    if (lane == 0) atomicAdd(P + degoff + dst, 1.0f);
}

// ---------------- node update + fused seg-max into next H ----------------
__global__ void node_dense(int hoff, int aggoff, int degoff, const int* __restrict__ cl,
                           int outoff, const float* __restrict__ root,
                           const float* __restrict__ bias, int ntot, int shift) {
    int t = blockIdx.x * blockDim.x + threadIdx.x;
    if (t >= ntot) return;
    int n = t >> shift;
    int o = t & ((1 << shift) - 1);
    float* P = pool();
    const float* h = P + hoff + n * 64;
    float acc = bias[o] + P[aggoff + t] / fmaxf(P[degoff + n], 1.0f);
#pragma unroll 16
    for (int i = 0; i < 64; i++)
        acc = fmaf(fixf(h[i]), root[(i << shift) + o], acc);
    atomicMaxFloat(P + outoff + (cl[n] << shift) + o, eluf(acc));
}

// ---------------- final MLP + log_softmax ----------------
__global__ void fc_kernel(const float* __restrict__ w1, const float* __restrict__ b1,
                          const float* __restrict__ w2, const float* __restrict__ b2,
                          float* __restrict__ out) {
    __shared__ float xrow[1024];
    __shared__ float hrow[256];
    __shared__ float logits[10];
    __shared__ float red[2];
    int b = blockIdx.x;
    int t = threadIdx.x;
    float* P = pool();
    for (int i = t; i < 1024; i += 256) xrow[i] = fixf(P[O_H4 + b * 1024 + i]);
    __syncthreads();

    float acc = b1[t];
#pragma unroll 8
    for (int i = 0; i < 1024; i++)
        acc = fmaf(xrow[i], w1[i * 256 + t], acc);
    hrow[t] = eluf(acc);
    __syncthreads();

    if (t < 10) {
        float a = b2[t];
#pragma unroll 8
        for (int i = 0; i < 256; i++)
            a = fmaf(hrow[i], w2[i * 10 + t], a);
        logits[t] = a;
    }
    __syncthreads();
    if (t == 0) {
        float m = logits[0];
        for (int j = 1; j < 10; j++) m = fmaxf(m, logits[j]);
        float s = 0.0f;
        for (int j = 0; j < 10; j++) s += expf(logits[j] - m);
        red[0] = m;
        red[1] = logf(s);
    }
    __syncthreads();
    if (t < 10) out[b * 10 + t] = logits[t] - red[0] - red[1];
}

// ---------------- host ----------------
extern "C" void kernel_launch(void* const* d_in, const int* in_sizes, int n_in,
                              void* d_out, int out_size) {
    const float* x0      = (const float*)d_in[0];
    const int*   cl0     = (const int*)  d_in[1];
    const int*   edge1   = (const int*)  d_in[2];
    const float* pseudo1 = (const float*)d_in[3];
    const float* W1      = (const float*)d_in[4];
    const float* root1   = (const float*)d_in[5];
    const float* b1      = (const float*)d_in[6];
    const int*   cl1     = (const int*)  d_in[7];
    const int*   edge2   = (const int*)  d_in[8];
    const float* pseudo2 = (const float*)d_in[9];
    const float* W2      = (const float*)d_in[10];
    const float* root2   = (const float*)d_in[11];
    const float* b2      = (const float*)d_in[12];
    const int*   cl2     = (const int*)  d_in[13];
    const int*   edge3   = (const int*)  d_in[14];
    const float* pseudo3 = (const float*)d_in[15];
    const float* W3      = (const float*)d_in[16];
    const float* root3   = (const float*)d_in[17];
    const float* b3      = (const float*)d_in[18];
    const int*   cl3     = (const int*)  d_in[19];
    const float* fc1w    = (const float*)d_in[20];
    const float* fc1b    = (const float*)d_in[21];
    const float* fc2w    = (const float*)d_in[22];
    const float* fc2b    = (const float*)d_in[23];
    float* out = (float*)d_out;

    const int TB = 256;

    __half2* xw2h; __half2* xw3h;
    cudaGetSymbolAddress((void**)&xw2h, g_xw2h4);
    cudaGetSymbolAddress((void**)&xw3h, g_xw3h4);

    // 1: init (seg-max -inf fills + accumulator zeros)
    init_all<<<1024, TB>>>();
    // 2: seg_max(x0) -> H1
    segmax_x0_kernel<<<CDIV(cN0, TB), TB>>>(x0, cl0);
    // 3: layer-1 scatter into c[dst][k]
    l1_scatter<<<CDIV(cE1, TB), TB>>>(edge1, pseudo1);
    // 4: layer-1 GEMM + node update + seg-max -> H2
    l1_gemm<<<CDIV(cN1, 64), 256>>>(W1, root1, b1, cl1);
    // 5: layer-2 batched GEMM -> XW2 (f16)
    {
        dim3 g(CDIV(cN2, 128), cK);
        gemm_xw<128, 64><<<g, 256>>>(O_H2, W2, xw2h, cN2);
    }
    // 6: layer-2 gather
    gather_64<<<CDIV(cE2 * 32, TB), TB>>>(edge2, cE2, pseudo2, xw2h, cN2, O_AGG2, O_DEG2);
    // 7: layer-2 node update + seg-max -> H3
    node_dense<<<CDIV(cN2 * 64, TB), TB>>>(O_H2, O_AGG2, O_DEG2, cl2, O_H3, root2, b2, cN2 * 64, 6);
    // 8: layer-3 batched GEMM -> XW3 (f16)
    {
        dim3 g(CDIV(cN3, 64), cK);
        gemm_xw<64, 128><<<g, 256>>>(O_H3, W3, xw3h, cN3);
    }
    // 9: layer-3 gather
    gather_128<<<CDIV(cE3 * 32, TB), TB>>>(edge3, cE3, pseudo3, xw3h, cN3, O_AGG3, O_DEG3);
    // 10: layer-3 node update + seg-max -> H4
    node_dense<<<CDIV(cN3 * 128, TB), TB>>>(O_H3, O_AGG3, O_DEG3, cl3, O_H4, root3, b3, cN3 * 128, 7);
    // 11: MLP head + log_softmax
    fc_kernel<<<cB, 256>>>(fc1w, fc1b, fc2w, fc2b, out);
}

// round 8
// speedup vs baseline: 3.7685x; 1.4974x over previous
#include <cuda_runtime.h>
#include <cuda_fp16.h>
#include <math.h>
#include <stdint.h>

#define CDIV(a,b) (((a)+(b)-1)/(b))

// Problem constants
constexpr int cN0 = 120000;
constexpr int cN1 = 20000;
constexpr int cN2 = 6000;
constexpr int cN3 = 1600;
constexpr int cB  = 64;
constexpr int cE1 = 480000;
constexpr int cE2 = 144000;
constexpr int cE3 = 38400;
constexpr int cK  = 125;

// ---------------- scratch pool (no cudaMalloc allowed) ----------------
constexpr int AL64(int x) { return (x + 63) & ~63; }
constexpr int O_H1   = 0;
constexpr int O_C1   = O_H1   + AL64(cN1);      // c[dst][128] (125 used)
constexpr int O_DEG1 = O_C1   + cN1 * 128;
constexpr int O_H2   = O_DEG1 + AL64(cN1);
constexpr int O_AGG2 = O_H2   + cN2 * 64;
constexpr int O_DEG2 = O_AGG2 + cN2 * 64;
constexpr int O_H3   = O_DEG2 + AL64(cN2);
constexpr int O_AGG3 = O_H3   + cN3 * 64;
constexpr int O_DEG3 = O_AGG3 + cN3 * 128;
constexpr int O_H4   = O_DEG3 + AL64(cN3);
constexpr int POOLN  = O_H4   + 512 * 128;

__device__ float4 g_pool4[(POOLN + 3) / 4];
__device__ __forceinline__ float* pool() { return (float*)g_pool4; }

// XW scratch in f16: XW2h[k][n][64], XW3h[k][n][128]
__device__ uint4 g_xw2h4[(size_t)cK * cN2 * 64 * 2 / 16];   // 96 MB
__device__ uint4 g_xw3h4[(size_t)cK * cN3 * 128 * 2 / 16];  // 51.2 MB
// f16 W tiles, layout [k][o][kk] (kk contiguous, 64 per row) = B col-major for mma
__device__ uint4 g_w2h4[cK * 64 * 64 * 2 / 16];    // 1 MB
__device__ uint4 g_w3h4[cK * 128 * 64 * 2 / 16];   // 2 MB

// ---------------- helpers ----------------
__device__ __forceinline__ void atomicMaxFloat(float* addr, float val) {
    if (val >= 0.0f)
        atomicMax((int*)addr, __float_as_int(val));
    else
        atomicMin((unsigned int*)addr, __float_as_uint(val));
}
__device__ __forceinline__ void redAdd4(float* addr, float a, float b, float c, float d) {
    asm volatile("red.global.add.v4.f32 [%0], {%1,%2,%3,%4};"
                 :: "l"(addr), "f"(a), "f"(b), "f"(c), "f"(d) : "memory");
}
__device__ __forceinline__ void redAdd2(float* addr, float a, float b) {
    asm volatile("red.global.add.v2.f32 [%0], {%1,%2};"
                 :: "l"(addr), "f"(a), "f"(b) : "memory");
}
__device__ __forceinline__ unsigned long long pk2(float x, float y) {
    unsigned long long r;
    asm("mov.b64 %0, {%1,%2};" : "=l"(r) : "f"(x), "f"(y));
    return r;
}
__device__ __forceinline__ void upk2(unsigned long long v, float& x, float& y) {
    asm("mov.b64 {%0,%1}, %2;" : "=f"(x), "=f"(y) : "l"(v));
}
#define FMA2(d, a, b) asm("fma.rn.f32x2 %0, %1, %2, %0;" : "+l"(d) : "l"(a), "l"(b))

__device__ __forceinline__ float eluf(float v) { return v > 0.0f ? v : expm1f(v); }
__device__ __forceinline__ float fixf(float v) { return isfinite(v) ? v : 0.0f; }
__device__ __forceinline__ uint32_t h2u(__half2 h) { return *(const uint32_t*)&h; }

// mma.sync m16n8k16 f16 x f16 -> f32 (sm_80+; works on compute_103)
__device__ __forceinline__ void mma16816(float c[4], uint32_t a0, uint32_t a1,
                                         uint32_t a2, uint32_t a3,
                                         uint32_t b0, uint32_t b1) {
    asm volatile("mma.sync.aligned.m16n8k16.row.col.f32.f16.f16.f32 "
                 "{%0,%1,%2,%3}, {%4,%5,%6,%7}, {%8,%9}, {%0,%1,%2,%3};"
                 : "+f"(c[0]), "+f"(c[1]), "+f"(c[2]), "+f"(c[3])
                 : "r"(a0), "r"(a1), "r"(a2), "r"(a3), "r"(b0), "r"(b1));
}

// ---------------- init: -inf seg-max buffers, zero accumulators ----------------
__global__ void init_all() {
    float* P = pool();
    const float NI = -INFINITY;
    int t = blockIdx.x * blockDim.x + threadIdx.x;
    int stride = gridDim.x * blockDim.x;
    for (int i = t; i < cN1; i += stride) P[O_H1 + i] = NI;
    for (int i = t; i < cN2 * 64; i += stride) P[O_H2 + i] = NI;
    for (int i = t; i < cN3 * 64; i += stride) P[O_H3 + i] = NI;
    for (int i = t; i < 512 * 128; i += stride) P[O_H4 + i] = NI;
    for (int i = t; i < cN1 * 128; i += stride) P[O_C1 + i] = 0.0f;
    for (int i = t; i < cN1; i += stride) P[O_DEG1 + i] = 0.0f;
    for (int i = t; i < cN2 * 64; i += stride) P[O_AGG2 + i] = 0.0f;
    for (int i = t; i < cN2; i += stride) P[O_DEG2 + i] = 0.0f;
    for (int i = t; i < cN3 * 128; i += stride) P[O_AGG3 + i] = 0.0f;
    for (int i = t; i < cN3; i += stride) P[O_DEG3 + i] = 0.0f;
}

__global__ void segmax_x0_kernel(const float* __restrict__ x, const int* __restrict__ cl) {
    int t = blockIdx.x * blockDim.x + threadIdx.x;
    if (t >= cN0) return;
    atomicMaxFloat(pool() + O_H1 + cl[t], x[t]);
}

// ---------------- W -> f16, layout [k][o][kk] ----------------
template<int OT>
__global__ void convert_w(const float* __restrict__ W, __half2* __restrict__ Wh) {
    int idx = blockIdx.x * blockDim.x + threadIdx.x;
    if (idx >= cK * OT * 32) return;
    int k   = idx / (OT * 32);
    int rem = idx % (OT * 32);
    int o   = rem >> 5;
    int ip  = rem & 31;
    const float* wk = W + (size_t)k * 64 * OT;
    float w0 = wk[(2 * ip) * OT + o];
    float w1 = wk[(2 * ip + 1) * OT + o];
    Wh[((size_t)k * OT + o) * 32 + ip] = __floats2half2_rn(w0, w1);
}

// ---------------- spline basis ----------------
__device__ __forceinline__ void load_pseudo(const float* __restrict__ ps, int e,
                                            float g0[2], float g1[2], float g2[2], int& kbase) {
    float p0 = ps[e * 3 + 0] * 4.0f;
    float p1 = ps[e * 3 + 1] * 4.0f;
    float p2 = ps[e * 3 + 2] * 4.0f;
    float lo0 = fmaxf(fminf(floorf(p0), 3.0f), 0.0f);
    float lo1 = fmaxf(fminf(floorf(p1), 3.0f), 0.0f);
    float lo2 = fmaxf(fminf(floorf(p2), 3.0f), 0.0f);
    float f0 = p0 - lo0, f1 = p1 - lo1, f2 = p2 - lo2;
    g0[0] = 1.0f - f0; g0[1] = f0;
    g1[0] = 1.0f - f1; g1[1] = f1;
    g2[0] = 1.0f - f2; g2[1] = f2;
    kbase = (int)lo0 + 5 * (int)lo1 + 25 * (int)lo2;
}

// ---------------- layer 1 scatter: c[dst][k] += basis * x_src ----------------
__global__ void l1_scatter(const int* __restrict__ edge, const float* __restrict__ ps) {
    int e = blockIdx.x * blockDim.x + threadIdx.x;
    if (e >= cE1) return;
    float g0[2], g1[2], g2[2]; int kb;
    load_pseudo(ps, e, g0, g1, g2, kb);
    int src = edge[e];
    int dst = edge[cE1 + e];
    float* P = pool();
    float xs = fixf(P[O_H1 + src]);
    float* c = P + O_C1 + dst * 128 + kb;
#pragma unroll
    for (int s = 0; s < 8; s++) {
        float basis = g0[s & 1] * g1[(s >> 1) & 1] * g2[s >> 2];
        int ko = (s & 1) + 5 * ((s >> 1) & 1) + 25 * (s >> 2);
        atomicAdd(c + ko, basis * xs);
    }
    atomicAdd(P + O_DEG1 + dst, 1.0f);
}

// ---------------- layer 1 GEMM + fused node update + fused seg-max -> H2 ----------------
__global__ void l1_gemm(const float* __restrict__ W1, const float* __restrict__ root1,
                        const float* __restrict__ b1, const int* __restrict__ cl1) {
    __shared__ float As[64 * 64];   // [kk][m] transposed
    __shared__ float Bs[64 * 64];   // [kk][o]
    int tid = threadIdx.x;
    int m0  = blockIdx.x * 64;
    float* P = pool();

    int tx = tid % 16;
    int ty = tid / 16;

    unsigned long long acc[2][4];
#pragma unroll
    for (int i = 0; i < 2; i++)
#pragma unroll
        for (int j = 0; j < 4; j++) acc[i][j] = 0ull;

    for (int ch = 0; ch < 2; ch++) {
        __syncthreads();
        for (int idx = tid; idx < 64 * 16; idx += 256) {
            int m = idx >> 4;
            int q = idx & 15;
            float4 v = make_float4(0.f, 0.f, 0.f, 0.f);
            if (m0 + m < cN1) v = *(const float4*)(P + O_C1 + (m0 + m) * 128 + ch * 64 + q * 4);
            As[(q * 4 + 0) * 64 + m] = v.x;
            As[(q * 4 + 1) * 64 + m] = v.y;
            As[(q * 4 + 2) * 64 + m] = v.z;
            As[(q * 4 + 3) * 64 + m] = v.w;
        }
        for (int idx = tid; idx < 64 * 16; idx += 256) {
            int kk = idx >> 4;
            int o4 = idx & 15;
            int g = ch * 64 + kk;
            float4 v = make_float4(0.f, 0.f, 0.f, 0.f);
            if (g < cK) v = *(const float4*)(W1 + g * 64 + o4 * 4);
            *(float4*)&Bs[kk * 64 + o4 * 4] = v;
        }
        __syncthreads();

#pragma unroll 4
        for (int kk = 0; kk < 64; kk++) {
            ulonglong2 a01 = *(const ulonglong2*)&As[kk * 64 + ty * 4];
            float4 b = *(const float4*)&Bs[kk * 64 + tx * 4];
            unsigned long long b0 = pk2(b.x, b.x);
            unsigned long long b1v = pk2(b.y, b.y);
            unsigned long long b2 = pk2(b.z, b.z);
            unsigned long long b3 = pk2(b.w, b.w);
            FMA2(acc[0][0], a01.x, b0); FMA2(acc[0][1], a01.x, b1v);
            FMA2(acc[0][2], a01.x, b2); FMA2(acc[0][3], a01.x, b3);
            FMA2(acc[1][0], a01.y, b0); FMA2(acc[1][1], a01.y, b1v);
            FMA2(acc[1][2], a01.y, b2); FMA2(acc[1][3], a01.y, b3);
        }
    }

    float4 rt4 = *(const float4*)(root1 + tx * 4);
    float4 bb4 = *(const float4*)(b1 + tx * 4);
#pragma unroll
    for (int rp = 0; rp < 2; rp++) {
        float lo0, hi0, lo1, hi1, lo2, hi2, lo3, hi3;
        upk2(acc[rp][0], lo0, hi0);
        upk2(acc[rp][1], lo1, hi1);
        upk2(acc[rp][2], lo2, hi2);
        upk2(acc[rp][3], lo3, hi3);
#pragma unroll
        for (int rr = 0; rr < 2; rr++) {
            int m = m0 + ty * 4 + 2 * rp + rr;
            if (m >= cN1) continue;
            float v0 = rr ? hi0 : lo0, v1 = rr ? hi1 : lo1;
            float v2 = rr ? hi2 : lo2, v3 = rr ? hi3 : lo3;
            float invd = 1.0f / fmaxf(P[O_DEG1 + m], 1.0f);
            float h = fixf(P[O_H1 + m]);
            float* dst = P + O_H2 + (cl1[m] << 6) + tx * 4;
            atomicMaxFloat(dst + 0, eluf(v0 * invd + h * rt4.x + bb4.x));
            atomicMaxFloat(dst + 1, eluf(v1 * invd + h * rt4.y + bb4.y));
            atomicMaxFloat(dst + 2, eluf(v2 * invd + h * rt4.z + bb4.z));
            atomicMaxFloat(dst + 3, eluf(v3 * invd + h * rt4.w + bb4.w));
        }
    }
}

// ---------------- tensor-core batched GEMM via mma.sync ----------------
// XWh[k] = f16( f16(fix(X)) @ f16(W[k]) ), X: Nn x 64, W[k]: 64 x OT.
// 256 threads = 8 warps; warp w owns rows [16w,16w+16) of a 128-row M tile.
// A smem: 128 rows x 64 f16, row stride 72 halves (144B -> conflict-free frags).
// B smem: OT rows (cols of W) x 64 f16, same stride.
// blockIdx.y selects a group of KPG k values (amortizes A conversion).
template<int OT, int KPG>
__global__ void __launch_bounds__(256) gemm_mma(int xoff, const __half2* __restrict__ Wh,
                                                __half2* __restrict__ XWh, int Nn) {
    constexpr int AST = 72;  // half stride per A/B row
    __shared__ __half As[128 * AST];
    __shared__ __half Bs[OT * AST];

    int tid = threadIdx.x, wid = tid >> 5, lane = tid & 31;
    int g = lane >> 2, t = lane & 3;
    int m0 = blockIdx.x * 128;
    int k0 = blockIdx.y * KPG;
    const float* X = pool() + xoff;

    // A conversion: fix(X) -> f16
    for (int idx = tid; idx < 128 * 32; idx += 256) {
        int r = idx >> 5, p = idx & 31;
        float2 v = make_float2(0.f, 0.f);
        if (m0 + r < Nn) {
            v = *(const float2*)(X + (size_t)(m0 + r) * 64 + p * 2);
            v.x = fixf(v.x); v.y = fixf(v.y);
        }
        *(__half2*)&As[r * AST + 2 * p] = __floats2half2_rn(v.x, v.y);
    }

    const uint32_t* A32 = (const uint32_t*)As;
    const uint32_t* B32 = (const uint32_t*)Bs;
    int mw = wid * 16;

    for (int j = 0; j < KPG; j++) {
        int k = k0 + j;
        __syncthreads();   // prior compute done (and A conversion on j=0)
        // load B = Wh[k] : OT rows x 32 half2
        for (int idx = tid; idx < OT * 32; idx += 256) {
            int r = idx >> 5, p = idx & 31;
            *(__half2*)&Bs[r * AST + 2 * p] = Wh[((size_t)k * OT + r) * 32 + p];
        }
        __syncthreads();

        float c[OT / 8][4];
#pragma unroll
        for (int nt = 0; nt < OT / 8; nt++) {
            c[nt][0] = 0.f; c[nt][1] = 0.f; c[nt][2] = 0.f; c[nt][3] = 0.f;
        }
#pragma unroll
        for (int ks = 0; ks < 4; ks++) {
            // A fragment (rows mw+g, mw+g+8; k cols ks*16 + {2t, 2t+8})
            uint32_t a0 = A32[((mw + g) * AST + ks * 16) / 2 + t];
            uint32_t a1 = A32[((mw + g + 8) * AST + ks * 16) / 2 + t];
            uint32_t a2 = A32[((mw + g) * AST + ks * 16 + 8) / 2 + t];
            uint32_t a3 = A32[((mw + g + 8) * AST + ks * 16 + 8) / 2 + t];
#pragma unroll
            for (int nt = 0; nt < OT / 8; nt++) {
                uint32_t b0 = B32[((nt * 8 + g) * AST + ks * 16) / 2 + t];
                uint32_t b1 = B32[((nt * 8 + g) * AST + ks * 16 + 8) / 2 + t];
                mma16816(c[nt], a0, a1, a2, a3, b0, b1);
            }
        }
        // store: lane covers (row mw+g, col nt*8+2t..+1) and (row mw+g+8, same cols)
        int mA = m0 + mw + g;
        int mB = mA + 8;
        __half2* dA = XWh + ((size_t)k * Nn + mA) * (OT / 2) + t;
        __half2* dB = XWh + ((size_t)k * Nn + mB) * (OT / 2) + t;
#pragma unroll
        for (int nt = 0; nt < OT / 8; nt++) {
            if (mA < Nn) dA[nt * 4] = __floats2half2_rn(c[nt][0], c[nt][1]);
            if (mB < Nn) dB[nt * 4] = __floats2half2_rn(c[nt][2], c[nt][3]);
        }
    }
}

// ---------------- gather layer2: warp per edge, f16 XW ----------------
__global__ void gather_64(const int* __restrict__ edge, int E, const float* __restrict__ ps,
                          const __half2* __restrict__ XWh, int Nn, int aggoff, int degoff) {
    int gw = (blockIdx.x * blockDim.x + threadIdx.x) >> 5;
    if (gw >= E) return;
    int lane = threadIdx.x & 31;
    float g0[2], g1[2], g2[2]; int kb;
    load_pseudo(ps, gw, g0, g1, g2, kb);
    int src = edge[gw];
    int dst = edge[E + gw];
    float ax = 0.0f, ay = 0.0f;
#pragma unroll
    for (int s = 0; s < 8; s++) {
        float basis = g0[s & 1] * g1[(s >> 1) & 1] * g2[s >> 2];
        int k = kb + (s & 1) + 5 * ((s >> 1) & 1) + 25 * (s >> 2);
        __half2 h = XWh[((size_t)k * Nn + src) * 32 + lane];
        float2 v = __half22float2(h);
        ax = fmaf(basis, v.x, ax);
        ay = fmaf(basis, v.y, ay);
    }
    float* P = pool();
    redAdd2(P + aggoff + dst * 64 + 2 * lane, ax, ay);
    if (lane == 0) atomicAdd(P + degoff + dst, 1.0f);
}

// ---------------- gather layer3: warp per edge, f16 XW ----------------
__global__ void gather_128(const int* __restrict__ edge, int E, const float* __restrict__ ps,
                           const __half2* __restrict__ XWh, int Nn, int aggoff, int degoff) {
    int gw = (blockIdx.x * blockDim.x + threadIdx.x) >> 5;
    if (gw >= E) return;
    int lane = threadIdx.x & 31;
    float g0[2], g1[2], g2[2]; int kb;
    load_pseudo(ps, gw, g0, g1, g2, kb);
    int src = edge[gw];
    int dst = edge[E + gw];
    float a0 = 0.0f, a1 = 0.0f, a2 = 0.0f, a3 = 0.0f;
#pragma unroll
    for (int s = 0; s < 8; s++) {
        float basis = g0[s & 1] * g1[(s >> 1) & 1] * g2[s >> 2];
        int k = kb + (s & 1) + 5 * ((s >> 1) & 1) + 25 * (s >> 2);
        uint2 u = *((const uint2*)(XWh + ((size_t)k * Nn + src) * 64) + lane);
        float2 v0 = __half22float2(*(const __half2*)&u.x);
        float2 v1 = __half22float2(*(const __half2*)&u.y);
        a0 = fmaf(basis, v0.x, a0);
        a1 = fmaf(basis, v0.y, a1);
        a2 = fmaf(basis, v1.x, a2);
        a3 = fmaf(basis, v1.y, a3);
    }
    float* P = pool();
    redAdd4(P + aggoff + dst * 128 + 4 * lane, a0, a1, a2, a3);
    if (lane == 0) atomicAdd(P + degoff + dst, 1.0f);
}

// ---------------- node update + fused seg-max into next H ----------------
__global__ void node_dense(int hoff, int aggoff, int degoff, const int* __restrict__ cl,
                           int outoff, const float* __restrict__ root,
                           const float* __restrict__ bias, int ntot, int shift) {
    int t = blockIdx.x * blockDim.x + threadIdx.x;
    if (t >= ntot) return;
    int n = t >> shift;
    int o = t & ((1 << shift) - 1);
    float* P = pool();
    const float* h = P + hoff + n * 64;
    float acc = bias[o] + P[aggoff + t] / fmaxf(P[degoff + n], 1.0f);
#pragma unroll 16
    for (int i = 0; i < 64; i++)
        acc = fmaf(fixf(h[i]), root[(i << shift) + o], acc);
    atomicMaxFloat(P + outoff + (cl[n] << shift) + o, eluf(acc));
}

// ---------------- final MLP + log_softmax ----------------
__global__ void fc_kernel(const float* __restrict__ w1, const float* __restrict__ b1,
                          const float* __restrict__ w2, const float* __restrict__ b2,
                          float* __restrict__ out) {
    __shared__ float xrow[1024];
    __shared__ float hrow[256];
    __shared__ float logits[10];
    __shared__ float red[2];
    int b = blockIdx.x;
    int t = threadIdx.x;
    float* P = pool();
    for (int i = t; i < 1024; i += 256) xrow[i] = fixf(P[O_H4 + b * 1024 + i]);
    __syncthreads();

    float acc = b1[t];
#pragma unroll 8
    for (int i = 0; i < 1024; i++)
        acc = fmaf(xrow[i], w1[i * 256 + t], acc);
    hrow[t] = eluf(acc);
    __syncthreads();

    if (t < 10) {
        float a = b2[t];
#pragma unroll 8
        for (int i = 0; i < 256; i++)
            a = fmaf(hrow[i], w2[i * 10 + t], a);
        logits[t] = a;
    }
    __syncthreads();
    if (t == 0) {
        float m = logits[0];
        for (int j = 1; j < 10; j++) m = fmaxf(m, logits[j]);
        float s = 0.0f;
        for (int j = 0; j < 10; j++) s += expf(logits[j] - m);
        red[0] = m;
        red[1] = logf(s);
    }
    __syncthreads();
    if (t < 10) out[b * 10 + t] = logits[t] - red[0] - red[1];
}

// ---------------- host ----------------
extern "C" void kernel_launch(void* const* d_in, const int* in_sizes, int n_in,
                              void* d_out, int out_size) {
    const float* x0      = (const float*)d_in[0];
    const int*   cl0     = (const int*)  d_in[1];
    const int*   edge1   = (const int*)  d_in[2];
    const float* pseudo1 = (const float*)d_in[3];
    const float* W1      = (const float*)d_in[4];
    const float* root1   = (const float*)d_in[5];
    const float* b1      = (const float*)d_in[6];
    const int*   cl1     = (const int*)  d_in[7];
    const int*   edge2   = (const int*)  d_in[8];
    const float* pseudo2 = (const float*)d_in[9];
    const float* W2      = (const float*)d_in[10];
    const float* root2   = (const float*)d_in[11];
    const float* b2      = (const float*)d_in[12];
    const int*   cl2     = (const int*)  d_in[13];
    const int*   edge3   = (const int*)  d_in[14];
    const float* pseudo3 = (const float*)d_in[15];
    const float* W3      = (const float*)d_in[16];
    const float* root3   = (const float*)d_in[17];
    const float* b3      = (const float*)d_in[18];
    const int*   cl3     = (const int*)  d_in[19];
    const float* fc1w    = (const float*)d_in[20];
    const float* fc1b    = (const float*)d_in[21];
    const float* fc2w    = (const float*)d_in[22];
    const float* fc2b    = (const float*)d_in[23];
    float* out = (float*)d_out;

    const int TB = 256;

    __half2* xw2h; __half2* xw3h; __half2* w2h; __half2* w3h;
    cudaGetSymbolAddress((void**)&xw2h, g_xw2h4);
    cudaGetSymbolAddress((void**)&xw3h, g_xw3h4);
    cudaGetSymbolAddress((void**)&w2h, g_w2h4);
    cudaGetSymbolAddress((void**)&w3h, g_w3h4);

    // 1: init
    init_all<<<1024, TB>>>();
    // 2-3: W -> f16 [k][o][kk]
    convert_w<64><<<CDIV(cK * 64 * 32, TB), TB>>>(W2, w2h);
    convert_w<128><<<CDIV(cK * 128 * 32, TB), TB>>>(W3, w3h);
    // 4: seg_max(x0) -> H1
    segmax_x0_kernel<<<CDIV(cN0, TB), TB>>>(x0, cl0);
    // 5: layer-1 scatter
    l1_scatter<<<CDIV(cE1, TB), TB>>>(edge1, pseudo1);
    // 6: layer-1 GEMM + node update + seg-max -> H2
    l1_gemm<<<CDIV(cN1, 64), 256>>>(W1, root1, b1, cl1);
    // 7: layer-2 tensor-core GEMM -> XW2 (f16)
    {
        dim3 g(CDIV(cN2, 128), 25);
        gemm_mma<64, 5><<<g, 256>>>(O_H2, w2h, xw2h, cN2);
    }
    // 8: layer-2 gather
    gather_64<<<CDIV(cE2 * 32, TB), TB>>>(edge2, cE2, pseudo2, xw2h, cN2, O_AGG2, O_DEG2);
    // 9: layer-2 node update + seg-max -> H3
    node_dense<<<CDIV(cN2 * 64, TB), TB>>>(O_H2, O_AGG2, O_DEG2, cl2, O_H3, root2, b2, cN2 * 64, 6);
    // 10: layer-3 tensor-core GEMM -> XW3 (f16)
    {
        dim3 g(CDIV(cN3, 128), 25);
        gemm_mma<128, 5><<<g, 256>>>(O_H3, w3h, xw3h, cN3);
    }
    // 11: layer-3 gather
    gather_128<<<CDIV(cE3 * 32, TB), TB>>>(edge3, cE3, pseudo3, xw3h, cN3, O_AGG3, O_DEG3);
    // 12: layer-3 node update + seg-max -> H4
    node_dense<<<CDIV(cN3 * 128, TB), TB>>>(O_H3, O_AGG3, O_DEG3, cl3, O_H4, root3, b3, cN3 * 128, 7);
    // 13: MLP head + log_softmax
    fc_kernel<<<cB, 256>>>(fc1w, fc1b, fc2w, fc2b, out);
}

// round 9
// speedup vs baseline: 3.7893x; 1.0055x over previous
#include <cuda_runtime.h>
#include <cuda_fp16.h>
#include <math.h>
#include <stdint.h>

#define CDIV(a,b) (((a)+(b)-1)/(b))

// Problem constants
constexpr int cN0 = 120000;
constexpr int cN1 = 20000;
constexpr int cN2 = 6000;
constexpr int cN3 = 1600;
constexpr int cB  = 64;
constexpr int cE1 = 480000;
constexpr int cE2 = 144000;
constexpr int cE3 = 38400;
constexpr int cK  = 125;

// ---------------- scratch pool (no cudaMalloc allowed) ----------------
constexpr int AL64(int x) { return (x + 63) & ~63; }
constexpr int O_H1   = 0;
constexpr int O_C1   = O_H1   + AL64(cN1);      // c[dst][128] (125 used)
constexpr int O_DEG1 = O_C1   + cN1 * 128;
constexpr int O_H2   = O_DEG1 + AL64(cN1);
constexpr int O_AGG2 = O_H2   + cN2 * 64;
constexpr int O_DEG2 = O_AGG2 + cN2 * 64;
constexpr int O_H3   = O_DEG2 + AL64(cN2);
constexpr int O_AGG3 = O_H3   + cN3 * 64;
constexpr int O_DEG3 = O_AGG3 + cN3 * 128;
constexpr int O_H4   = O_DEG3 + AL64(cN3);
constexpr int POOLN  = O_H4   + 512 * 128;

__device__ float4 g_pool4[(POOLN + 3) / 4];
__device__ __forceinline__ float* pool() { return (float*)g_pool4; }

// XW scratch in f16: XW2h[k][n][64], XW3h[k][n][128]
__device__ uint4 g_xw2h4[(size_t)cK * cN2 * 64 * 2 / 16];   // 96 MB
__device__ uint4 g_xw3h4[(size_t)cK * cN3 * 128 * 2 / 16];  // 51.2 MB
// f16 W tiles, layout [k][o][kk] (kk contiguous, 64 per row) = B col-major for mma
__device__ uint4 g_w2h4[cK * 64 * 64 * 2 / 16];    // 1 MB
__device__ uint4 g_w3h4[cK * 128 * 64 * 2 / 16];   // 2 MB

// ---------------- helpers ----------------
__device__ __forceinline__ void atomicMaxFloat(float* addr, float val) {
    if (val >= 0.0f)
        atomicMax((int*)addr, __float_as_int(val));
    else
        atomicMin((unsigned int*)addr, __float_as_uint(val));
}
__device__ __forceinline__ void redAdd4(float* addr, float a, float b, float c, float d) {
    asm volatile("red.global.add.v4.f32 [%0], {%1,%2,%3,%4};"
                 :: "l"(addr), "f"(a), "f"(b), "f"(c), "f"(d) : "memory");
}
__device__ __forceinline__ unsigned long long pk2(float x, float y) {
    unsigned long long r;
    asm("mov.b64 %0, {%1,%2};" : "=l"(r) : "f"(x), "f"(y));
    return r;
}
__device__ __forceinline__ void upk2(unsigned long long v, float& x, float& y) {
    asm("mov.b64 {%0,%1}, %2;" : "=f"(x), "=f"(y) : "l"(v));
}
#define FMA2(d, a, b) asm("fma.rn.f32x2 %0, %1, %2, %0;" : "+l"(d) : "l"(a), "l"(b))

__device__ __forceinline__ float eluf(float v) { return v > 0.0f ? v : expm1f(v); }
__device__ __forceinline__ float fixf(float v) { return isfinite(v) ? v : 0.0f; }

// mma.sync m16n8k16 f16 x f16 -> f32 (sm_80+; works on compute_103)
__device__ __forceinline__ void mma16816(float c[4], uint32_t a0, uint32_t a1,
                                         uint32_t a2, uint32_t a3,
                                         uint32_t b0, uint32_t b1) {
    asm volatile("mma.sync.aligned.m16n8k16.row.col.f32.f16.f16.f32 "
                 "{%0,%1,%2,%3}, {%4,%5,%6,%7}, {%8,%9}, {%0,%1,%2,%3};"
                 : "+f"(c[0]), "+f"(c[1]), "+f"(c[2]), "+f"(c[3])
                 : "r"(a0), "r"(a1), "r"(a2), "r"(a3), "r"(b0), "r"(b1));
}

// ---------------- init: -inf seg-max buffers, zero accumulators ----------------
__global__ void init_all() {
    float* P = pool();
    const float NI = -INFINITY;
    int t = blockIdx.x * blockDim.x + threadIdx.x;
    int stride = gridDim.x * blockDim.x;
    for (int i = t; i < cN1; i += stride) P[O_H1 + i] = NI;
    for (int i = t; i < cN2 * 64; i += stride) P[O_H2 + i] = NI;
    for (int i = t; i < cN3 * 64; i += stride) P[O_H3 + i] = NI;
    for (int i = t; i < 512 * 128; i += stride) P[O_H4 + i] = NI;
    for (int i = t; i < cN1 * 128; i += stride) P[O_C1 + i] = 0.0f;
    for (int i = t; i < cN1; i += stride) P[O_DEG1 + i] = 0.0f;
    for (int i = t; i < cN2 * 64; i += stride) P[O_AGG2 + i] = 0.0f;
    for (int i = t; i < cN2; i += stride) P[O_DEG2 + i] = 0.0f;
    for (int i = t; i < cN3 * 128; i += stride) P[O_AGG3 + i] = 0.0f;
    for (int i = t; i < cN3; i += stride) P[O_DEG3 + i] = 0.0f;
}

__global__ void segmax_x0_kernel(const float* __restrict__ x, const int* __restrict__ cl) {
    int t = blockIdx.x * blockDim.x + threadIdx.x;
    if (t >= cN0) return;
    atomicMaxFloat(pool() + O_H1 + cl[t], x[t]);
}

// ---------------- W2+W3 -> f16, layout [k][o][kk], one launch ----------------
__global__ void convert_w_all(const float* __restrict__ W2, const float* __restrict__ W3,
                              __half2* __restrict__ Wh2, __half2* __restrict__ Wh3) {
    constexpr int n2 = cK * 64 * 32;
    constexpr int n3 = cK * 128 * 32;
    int idx = blockIdx.x * blockDim.x + threadIdx.x;
    if (idx < n2) {
        int k = idx / (64 * 32);
        int rem = idx % (64 * 32);
        int o = rem >> 5, ip = rem & 31;
        const float* wk = W2 + (size_t)k * 64 * 64;
        Wh2[((size_t)k * 64 + o) * 32 + ip] =
            __floats2half2_rn(wk[(2 * ip) * 64 + o], wk[(2 * ip + 1) * 64 + o]);
    } else if (idx < n2 + n3) {
        int j = idx - n2;
        int k = j / (128 * 32);
        int rem = j % (128 * 32);
        int o = rem >> 5, ip = rem & 31;
        const float* wk = W3 + (size_t)k * 64 * 128;
        Wh3[((size_t)k * 128 + o) * 32 + ip] =
            __floats2half2_rn(wk[(2 * ip) * 128 + o], wk[(2 * ip + 1) * 128 + o]);
    }
}

// ---------------- spline basis ----------------
__device__ __forceinline__ void load_pseudo(const float* __restrict__ ps, int e,
                                            float g0[2], float g1[2], float g2[2], int& kbase) {
    float p0 = ps[e * 3 + 0] * 4.0f;
    float p1 = ps[e * 3 + 1] * 4.0f;
    float p2 = ps[e * 3 + 2] * 4.0f;
    float lo0 = fmaxf(fminf(floorf(p0), 3.0f), 0.0f);
    float lo1 = fmaxf(fminf(floorf(p1), 3.0f), 0.0f);
    float lo2 = fmaxf(fminf(floorf(p2), 3.0f), 0.0f);
    float f0 = p0 - lo0, f1 = p1 - lo1, f2 = p2 - lo2;
    g0[0] = 1.0f - f0; g0[1] = f0;
    g1[0] = 1.0f - f1; g1[1] = f1;
    g2[0] = 1.0f - f2; g2[1] = f2;
    kbase = (int)lo0 + 5 * (int)lo1 + 25 * (int)lo2;
}

// ---------------- layer 1 scatter: c[dst][k] += basis * x_src ----------------
__global__ void l1_scatter(const int* __restrict__ edge, const float* __restrict__ ps) {
    int e = blockIdx.x * blockDim.x + threadIdx.x;
    if (e >= cE1) return;
    float g0[2], g1[2], g2[2]; int kb;
    load_pseudo(ps, e, g0, g1, g2, kb);
    int src = edge[e];
    int dst = edge[cE1 + e];
    float* P = pool();
    float xs = fixf(P[O_H1 + src]);
    float* c = P + O_C1 + dst * 128 + kb;
#pragma unroll
    for (int s = 0; s < 8; s++) {
        float basis = g0[s & 1] * g1[(s >> 1) & 1] * g2[s >> 2];
        int ko = (s & 1) + 5 * ((s >> 1) & 1) + 25 * (s >> 2);
        atomicAdd(c + ko, basis * xs);
    }
    atomicAdd(P + O_DEG1 + dst, 1.0f);
}

// ---------------- layer 1 GEMM (32-row tiles) + node update + seg-max -> H2 ----------------
__global__ void l1_gemm(const float* __restrict__ W1, const float* __restrict__ root1,
                        const float* __restrict__ b1, const int* __restrict__ cl1) {
    __shared__ float As[64 * 32];   // [kk][m] transposed
    __shared__ float Bs[64 * 64];   // [kk][o]
    int tid = threadIdx.x;          // 256
    int m0  = blockIdx.x * 32;
    float* P = pool();

    int tx = tid % 16;              // cols tx*4 .. +3
    int ty = tid / 16;              // row pair 2*ty

    unsigned long long acc[4];
#pragma unroll
    for (int j = 0; j < 4; j++) acc[j] = 0ull;

    for (int ch = 0; ch < 2; ch++) {
        __syncthreads();
        for (int idx = tid; idx < 32 * 16; idx += 256) {
            int m = idx >> 4;
            int q = idx & 15;
            float4 v = make_float4(0.f, 0.f, 0.f, 0.f);
            if (m0 + m < cN1) v = *(const float4*)(P + O_C1 + (m0 + m) * 128 + ch * 64 + q * 4);
            As[(q * 4 + 0) * 32 + m] = v.x;
            As[(q * 4 + 1) * 32 + m] = v.y;
            As[(q * 4 + 2) * 32 + m] = v.z;
            As[(q * 4 + 3) * 32 + m] = v.w;
        }
        for (int idx = tid; idx < 64 * 16; idx += 256) {
            int kk = idx >> 4;
            int o4 = idx & 15;
            int g = ch * 64 + kk;
            float4 v = make_float4(0.f, 0.f, 0.f, 0.f);
            if (g < cK) v = *(const float4*)(W1 + g * 64 + o4 * 4);
            *(float4*)&Bs[kk * 64 + o4 * 4] = v;
        }
        __syncthreads();

#pragma unroll 8
        for (int kk = 0; kk < 64; kk++) {
            unsigned long long a01 = *(const unsigned long long*)&As[kk * 32 + ty * 2];
            float4 b = *(const float4*)&Bs[kk * 64 + tx * 4];
            FMA2(acc[0], a01, pk2(b.x, b.x));
            FMA2(acc[1], a01, pk2(b.y, b.y));
            FMA2(acc[2], a01, pk2(b.z, b.z));
            FMA2(acc[3], a01, pk2(b.w, b.w));
        }
    }

    float4 rt4 = *(const float4*)(root1 + tx * 4);
    float4 bb4 = *(const float4*)(b1 + tx * 4);
    float lo0, hi0, lo1, hi1, lo2, hi2, lo3, hi3;
    upk2(acc[0], lo0, hi0);
    upk2(acc[1], lo1, hi1);
    upk2(acc[2], lo2, hi2);
    upk2(acc[3], lo3, hi3);
#pragma unroll
    for (int rr = 0; rr < 2; rr++) {
        int m = m0 + ty * 2 + rr;
        if (m >= cN1) continue;
        float v0 = rr ? hi0 : lo0, v1 = rr ? hi1 : lo1;
        float v2 = rr ? hi2 : lo2, v3 = rr ? hi3 : lo3;
        float invd = 1.0f / fmaxf(P[O_DEG1 + m], 1.0f);
        float h = fixf(P[O_H1 + m]);
        float* dst = P + O_H2 + (cl1[m] << 6) + tx * 4;
        atomicMaxFloat(dst + 0, eluf(v0 * invd + h * rt4.x + bb4.x));
        atomicMaxFloat(dst + 1, eluf(v1 * invd + h * rt4.y + bb4.y));
        atomicMaxFloat(dst + 2, eluf(v2 * invd + h * rt4.z + bb4.z));
        atomicMaxFloat(dst + 3, eluf(v3 * invd + h * rt4.w + bb4.w));
    }
}

// ---------------- tensor-core batched GEMM via mma.sync ----------------
template<int OT, int KPG>
__global__ void __launch_bounds__(256) gemm_mma(int xoff, const __half2* __restrict__ Wh,
                                                __half2* __restrict__ XWh, int Nn) {
    constexpr int AST = 72;  // half stride per A/B row
    __shared__ __half As[128 * AST];
    __shared__ __half Bs[OT * AST];

    int tid = threadIdx.x, wid = tid >> 5, lane = tid & 31;
    int g = lane >> 2, t = lane & 3;
    int m0 = blockIdx.x * 128;
    int k0 = blockIdx.y * KPG;
    const float* X = pool() + xoff;

    // A conversion: fix(X) -> f16
    for (int idx = tid; idx < 128 * 32; idx += 256) {
        int r = idx >> 5, p = idx & 31;
        float2 v = make_float2(0.f, 0.f);
        if (m0 + r < Nn) {
            v = *(const float2*)(X + (size_t)(m0 + r) * 64 + p * 2);
            v.x = fixf(v.x); v.y = fixf(v.y);
        }
        *(__half2*)&As[r * AST + 2 * p] = __floats2half2_rn(v.x, v.y);
    }

    const uint32_t* A32 = (const uint32_t*)As;
    const uint32_t* B32 = (const uint32_t*)Bs;
    int mw = wid * 16;

    for (int j = 0; j < KPG; j++) {
        int k = k0 + j;
        __syncthreads();
        for (int idx = tid; idx < OT * 32; idx += 256) {
            int r = idx >> 5, p = idx & 31;
            *(__half2*)&Bs[r * AST + 2 * p] = Wh[((size_t)k * OT + r) * 32 + p];
        }
        __syncthreads();

        float c[OT / 8][4];
#pragma unroll
        for (int nt = 0; nt < OT / 8; nt++) {
            c[nt][0] = 0.f; c[nt][1] = 0.f; c[nt][2] = 0.f; c[nt][3] = 0.f;
        }
#pragma unroll
        for (int ks = 0; ks < 4; ks++) {
            uint32_t a0 = A32[((mw + g) * AST + ks * 16) / 2 + t];
            uint32_t a1 = A32[((mw + g + 8) * AST + ks * 16) / 2 + t];
            uint32_t a2 = A32[((mw + g) * AST + ks * 16 + 8) / 2 + t];
            uint32_t a3 = A32[((mw + g + 8) * AST + ks * 16 + 8) / 2 + t];
#pragma unroll
            for (int nt = 0; nt < OT / 8; nt++) {
                uint32_t b0 = B32[((nt * 8 + g) * AST + ks * 16) / 2 + t];
                uint32_t b1 = B32[((nt * 8 + g) * AST + ks * 16 + 8) / 2 + t];
                mma16816(c[nt], a0, a1, a2, a3, b0, b1);
            }
        }
        int mA = m0 + mw + g;
        int mB = mA + 8;
        __half2* dA = XWh + ((size_t)k * Nn + mA) * (OT / 2) + t;
        __half2* dB = XWh + ((size_t)k * Nn + mB) * (OT / 2) + t;
#pragma unroll
        for (int nt = 0; nt < OT / 8; nt++) {
            if (mA < Nn) dA[nt * 4] = __floats2half2_rn(c[nt][0], c[nt][1]);
            if (mB < Nn) dB[nt * 4] = __floats2half2_rn(c[nt][2], c[nt][3]);
        }
    }
}

// ---------------- gather layer2: warp per edge, pair-split halves ----------------
// taps come in contiguous-k pairs; lanes 0-15 take even tap, 16-31 odd tap.
__global__ void gather_64(const int* __restrict__ edge, int E, const float* __restrict__ ps,
                          const __half2* __restrict__ XWh, int Nn, int aggoff, int degoff) {
    int gw = (blockIdx.x * blockDim.x + threadIdx.x) >> 5;
    if (gw >= E) return;
    int lane = threadIdx.x & 31;
    int half = lane >> 4, l16 = lane & 15;
    float g0[2], g1[2], g2[2]; int kb;
    load_pseudo(ps, gw, g0, g1, g2, kb);
    int src = edge[gw];
    int dst = edge[E + gw];
    float gh = g0[half];
    float a0 = 0.f, a1 = 0.f, a2 = 0.f, a3 = 0.f;
#pragma unroll
    for (int p = 0; p < 4; p++) {
        float basis = gh * g1[p & 1] * g2[p >> 1];
        int k = kb + 5 * (p & 1) + 25 * (p >> 1) + half;
        uint2 u = *((const uint2*)(XWh + ((size_t)k * Nn + src) * 32) + l16);
        float2 v0 = __half22float2(*(const __half2*)&u.x);
        float2 v1 = __half22float2(*(const __half2*)&u.y);
        a0 = fmaf(basis, v0.x, a0);
        a1 = fmaf(basis, v0.y, a1);
        a2 = fmaf(basis, v1.x, a2);
        a3 = fmaf(basis, v1.y, a3);
    }
    a0 += __shfl_xor_sync(0xffffffffu, a0, 16);
    a1 += __shfl_xor_sync(0xffffffffu, a1, 16);
    a2 += __shfl_xor_sync(0xffffffffu, a2, 16);
    a3 += __shfl_xor_sync(0xffffffffu, a3, 16);
    float* P = pool();
    if (half == 0)
        redAdd4(P + aggoff + dst * 64 + 4 * l16, a0, a1, a2, a3);
    if (lane == 0) atomicAdd(P + degoff + dst, 1.0f);
}

// ---------------- gather layer3: warp per edge, pair-split halves ----------------
__global__ void gather_128(const int* __restrict__ edge, int E, const float* __restrict__ ps,
                           const __half2* __restrict__ XWh, int Nn, int aggoff, int degoff) {
    int gw = (blockIdx.x * blockDim.x + threadIdx.x) >> 5;
    if (gw >= E) return;
    int lane = threadIdx.x & 31;
    int half = lane >> 4, l16 = lane & 15;
    float g0[2], g1[2], g2[2]; int kb;
    load_pseudo(ps, gw, g0, g1, g2, kb);
    int src = edge[gw];
    int dst = edge[E + gw];
    float gh = g0[half];
    float a[8];
#pragma unroll
    for (int i = 0; i < 8; i++) a[i] = 0.f;
#pragma unroll
    for (int p = 0; p < 4; p++) {
        float basis = gh * g1[p & 1] * g2[p >> 1];
        int k = kb + 5 * (p & 1) + 25 * (p >> 1) + half;
        uint4 u = *((const uint4*)(XWh + ((size_t)k * Nn + src) * 64) + l16);
        float2 v0 = __half22float2(*(const __half2*)&u.x);
        float2 v1 = __half22float2(*(const __half2*)&u.y);
        float2 v2 = __half22float2(*(const __half2*)&u.z);
        float2 v3 = __half22float2(*(const __half2*)&u.w);
        a[0] = fmaf(basis, v0.x, a[0]); a[1] = fmaf(basis, v0.y, a[1]);
        a[2] = fmaf(basis, v1.x, a[2]); a[3] = fmaf(basis, v1.y, a[3]);
        a[4] = fmaf(basis, v2.x, a[4]); a[5] = fmaf(basis, v2.y, a[5]);
        a[6] = fmaf(basis, v3.x, a[6]); a[7] = fmaf(basis, v3.y, a[7]);
    }
#pragma unroll
    for (int i = 0; i < 8; i++)
        a[i] += __shfl_xor_sync(0xffffffffu, a[i], 16);
    float* P = pool();
    if (half == 0) {
        redAdd4(P + aggoff + dst * 128 + 8 * l16,     a[0], a[1], a[2], a[3]);
        redAdd4(P + aggoff + dst * 128 + 8 * l16 + 4, a[4], a[5], a[6], a[7]);
    }
    if (lane == 0) atomicAdd(P + degoff + dst, 1.0f);
}

// ---------------- node update + fused seg-max into next H ----------------
__global__ void node_dense(int hoff, int aggoff, int degoff, const int* __restrict__ cl,
                           int outoff, const float* __restrict__ root,
                           const float* __restrict__ bias, int ntot, int shift) {
    int t = blockIdx.x * blockDim.x + threadIdx.x;
    if (t >= ntot) return;
    int n = t >> shift;
    int o = t & ((1 << shift) - 1);
    float* P = pool();
    const float* h = P + hoff + n * 64;
    float acc = bias[o] + P[aggoff + t] / fmaxf(P[degoff + n], 1.0f);
#pragma unroll 16
    for (int i = 0; i < 64; i++)
        acc = fmaf(fixf(h[i]), root[(i << shift) + o], acc);
    atomicMaxFloat(P + outoff + (cl[n] << shift) + o, eluf(acc));
}

// ---------------- final MLP + log_softmax ----------------
__global__ void fc_kernel(const float* __restrict__ w1, const float* __restrict__ b1,
                          const float* __restrict__ w2, const float* __restrict__ b2,
                          float* __restrict__ out) {
    __shared__ float xrow[1024];
    __shared__ float hrow[256];
    __shared__ float logits[10];
    __shared__ float red[2];
    int b = blockIdx.x;
    int t = threadIdx.x;
    float* P = pool();
    for (int i = t; i < 1024; i += 256) xrow[i] = fixf(P[O_H4 + b * 1024 + i]);
    __syncthreads();

    float acc = b1[t];
#pragma unroll 8
    for (int i = 0; i < 1024; i++)
        acc = fmaf(xrow[i], w1[i * 256 + t], acc);
    hrow[t] = eluf(acc);
    __syncthreads();

    if (t < 10) {
        float a = b2[t];
#pragma unroll 8
        for (int i = 0; i < 256; i++)
            a = fmaf(hrow[i], w2[i * 10 + t], a);
        logits[t] = a;
    }
    __syncthreads();
    if (t == 0) {
        float m = logits[0];
        for (int j = 1; j < 10; j++) m = fmaxf(m, logits[j]);
        float s = 0.0f;
        for (int j = 0; j < 10; j++) s += expf(logits[j] - m);
        red[0] = m;
        red[1] = logf(s);
    }
    __syncthreads();
    if (t < 10) out[b * 10 + t] = logits[t] - red[0] - red[1];
}

// ---------------- host ----------------
extern "C" void kernel_launch(void* const* d_in, const int* in_sizes, int n_in,
                              void* d_out, int out_size) {
    const float* x0      = (const float*)d_in[0];
    const int*   cl0     = (const int*)  d_in[1];
    const int*   edge1   = (const int*)  d_in[2];
    const float* pseudo1 = (const float*)d_in[3];
    const float* W1      = (const float*)d_in[4];
    const float* root1   = (const float*)d_in[5];
    const float* b1      = (const float*)d_in[6];
    const int*   cl1     = (const int*)  d_in[7];
    const int*   edge2   = (const int*)  d_in[8];
    const float* pseudo2 = (const float*)d_in[9];
    const float* W2      = (const float*)d_in[10];
    const float* root2   = (const float*)d_in[11];
    const float* b2      = (const float*)d_in[12];
    const int*   cl2     = (const int*)  d_in[13];
    const int*   edge3   = (const int*)  d_in[14];
    const float* pseudo3 = (const float*)d_in[15];
    const float* W3      = (const float*)d_in[16];
    const float* root3   = (const float*)d_in[17];
    const float* b3      = (const float*)d_in[18];
    const int*   cl3     = (const int*)  d_in[19];
    const float* fc1w    = (const float*)d_in[20];
    const float* fc1b    = (const float*)d_in[21];
    const float* fc2w    = (const float*)d_in[22];
    const float* fc2b    = (const float*)d_in[23];
    float* out = (float*)d_out;

    const int TB = 256;

    __half2* xw2h; __half2* xw3h; __half2* w2h; __half2* w3h;
    cudaGetSymbolAddress((void**)&xw2h, g_xw2h4);
    cudaGetSymbolAddress((void**)&xw3h, g_xw3h4);
    cudaGetSymbolAddress((void**)&w2h, g_w2h4);
    cudaGetSymbolAddress((void**)&w3h, g_w3h4);

    // 1: init
    init_all<<<1024, TB>>>();
    // 2: W2+W3 -> f16 (single launch)
    convert_w_all<<<CDIV(cK * (64 + 128) * 32, TB), TB>>>(W2, W3, w2h, w3h);
    // 3: seg_max(x0) -> H1
    segmax_x0_kernel<<<CDIV(cN0, TB), TB>>>(x0, cl0);
    // 4: layer-1 scatter (profile slot)
    l1_scatter<<<CDIV(cE1, TB), TB>>>(edge1, pseudo1);
    // 5: layer-1 GEMM + node update + seg-max -> H2
    l1_gemm<<<CDIV(cN1, 32), 256>>>(W1, root1, b1, cl1);
    // 6: layer-2 tensor-core GEMM -> XW2 (f16)
    {
        dim3 g(CDIV(cN2, 128), 25);
        gemm_mma<64, 5><<<g, 256>>>(O_H2, w2h, xw2h, cN2);
    }
    // 7: layer-2 gather
    gather_64<<<CDIV(cE2 * 32, TB), TB>>>(edge2, cE2, pseudo2, xw2h, cN2, O_AGG2, O_DEG2);
    // 8: layer-2 node update + seg-max -> H3
    node_dense<<<CDIV(cN2 * 64, TB), TB>>>(O_H2, O_AGG2, O_DEG2, cl2, O_H3, root2, b2, cN2 * 64, 6);
    // 9: layer-3 tensor-core GEMM -> XW3 (f16)
    {
        dim3 g(CDIV(cN3, 128), 25);
        gemm_mma<128, 5><<<g, 256>>>(O_H3, w3h, xw3h, cN3);
    }
    // 10: layer-3 gather
    gather_128<<<CDIV(cE3 * 32, TB), TB>>>(edge3, cE3, pseudo3, xw3h, cN3, O_AGG3, O_DEG3);
    // 11: layer-3 node update + seg-max -> H4
    node_dense<<<CDIV(cN3 * 128, TB), TB>>>(O_H3, O_AGG3, O_DEG3, cl3, O_H4, root3, b3, cN3 * 128, 7);
    // 12: MLP head + log_softmax
    fc_kernel<<<cB, 256>>>(fc1w, fc1b, fc2w, fc2b, out);
}

// round 10
// speedup vs baseline: 4.2571x; 1.1234x over previous
#include <cuda_runtime.h>
#include <cuda_fp16.h>
#include <math.h>
#include <stdint.h>

#define CDIV(a,b) (((a)+(b)-1)/(b))

// Problem constants
constexpr int cN0 = 120000;
constexpr int cN1 = 20000;
constexpr int cN2 = 6000;
constexpr int cN3 = 1600;
constexpr int cB  = 64;
constexpr int cE1 = 480000;
constexpr int cE2 = 144000;
constexpr int cE3 = 38400;
constexpr int cK  = 125;

// ---------------- scratch pool (no cudaMalloc allowed) ----------------
constexpr int AL64(int x) { return (x + 63) & ~63; }
constexpr int O_H1   = 0;
constexpr int O_C1   = O_H1   + AL64(cN1);      // c[dst][128] (125 used)
constexpr int O_DEG1 = O_C1   + cN1 * 128;
constexpr int O_H2   = O_DEG1 + AL64(cN1);
constexpr int O_AGG2 = O_H2   + cN2 * 64;
constexpr int O_DEG2 = O_AGG2 + cN2 * 64;
constexpr int O_H3   = O_DEG2 + AL64(cN2);
constexpr int O_AGG3 = O_H3   + cN3 * 64;
constexpr int O_DEG3 = O_AGG3 + cN3 * 128;
constexpr int O_H4   = O_DEG3 + AL64(cN3);
constexpr int POOLN  = O_H4   + 512 * 128;

__device__ float4 g_pool4[(POOLN + 3) / 4];
__device__ __forceinline__ float* pool() { return (float*)g_pool4; }

// XW scratch in f16: XW2h[k][n][64], XW3h[k][n][128]
__device__ uint4 g_xw2h4[(size_t)cK * cN2 * 64 * 2 / 16];   // 96 MB
__device__ uint4 g_xw3h4[(size_t)cK * cN3 * 128 * 2 / 16];  // 51.2 MB
// f16 W tiles, layout [k][o][kk] (kk contiguous, 64 per row) = B col-major for mma
__device__ uint4 g_w2h4[cK * 64 * 64 * 2 / 16];    // 1 MB
__device__ uint4 g_w3h4[cK * 128 * 64 * 2 / 16];   // 2 MB

// ---------------- helpers ----------------
__device__ __forceinline__ void atomicMaxFloat(float* addr, float val) {
    if (val >= 0.0f)
        atomicMax((int*)addr, __float_as_int(val));
    else
        atomicMin((unsigned int*)addr, __float_as_uint(val));
}
__device__ __forceinline__ void redAdd4(float* addr, float a, float b, float c, float d) {
    asm volatile("red.global.add.v4.f32 [%0], {%1,%2,%3,%4};"
                 :: "l"(addr), "f"(a), "f"(b), "f"(c), "f"(d) : "memory");
}
__device__ __forceinline__ unsigned long long pk2(float x, float y) {
    unsigned long long r;
    asm("mov.b64 %0, {%1,%2};" : "=l"(r) : "f"(x), "f"(y));
    return r;
}
__device__ __forceinline__ void upk2(unsigned long long v, float& x, float& y) {
    asm("mov.b64 {%0,%1}, %2;" : "=f"(x), "=f"(y) : "l"(v));
}
#define FMA2(d, a, b) asm("fma.rn.f32x2 %0, %1, %2, %0;" : "+l"(d) : "l"(a), "l"(b))

__device__ __forceinline__ float eluf(float v) { return v > 0.0f ? v : expm1f(v); }
__device__ __forceinline__ float fixf(float v) { return isfinite(v) ? v : 0.0f; }

__device__ __forceinline__ uint32_t su32(const void* p) {
    uint32_t a;
    asm("{ .reg .u64 t; cvta.to.shared.u64 t, %1; cvt.u32.u64 %0, t; }" : "=r"(a) : "l"(p));
    return a;
}
__device__ __forceinline__ void mma16816(float c[4], uint32_t a0, uint32_t a1,
                                         uint32_t a2, uint32_t a3,
                                         uint32_t b0, uint32_t b1) {
    asm volatile("mma.sync.aligned.m16n8k16.row.col.f32.f16.f16.f32 "
                 "{%0,%1,%2,%3}, {%4,%5,%6,%7}, {%8,%9}, {%0,%1,%2,%3};"
                 : "+f"(c[0]), "+f"(c[1]), "+f"(c[2]), "+f"(c[3])
                 : "r"(a0), "r"(a1), "r"(a2), "r"(a3), "r"(b0), "r"(b1));
}
__device__ __forceinline__ void ldmx4(uint32_t& f0, uint32_t& f1, uint32_t& f2, uint32_t& f3,
                                      uint32_t addr) {
    asm volatile("ldmatrix.sync.aligned.m8n8.x4.shared.b16 {%0,%1,%2,%3}, [%4];"
                 : "=r"(f0), "=r"(f1), "=r"(f2), "=r"(f3) : "r"(addr));
}
__device__ __forceinline__ void cpasync16(uint32_t sdst, const void* gsrc) {
    asm volatile("cp.async.cg.shared.global [%0], [%1], 16;" :: "r"(sdst), "l"(gsrc));
}
#define CP_COMMIT() asm volatile("cp.async.commit_group;" ::: "memory")

// ---------------- init + W conversion (fused, independent work) ----------------
__global__ void init_and_convert(const float* __restrict__ W2, const float* __restrict__ W3,
                                 __half2* __restrict__ Wh2, __half2* __restrict__ Wh3) {
    float* P = pool();
    const float NI = -INFINITY;
    int t = blockIdx.x * blockDim.x + threadIdx.x;
    int stride = gridDim.x * blockDim.x;
    for (int i = t; i < cN1; i += stride) P[O_H1 + i] = NI;
    for (int i = t; i < cN2 * 64; i += stride) P[O_H2 + i] = NI;
    for (int i = t; i < cN3 * 64; i += stride) P[O_H3 + i] = NI;
    for (int i = t; i < 512 * 128; i += stride) P[O_H4 + i] = NI;
    for (int i = t; i < cN1 * 128; i += stride) P[O_C1 + i] = 0.0f;
    for (int i = t; i < cN1; i += stride) P[O_DEG1 + i] = 0.0f;
    for (int i = t; i < cN2 * 64; i += stride) P[O_AGG2 + i] = 0.0f;
    for (int i = t; i < cN2; i += stride) P[O_DEG2 + i] = 0.0f;
    for (int i = t; i < cN3 * 128; i += stride) P[O_AGG3 + i] = 0.0f;
    for (int i = t; i < cN3; i += stride) P[O_DEG3 + i] = 0.0f;
    // W2 -> f16 [k][o][kk]
    for (int idx = t; idx < cK * 64 * 32; idx += stride) {
        int k = idx / (64 * 32);
        int rem = idx % (64 * 32);
        int o = rem >> 5, ip = rem & 31;
        const float* wk = W2 + (size_t)k * 64 * 64;
        Wh2[((size_t)k * 64 + o) * 32 + ip] =
            __floats2half2_rn(wk[(2 * ip) * 64 + o], wk[(2 * ip + 1) * 64 + o]);
    }
    // W3 -> f16 [k][o][kk]
    for (int idx = t; idx < cK * 128 * 32; idx += stride) {
        int k = idx / (128 * 32);
        int rem = idx % (128 * 32);
        int o = rem >> 5, ip = rem & 31;
        const float* wk = W3 + (size_t)k * 64 * 128;
        Wh3[((size_t)k * 128 + o) * 32 + ip] =
            __floats2half2_rn(wk[(2 * ip) * 128 + o], wk[(2 * ip + 1) * 128 + o]);
    }
}

__global__ void segmax_x0_kernel(const float* __restrict__ x, const int* __restrict__ cl) {
    int t = blockIdx.x * blockDim.x + threadIdx.x;
    if (t >= cN0) return;
    atomicMaxFloat(pool() + O_H1 + cl[t], x[t]);
}

// ---------------- spline basis ----------------
__device__ __forceinline__ void load_pseudo(const float* __restrict__ ps, int e,
                                            float g0[2], float g1[2], float g2[2], int& kbase) {
    float p0 = ps[e * 3 + 0] * 4.0f;
    float p1 = ps[e * 3 + 1] * 4.0f;
    float p2 = ps[e * 3 + 2] * 4.0f;
    float lo0 = fmaxf(fminf(floorf(p0), 3.0f), 0.0f);
    float lo1 = fmaxf(fminf(floorf(p1), 3.0f), 0.0f);
    float lo2 = fmaxf(fminf(floorf(p2), 3.0f), 0.0f);
    float f0 = p0 - lo0, f1 = p1 - lo1, f2 = p2 - lo2;
    g0[0] = 1.0f - f0; g0[1] = f0;
    g1[0] = 1.0f - f1; g1[1] = f1;
    g2[0] = 1.0f - f2; g2[1] = f2;
    kbase = (int)lo0 + 5 * (int)lo1 + 25 * (int)lo2;
}

// ---------------- layer 1 scatter: c[dst][k] += basis * x_src ----------------
__global__ void l1_scatter(const int* __restrict__ edge, const float* __restrict__ ps) {
    int e = blockIdx.x * blockDim.x + threadIdx.x;
    if (e >= cE1) return;
    float g0[2], g1[2], g2[2]; int kb;
    load_pseudo(ps, e, g0, g1, g2, kb);
    int src = edge[e];
    int dst = edge[cE1 + e];
    float* P = pool();
    float xs = fixf(P[O_H1 + src]);
    float* c = P + O_C1 + dst * 128 + kb;
#pragma unroll
    for (int s = 0; s < 8; s++) {
        float basis = g0[s & 1] * g1[(s >> 1) & 1] * g2[s >> 2];
        int ko = (s & 1) + 5 * ((s >> 1) & 1) + 25 * (s >> 2);
        atomicAdd(c + ko, basis * xs);
    }
    atomicAdd(P + O_DEG1 + dst, 1.0f);
}

// ---------------- layer 1 GEMM (32-row tiles) + node update + seg-max -> H2 ----------------
__global__ void l1_gemm(const float* __restrict__ W1, const float* __restrict__ root1,
                        const float* __restrict__ b1, const int* __restrict__ cl1) {
    __shared__ float As[64 * 32];   // [kk][m] transposed
    __shared__ float Bs[64 * 64];   // [kk][o]
    int tid = threadIdx.x;          // 256
    int m0  = blockIdx.x * 32;
    float* P = pool();

    int tx = tid % 16;
    int ty = tid / 16;

    unsigned long long acc[4];
#pragma unroll
    for (int j = 0; j < 4; j++) acc[j] = 0ull;

    for (int ch = 0; ch < 2; ch++) {
        __syncthreads();
        for (int idx = tid; idx < 32 * 16; idx += 256) {
            int m = idx >> 4;
            int q = idx & 15;
            float4 v = make_float4(0.f, 0.f, 0.f, 0.f);
            if (m0 + m < cN1) v = *(const float4*)(P + O_C1 + (m0 + m) * 128 + ch * 64 + q * 4);
            As[(q * 4 + 0) * 32 + m] = v.x;
            As[(q * 4 + 1) * 32 + m] = v.y;
            As[(q * 4 + 2) * 32 + m] = v.z;
            As[(q * 4 + 3) * 32 + m] = v.w;
        }
        for (int idx = tid; idx < 64 * 16; idx += 256) {
            int kk = idx >> 4;
            int o4 = idx & 15;
            int g = ch * 64 + kk;
            float4 v = make_float4(0.f, 0.f, 0.f, 0.f);
            if (g < cK) v = *(const float4*)(W1 + g * 64 + o4 * 4);
            *(float4*)&Bs[kk * 64 + o4 * 4] = v;
        }
        __syncthreads();

#pragma unroll 8
        for (int kk = 0; kk < 64; kk++) {
            unsigned long long a01 = *(const unsigned long long*)&As[kk * 32 + ty * 2];
            float4 b = *(const float4*)&Bs[kk * 64 + tx * 4];
            FMA2(acc[0], a01, pk2(b.x, b.x));
            FMA2(acc[1], a01, pk2(b.y, b.y));
            FMA2(acc[2], a01, pk2(b.z, b.z));
            FMA2(acc[3], a01, pk2(b.w, b.w));
        }
    }

    float4 rt4 = *(const float4*)(root1 + tx * 4);
    float4 bb4 = *(const float4*)(b1 + tx * 4);
    float lo0, hi0, lo1, hi1, lo2, hi2, lo3, hi3;
    upk2(acc[0], lo0, hi0);
    upk2(acc[1], lo1, hi1);
    upk2(acc[2], lo2, hi2);
    upk2(acc[3], lo3, hi3);
#pragma unroll
    for (int rr = 0; rr < 2; rr++) {
        int m = m0 + ty * 2 + rr;
        if (m >= cN1) continue;
        float v0 = rr ? hi0 : lo0, v1 = rr ? hi1 : lo1;
        float v2 = rr ? hi2 : lo2, v3 = rr ? hi3 : lo3;
        float invd = 1.0f / fmaxf(P[O_DEG1 + m], 1.0f);
        float h = fixf(P[O_H1 + m]);
        float* dst = P + O_H2 + (cl1[m] << 6) + tx * 4;
        atomicMaxFloat(dst + 0, eluf(v0 * invd + h * rt4.x + bb4.x));
        atomicMaxFloat(dst + 1, eluf(v1 * invd + h * rt4.y + bb4.y));
        atomicMaxFloat(dst + 2, eluf(v2 * invd + h * rt4.z + bb4.z));
        atomicMaxFloat(dst + 3, eluf(v3 * invd + h * rt4.w + bb4.w));
    }
}

// ---------------- tensor-core batched GEMM: ldmatrix + cp.async double-buffered B ----------------
// XWh[k] = f16( f16(fix(X)) @ f16(W[k]) ).  A tile 128x64 f16 (row stride 72 halves),
// A fragments hoisted (k-invariant). B tiles double-buffered via cp.async.
template<int OT, int KPG>
__global__ void __launch_bounds__(256) gemm_mma(int xoff, const __half2* __restrict__ Wh,
                                                __half2* __restrict__ XWh, int Nn) {
    constexpr int AST   = 72;              // halves per row (144 B)
    constexpr int ABYTES = 128 * AST * 2;  // 18432
    constexpr int BROW  = AST * 2;         // 144 B per B row
    constexpr int BBYTES = OT * BROW;      // one B buffer
    extern __shared__ char dynsmem[];
    __half* As = (__half*)dynsmem;
    char*   Bs = dynsmem + ABYTES;

    int tid = threadIdx.x, wid = tid >> 5, lane = tid & 31;
    int g = lane >> 2, t = lane & 3;
    int m0 = blockIdx.x * 128;
    int k0 = blockIdx.y * KPG;
    const float* X = pool() + xoff;
    uint32_t sbA = su32(As);
    uint32_t sbB = su32(Bs);

    // ldmatrix per-lane address components
    int lq  = lane >> 3;          // tile index 0..3
    int lr  = lane & 7;           // row within tile
    int rowq = (lq & 1) * 8 + lr; // row offset within 16-row group
    int colq = (lq >> 1) * 8;     // half-offset in k

    // A conversion: fix(X) -> f16
    for (int idx = tid; idx < 128 * 32; idx += 256) {
        int r = idx >> 5, p = idx & 31;
        float2 v = make_float2(0.f, 0.f);
        if (m0 + r < Nn) {
            v = *(const float2*)(X + (size_t)(m0 + r) * 64 + p * 2);
            v.x = fixf(v.x); v.y = fixf(v.y);
        }
        *(__half2*)&As[r * AST + 2 * p] = __floats2half2_rn(v.x, v.y);
    }

    // prefetch B for k0 into buffer 0
    {
        const char* src = (const char*)Wh + (size_t)k0 * OT * 128;
        for (int idx = tid; idx < OT * 8; idx += 256) {
            int row = idx >> 3, c = idx & 7;
            cpasync16(sbB + row * BROW + c * 16, src + idx * 16);
        }
        CP_COMMIT();
    }
    __syncthreads();

    // hoist A fragments (k-invariant): af[ks][0..3]
    int mw = wid * 16;
    uint32_t af[4][4];
#pragma unroll
    for (int ks = 0; ks < 4; ks++) {
        uint32_t addr = sbA + (uint32_t)((mw + rowq) * AST + ks * 16 + colq) * 2;
        ldmx4(af[ks][0], af[ks][1], af[ks][2], af[ks][3], addr);
    }

    for (int j = 0; j < KPG; j++) {
        int buf = j & 1;
        if (j + 1 < KPG) {
            const char* src = (const char*)Wh + (size_t)(k0 + j + 1) * OT * 128;
            uint32_t dstb = sbB + ((j + 1) & 1) * BBYTES;
            for (int idx = tid; idx < OT * 8; idx += 256) {
                int row = idx >> 3, c = idx & 7;
                cpasync16(dstb + row * BROW + c * 16, src + idx * 16);
            }
            CP_COMMIT();
            asm volatile("cp.async.wait_group 1;" ::: "memory");
        } else {
            asm volatile("cp.async.wait_group 0;" ::: "memory");
        }
        __syncthreads();

        float c[OT / 8][4];
#pragma unroll
        for (int nt = 0; nt < OT / 8; nt++) {
            c[nt][0] = 0.f; c[nt][1] = 0.f; c[nt][2] = 0.f; c[nt][3] = 0.f;
        }
        uint32_t bufb = sbB + buf * BBYTES;
#pragma unroll
        for (int ks = 0; ks < 4; ks++) {
#pragma unroll
            for (int p = 0; p < OT / 16; p++) {
                uint32_t baddr = bufb + (uint32_t)(16 * p + rowq) * BROW +
                                 (uint32_t)(ks * 16 + colq) * 2;
                uint32_t b0, b1, b2, b3;
                ldmx4(b0, b1, b2, b3, baddr);
                mma16816(c[2 * p],     af[ks][0], af[ks][1], af[ks][2], af[ks][3], b0, b2);
                mma16816(c[2 * p + 1], af[ks][0], af[ks][1], af[ks][2], af[ks][3], b1, b3);
            }
        }
        // store
        int k = k0 + j;
        int mA = m0 + mw + g;
        int mB = mA + 8;
        __half2* dA = XWh + ((size_t)k * Nn + mA) * (OT / 2) + t;
        __half2* dB = XWh + ((size_t)k * Nn + mB) * (OT / 2) + t;
#pragma unroll
        for (int nt = 0; nt < OT / 8; nt++) {
            if (mA < Nn) dA[nt * 4] = __floats2half2_rn(c[nt][0], c[nt][1]);
            if (mB < Nn) dB[nt * 4] = __floats2half2_rn(c[nt][2], c[nt][3]);
        }
        __syncthreads();
    }
}

// ---------------- gather layer2: warp per edge, pair-split halves ----------------
__global__ void gather_64(const int* __restrict__ edge, int E, const float* __restrict__ ps,
                          const __half2* __restrict__ XWh, int Nn, int aggoff, int degoff) {
    int gw = (blockIdx.x * blockDim.x + threadIdx.x) >> 5;
    if (gw >= E) return;
    int lane = threadIdx.x & 31;
    int half = lane >> 4, l16 = lane & 15;
    float g0[2], g1[2], g2[2]; int kb;
    load_pseudo(ps, gw, g0, g1, g2, kb);
    int src = edge[gw];
    int dst = edge[E + gw];
    float gh = g0[half];
    float a0 = 0.f, a1 = 0.f, a2 = 0.f, a3 = 0.f;
#pragma unroll
    for (int p = 0; p < 4; p++) {
        float basis = gh * g1[p & 1] * g2[p >> 1];
        int k = kb + 5 * (p & 1) + 25 * (p >> 1) + half;
        uint2 u = *((const uint2*)(XWh + ((size_t)k * Nn + src) * 32) + l16);
        float2 v0 = __half22float2(*(const __half2*)&u.x);
        float2 v1 = __half22float2(*(const __half2*)&u.y);
        a0 = fmaf(basis, v0.x, a0);
        a1 = fmaf(basis, v0.y, a1);
        a2 = fmaf(basis, v1.x, a2);
        a3 = fmaf(basis, v1.y, a3);
    }
    a0 += __shfl_xor_sync(0xffffffffu, a0, 16);
    a1 += __shfl_xor_sync(0xffffffffu, a1, 16);
    a2 += __shfl_xor_sync(0xffffffffu, a2, 16);
    a3 += __shfl_xor_sync(0xffffffffu, a3, 16);
    float* P = pool();
    if (half == 0)
        redAdd4(P + aggoff + dst * 64 + 4 * l16, a0, a1, a2, a3);
    if (lane == 0) atomicAdd(P + degoff + dst, 1.0f);
}

// ---------------- gather layer3: warp per edge, pair-split halves ----------------
__global__ void gather_128(const int* __restrict__ edge, int E, const float* __restrict__ ps,
                           const __half2* __restrict__ XWh, int Nn, int aggoff, int degoff) {
    int gw = (blockIdx.x * blockDim.x + threadIdx.x) >> 5;
    if (gw >= E) return;
    int lane = threadIdx.x & 31;
    int half = lane >> 4, l16 = lane & 15;
    float g0[2], g1[2], g2[2]; int kb;
    load_pseudo(ps, gw, g0, g1, g2, kb);
    int src = edge[gw];
    int dst = edge[E + gw];
    float gh = g0[half];
    float a[8];
#pragma unroll
    for (int i = 0; i < 8; i++) a[i] = 0.f;
#pragma unroll
    for (int p = 0; p < 4; p++) {
        float basis = gh * g1[p & 1] * g2[p >> 1];
        int k = kb + 5 * (p & 1) + 25 * (p >> 1) + half;
        uint4 u = *((const uint4*)(XWh + ((size_t)k * Nn + src) * 64) + l16);
        float2 v0 = __half22float2(*(const __half2*)&u.x);
        float2 v1 = __half22float2(*(const __half2*)&u.y);
        float2 v2 = __half22float2(*(const __half2*)&u.z);
        float2 v3 = __half22float2(*(const __half2*)&u.w);
        a[0] = fmaf(basis, v0.x, a[0]); a[1] = fmaf(basis, v0.y, a[1]);
        a[2] = fmaf(basis, v1.x, a[2]); a[3] = fmaf(basis, v1.y, a[3]);
        a[4] = fmaf(basis, v2.x, a[4]); a[5] = fmaf(basis, v2.y, a[5]);
        a[6] = fmaf(basis, v3.x, a[6]); a[7] = fmaf(basis, v3.y, a[7]);
    }
#pragma unroll
    for (int i = 0; i < 8; i++)
        a[i] += __shfl_xor_sync(0xffffffffu, a[i], 16);
    float* P = pool();
    if (half == 0) {
        redAdd4(P + aggoff + dst * 128 + 8 * l16,     a[0], a[1], a[2], a[3]);
        redAdd4(P + aggoff + dst * 128 + 8 * l16 + 4, a[4], a[5], a[6], a[7]);
    }
    if (lane == 0) atomicAdd(P + degoff + dst, 1.0f);
}

// ---------------- node update + fused seg-max into next H ----------------
__global__ void node_dense(int hoff, int aggoff, int degoff, const int* __restrict__ cl,
                           int outoff, const float* __restrict__ root,
                           const float* __restrict__ bias, int ntot, int shift) {
    int t = blockIdx.x * blockDim.x + threadIdx.x;
    if (t >= ntot) return;
    int n = t >> shift;
    int o = t & ((1 << shift) - 1);
    float* P = pool();
    const float* h = P + hoff + n * 64;
    float acc = bias[o] + P[aggoff + t] / fmaxf(P[degoff + n], 1.0f);
#pragma unroll 16
    for (int i = 0; i < 64; i++)
        acc = fmaf(fixf(h[i]), root[(i << shift) + o], acc);
    atomicMaxFloat(P + outoff + (cl[n] << shift) + o, eluf(acc));
}

// ---------------- final MLP + log_softmax ----------------
__global__ void fc_kernel(const float* __restrict__ w1, const float* __restrict__ b1,
                          const float* __restrict__ w2, const float* __restrict__ b2,
                          float* __restrict__ out) {
    __shared__ float xrow[1024];
    __shared__ float hrow[256];
    __shared__ float logits[10];
    __shared__ float red[2];
    int b = blockIdx.x;
    int t = threadIdx.x;
    float* P = pool();
    for (int i = t; i < 1024; i += 256) xrow[i] = fixf(P[O_H4 + b * 1024 + i]);
    __syncthreads();

    float a0 = b1[t], a1 = 0.f, a2 = 0.f, a3 = 0.f;
#pragma unroll 4
    for (int i = 0; i < 1024; i += 4) {
        a0 = fmaf(xrow[i + 0], w1[(i + 0) * 256 + t], a0);
        a1 = fmaf(xrow[i + 1], w1[(i + 1) * 256 + t], a1);
        a2 = fmaf(xrow[i + 2], w1[(i + 2) * 256 + t], a2);
        a3 = fmaf(xrow[i + 3], w1[(i + 3) * 256 + t], a3);
    }
    hrow[t] = eluf((a0 + a1) + (a2 + a3));
    __syncthreads();

    if (t < 10) {
        float a = b2[t];
#pragma unroll 8
        for (int i = 0; i < 256; i++)
            a = fmaf(hrow[i], w2[i * 10 + t], a);
        logits[t] = a;
    }
    __syncthreads();
    if (t == 0) {
        float m = logits[0];
        for (int j = 1; j < 10; j++) m = fmaxf(m, logits[j]);
        float s = 0.0f;
        for (int j = 0; j < 10; j++) s += expf(logits[j] - m);
        red[0] = m;
        red[1] = logf(s);
    }
    __syncthreads();
    if (t < 10) out[b * 10 + t] = logits[t] - red[0] - red[1];
}

// ---------------- host ----------------
extern "C" void kernel_launch(void* const* d_in, const int* in_sizes, int n_in,
                              void* d_out, int out_size) {
    const float* x0      = (const float*)d_in[0];
    const int*   cl0     = (const int*)  d_in[1];
    const int*   edge1   = (const int*)  d_in[2];
    const float* pseudo1 = (const float*)d_in[3];
    const float* W1      = (const float*)d_in[4];
    const float* root1   = (const float*)d_in[5];
    const float* b1      = (const float*)d_in[6];
    const int*   cl1     = (const int*)  d_in[7];
    const int*   edge2   = (const int*)  d_in[8];
    const float* pseudo2 = (const float*)d_in[9];
    const float* W2      = (const float*)d_in[10];
    const float* root2   = (const float*)d_in[11];
    const float* b2      = (const float*)d_in[12];
    const int*   cl2     = (const int*)  d_in[13];
    const int*   edge3   = (const int*)  d_in[14];
    const float* pseudo3 = (const float*)d_in[15];
    const float* W3      = (const float*)d_in[16];
    const float* root3   = (const float*)d_in[17];
    const float* b3      = (const float*)d_in[18];
    const int*   cl3     = (const int*)  d_in[19];
    const float* fc1w    = (const float*)d_in[20];
    const float* fc1b    = (const float*)d_in[21];
    const float* fc2w    = (const float*)d_in[22];
    const float* fc2b    = (const float*)d_in[23];
    float* out = (float*)d_out;

    const int TB = 256;

    __half2* xw2h; __half2* xw3h; __half2* w2h; __half2* w3h;
    cudaGetSymbolAddress((void**)&xw2h, g_xw2h4);
    cudaGetSymbolAddress((void**)&xw3h, g_xw3h4);
    cudaGetSymbolAddress((void**)&w2h, g_w2h4);
    cudaGetSymbolAddress((void**)&w3h, g_w3h4);

    // dynamic smem: A tile 18432 B + 2 B buffers
    const int SM64  = 18432 + 2 * 64 * 144;   // 36864
    const int SM128 = 18432 + 2 * 128 * 144;  // 55296
    cudaFuncSetAttribute(gemm_mma<64, 5>,  cudaFuncAttributeMaxDynamicSharedMemorySize, SM64);
    cudaFuncSetAttribute(gemm_mma<128, 5>, cudaFuncAttributeMaxDynamicSharedMemorySize, SM128);

    // 1: init + W conversion
    init_and_convert<<<1024, TB>>>(W2, W3, w2h, w3h);
    // 2: seg_max(x0) -> H1
    segmax_x0_kernel<<<CDIV(cN0, TB), TB>>>(x0, cl0);
    // 3: layer-1 scatter
    l1_scatter<<<CDIV(cE1, TB), TB>>>(edge1, pseudo1);
    // 4: layer-1 GEMM + node update + seg-max -> H2 (profile slot)
    l1_gemm<<<CDIV(cN1, 32), 256>>>(W1, root1, b1, cl1);
    // 5: layer-2 tensor-core GEMM -> XW2 (f16)
    {
        dim3 g(CDIV(cN2, 128), 25);
        gemm_mma<64, 5><<<g, 256, SM64>>>(O_H2, w2h, xw2h, cN2);
    }
    // 6: layer-2 gather
    gather_64<<<CDIV(cE2 * 32, TB), TB>>>(edge2, cE2, pseudo2, xw2h, cN2, O_AGG2, O_DEG2);
    // 7: layer-2 node update + seg-max -> H3
    node_dense<<<CDIV(cN2 * 64, TB), TB>>>(O_H2, O_AGG2, O_DEG2, cl2, O_H3, root2, b2, cN2 * 64, 6);
    // 8: layer-3 tensor-core GEMM -> XW3 (f16)
    {
        dim3 g(CDIV(cN3, 128), 25);
        gemm_mma<128, 5><<<g, 256, SM128>>>(O_H3, w3h, xw3h, cN3);
    }
    // 9: layer-3 gather
    gather_128<<<CDIV(cE3 * 32, TB), TB>>>(edge3, cE3, pseudo3, xw3h, cN3, O_AGG3, O_DEG3);
    // 10: layer-3 node update + seg-max -> H4
    node_dense<<<CDIV(cN3 * 128, TB), TB>>>(O_H3, O_AGG3, O_DEG3, cl3, O_H4, root3, b3, cN3 * 128, 7);
    // 11: MLP head + log_softmax
    fc_kernel<<<cB, 256>>>(fc1w, fc1b, fc2w, fc2b, out);
}

// round 11
// speedup vs baseline: 4.3485x; 1.0215x over previous
#include <cuda_runtime.h>
#include <cuda_fp16.h>
#include <math.h>
#include <stdint.h>

#define CDIV(a,b) (((a)+(b)-1)/(b))

// Problem constants
constexpr int cN0 = 120000;
constexpr int cN1 = 20000;
constexpr int cN2 = 6000;
constexpr int cN3 = 1600;
constexpr int cB  = 64;
constexpr int cE1 = 480000;
constexpr int cE2 = 144000;
constexpr int cE3 = 38400;
constexpr int cK  = 125;

// ---------------- scratch pool (no cudaMalloc allowed) ----------------
constexpr int AL64(int x) { return (x + 63) & ~63; }
constexpr int O_H1   = 0;
constexpr int O_C1   = O_H1   + AL64(cN1);      // C1v2[dst][256]: slot 2k+off (pair-vectorized)
constexpr int O_DEG1 = O_C1   + cN1 * 256;
constexpr int O_H2   = O_DEG1 + AL64(cN1);
constexpr int O_AGG2 = O_H2   + cN2 * 64;
constexpr int O_DEG2 = O_AGG2 + cN2 * 64;
constexpr int O_H3   = O_DEG2 + AL64(cN2);
constexpr int O_AGG3 = O_H3   + cN3 * 64;
constexpr int O_DEG3 = O_AGG3 + cN3 * 128;
constexpr int O_H4   = O_DEG3 + AL64(cN3);
constexpr int POOLN  = O_H4   + 512 * 128;

__device__ float4 g_pool4[(POOLN + 3) / 4];
__device__ __forceinline__ float* pool() { return (float*)g_pool4; }

// XW scratch in f16: XW2h[k][n][64], XW3h[k][n][128]
__device__ uint4 g_xw2h4[(size_t)cK * cN2 * 64 * 2 / 16];   // 96 MB
__device__ uint4 g_xw3h4[(size_t)cK * cN3 * 128 * 2 / 16];  // 51.2 MB
// f16 W tiles, layout [k][o][kk] = B col-major for mma
__device__ uint4 g_w2h4[cK * 64 * 64 * 2 / 16];    // 1 MB
__device__ uint4 g_w3h4[cK * 128 * 64 * 2 / 16];   // 2 MB
// W1 f16: [o(64)][kk(128, padded)] halves
__device__ uint4 g_w1h4[64 * 128 * 2 / 16];        // 16 KB

// ---------------- helpers ----------------
__device__ __forceinline__ void atomicMaxFloat(float* addr, float val) {
    if (val >= 0.0f)
        atomicMax((int*)addr, __float_as_int(val));
    else
        atomicMin((unsigned int*)addr, __float_as_uint(val));
}
__device__ __forceinline__ void redAdd4(float* addr, float a, float b, float c, float d) {
    asm volatile("red.global.add.v4.f32 [%0], {%1,%2,%3,%4};"
                 :: "l"(addr), "f"(a), "f"(b), "f"(c), "f"(d) : "memory");
}
__device__ __forceinline__ void redAdd2(float* addr, float a, float b) {
    asm volatile("red.global.add.v2.f32 [%0], {%1,%2};"
                 :: "l"(addr), "f"(a), "f"(b) : "memory");
}
__device__ __forceinline__ float eluf(float v) { return v > 0.0f ? v : expm1f(v); }
__device__ __forceinline__ float fixf(float v) { return isfinite(v) ? v : 0.0f; }

__device__ __forceinline__ uint32_t su32(const void* p) {
    uint32_t a;
    asm("{ .reg .u64 t; cvta.to.shared.u64 t, %1; cvt.u32.u64 %0, t; }" : "=r"(a) : "l"(p));
    return a;
}
__device__ __forceinline__ void mma16816(float c[4], uint32_t a0, uint32_t a1,
                                         uint32_t a2, uint32_t a3,
                                         uint32_t b0, uint32_t b1) {
    asm volatile("mma.sync.aligned.m16n8k16.row.col.f32.f16.f16.f32 "
                 "{%0,%1,%2,%3}, {%4,%5,%6,%7}, {%8,%9}, {%0,%1,%2,%3};"
                 : "+f"(c[0]), "+f"(c[1]), "+f"(c[2]), "+f"(c[3])
                 : "r"(a0), "r"(a1), "r"(a2), "r"(a3), "r"(b0), "r"(b1));
}
__device__ __forceinline__ void ldmx4(uint32_t& f0, uint32_t& f1, uint32_t& f2, uint32_t& f3,
                                      uint32_t addr) {
    asm volatile("ldmatrix.sync.aligned.m8n8.x4.shared.b16 {%0,%1,%2,%3}, [%4];"
                 : "=r"(f0), "=r"(f1), "=r"(f2), "=r"(f3) : "r"(addr));
}
__device__ __forceinline__ void cpasync16(uint32_t sdst, const void* gsrc) {
    asm volatile("cp.async.cg.shared.global [%0], [%1], 16;" :: "r"(sdst), "l"(gsrc));
}
#define CP_COMMIT() asm volatile("cp.async.commit_group;" ::: "memory")

// ---------------- init + W conversion (fused, independent work) ----------------
__global__ void init_and_convert(const float* __restrict__ W1, const float* __restrict__ W2,
                                 const float* __restrict__ W3, __half2* __restrict__ Wh1,
                                 __half2* __restrict__ Wh2, __half2* __restrict__ Wh3) {
    float* P = pool();
    const float NI = -INFINITY;
    int t = blockIdx.x * blockDim.x + threadIdx.x;
    int stride = gridDim.x * blockDim.x;
    for (int i = t; i < cN1; i += stride) P[O_H1 + i] = NI;
    for (int i = t; i < cN2 * 64; i += stride) P[O_H2 + i] = NI;
    for (int i = t; i < cN3 * 64; i += stride) P[O_H3 + i] = NI;
    for (int i = t; i < 512 * 128; i += stride) P[O_H4 + i] = NI;
    for (int i = t; i < cN1 * 256; i += stride) P[O_C1 + i] = 0.0f;
    for (int i = t; i < cN1; i += stride) P[O_DEG1 + i] = 0.0f;
    for (int i = t; i < cN2 * 64; i += stride) P[O_AGG2 + i] = 0.0f;
    for (int i = t; i < cN2; i += stride) P[O_DEG2 + i] = 0.0f;
    for (int i = t; i < cN3 * 128; i += stride) P[O_AGG3 + i] = 0.0f;
    for (int i = t; i < cN3; i += stride) P[O_DEG3 + i] = 0.0f;
    // W1 -> f16 [o][kk] (kk padded to 128 with zeros)
    for (int idx = t; idx < 64 * 64; idx += stride) {
        int o = idx >> 6, p = idx & 63;
        float w0 = (2 * p     < cK) ? W1[(2 * p) * 64 + o]     : 0.0f;
        float w1 = (2 * p + 1 < cK) ? W1[(2 * p + 1) * 64 + o] : 0.0f;
        Wh1[o * 64 + p] = __floats2half2_rn(w0, w1);
    }
    // W2 -> f16 [k][o][kk]
    for (int idx = t; idx < cK * 64 * 32; idx += stride) {
        int k = idx / (64 * 32);
        int rem = idx % (64 * 32);
        int o = rem >> 5, ip = rem & 31;
        const float* wk = W2 + (size_t)k * 64 * 64;
        Wh2[((size_t)k * 64 + o) * 32 + ip] =
            __floats2half2_rn(wk[(2 * ip) * 64 + o], wk[(2 * ip + 1) * 64 + o]);
    }
    // W3 -> f16 [k][o][kk]
    for (int idx = t; idx < cK * 128 * 32; idx += stride) {
        int k = idx / (128 * 32);
        int rem = idx % (128 * 32);
        int o = rem >> 5, ip = rem & 31;
        const float* wk = W3 + (size_t)k * 64 * 128;
        Wh3[((size_t)k * 128 + o) * 32 + ip] =
            __floats2half2_rn(wk[(2 * ip) * 128 + o], wk[(2 * ip + 1) * 128 + o]);
    }
}

__global__ void segmax_x0_kernel(const float* __restrict__ x, const int* __restrict__ cl) {
    int t = blockIdx.x * blockDim.x + threadIdx.x;
    if (t >= cN0) return;
    atomicMaxFloat(pool() + O_H1 + cl[t], x[t]);
}

// ---------------- spline basis ----------------
__device__ __forceinline__ void load_pseudo(const float* __restrict__ ps, int e,
                                            float g0[2], float g1[2], float g2[2], int& kbase) {
    float p0 = ps[e * 3 + 0] * 4.0f;
    float p1 = ps[e * 3 + 1] * 4.0f;
    float p2 = ps[e * 3 + 2] * 4.0f;
    float lo0 = fmaxf(fminf(floorf(p0), 3.0f), 0.0f);
    float lo1 = fmaxf(fminf(floorf(p1), 3.0f), 0.0f);
    float lo2 = fmaxf(fminf(floorf(p2), 3.0f), 0.0f);
    float f0 = p0 - lo0, f1 = p1 - lo1, f2 = p2 - lo2;
    g0[0] = 1.0f - f0; g0[1] = f0;
    g1[0] = 1.0f - f1; g1[1] = f1;
    g2[0] = 1.0f - f2; g2[1] = f2;
    kbase = (int)lo0 + 5 * (int)lo1 + 25 * (int)lo2;
}

// ---------------- layer 1 scatter: C1v2[dst][2*pairk + {0,1}] += basis * x_src ----------------
// taps pair as (kb+d, kb+d+1) for d = 5a+25b; one red.v2 per pair.
__global__ void l1_scatter(const int* __restrict__ edge, const float* __restrict__ ps) {
    int e = blockIdx.x * blockDim.x + threadIdx.x;
    if (e >= cE1) return;
    float g0[2], g1[2], g2[2]; int kb;
    load_pseudo(ps, e, g0, g1, g2, kb);
    int src = edge[e];
    int dst = edge[cE1 + e];
    float* P = pool();
    float xs = fixf(P[O_H1 + src]);
    float x0s = g0[0] * xs, x1s = g0[1] * xs;
    float* c = P + O_C1 + dst * 256;
#pragma unroll
    for (int p = 0; p < 4; p++) {
        float gb = g1[p & 1] * g2[p >> 1];
        int pairk = kb + 5 * (p & 1) + 25 * (p >> 1);
        redAdd2(c + 2 * pairk, gb * x0s, gb * x1s);
    }
    atomicAdd(P + O_DEG1 + dst, 1.0f);
}

// ---------------- layer 1 GEMM via mma.sync + fused node update + seg-max -> H2 ----------------
// A[m][k] = C1v2[m][2k] + C1v2[m][2k-1]  (f16), B = W1h [o][kk], K=128, OT=64.
__global__ void __launch_bounds__(256) l1_gemm_mma(const __half2* __restrict__ W1h,
                                                   const float* __restrict__ root1,
                                                   const float* __restrict__ b1,
                                                   const int* __restrict__ cl1) {
    constexpr int AST = 136;               // halves per A/B row (272 B)
    extern __shared__ char dynsmem[];
    __half* As = (__half*)dynsmem;                    // 128 x 136 halves
    __half* Bs = (__half*)(dynsmem + 128 * AST * 2);  // 64 x 136 halves

    int tid = threadIdx.x, wid = tid >> 5, lane = tid & 31;
    int g = lane >> 2, t = lane & 3;
    int m0 = blockIdx.x * 128;
    float* P = pool();
    uint32_t sbA = su32(As);
    uint32_t sbB = su32(Bs);

    int lq = lane >> 3, lr = lane & 7;
    int rowq = (lq & 1) * 8 + lr;
    int colq = (lq >> 1) * 8;

    // A conversion: combine slot pairs -> f16
    for (int idx = tid; idx < 128 * 64; idx += 256) {
        int r = idx >> 6, p = idx & 63;    // p = half2 col (covers k=2p, 2p+1)
        float lo = 0.f, hi = 0.f;
        int m = m0 + r;
        if (m < cN1) {
            const float* v2 = P + O_C1 + (size_t)m * 256;
            float4 u = *(const float4*)(v2 + 4 * p);
            float prev = (p > 0) ? v2[4 * p - 1] : 0.0f;
            lo = u.x + prev;       // k = 2p  : slots 4p, 4p-1
            hi = u.z + u.y;        // k = 2p+1: slots 4p+2, 4p+1
        }
        *(__half2*)&As[r * AST + 2 * p] = __floats2half2_rn(lo, hi);
    }
    // B load: 64 rows x 64 half2
    for (int idx = tid; idx < 64 * 64; idx += 256) {
        int r = idx >> 6, p = idx & 63;
        *(__half2*)&Bs[r * AST + 2 * p] = W1h[r * 64 + p];
    }
    __syncthreads();

    int mw = wid * 16;
    float c[8][4];
#pragma unroll
    for (int nt = 0; nt < 8; nt++) {
        c[nt][0] = 0.f; c[nt][1] = 0.f; c[nt][2] = 0.f; c[nt][3] = 0.f;
    }
#pragma unroll
    for (int ks = 0; ks < 8; ks++) {
        uint32_t a0, a1, a2, a3;
        ldmx4(a0, a1, a2, a3, sbA + (uint32_t)((mw + rowq) * AST + ks * 16 + colq) * 2);
#pragma unroll
        for (int p = 0; p < 4; p++) {
            uint32_t b0, b1v, b2, b3;
            ldmx4(b0, b1v, b2, b3, sbB + (uint32_t)((16 * p + rowq) * AST + ks * 16 + colq) * 2);
            mma16816(c[2 * p],     a0, a1, a2, a3, b0, b2);
            mma16816(c[2 * p + 1], a0, a1, a2, a3, b1v, b3);
        }
    }

    // fused epilogue
    int mA = m0 + mw + g;
    int mB = mA + 8;
    float invdA = 0.f, hA = 0.f; int clA = 0;
    float invdB = 0.f, hB = 0.f; int clB = 0;
    if (mA < cN1) {
        invdA = 1.0f / fmaxf(P[O_DEG1 + mA], 1.0f);
        hA = fixf(P[O_H1 + mA]);
        clA = cl1[mA] << 6;
    }
    if (mB < cN1) {
        invdB = 1.0f / fmaxf(P[O_DEG1 + mB], 1.0f);
        hB = fixf(P[O_H1 + mB]);
        clB = cl1[mB] << 6;
    }
#pragma unroll
    for (int nt = 0; nt < 8; nt++) {
        int col = nt * 8 + 2 * t;
        float r0 = root1[col], r1 = root1[col + 1];
        float bb0 = b1[col],  bb1 = b1[col + 1];
        if (mA < cN1) {
            atomicMaxFloat(P + O_H2 + clA + col,     eluf(c[nt][0] * invdA + hA * r0 + bb0));
            atomicMaxFloat(P + O_H2 + clA + col + 1, eluf(c[nt][1] * invdA + hA * r1 + bb1));
        }
        if (mB < cN1) {
            atomicMaxFloat(P + O_H2 + clB + col,     eluf(c[nt][2] * invdB + hB * r0 + bb0));
            atomicMaxFloat(P + O_H2 + clB + col + 1, eluf(c[nt][3] * invdB + hB * r1 + bb1));
        }
    }
}

// ---------------- tensor-core batched GEMM: ldmatrix + cp.async double-buffered B ----------------
template<int OT, int KPG>
__global__ void __launch_bounds__(256) gemm_mma(int xoff, const __half2* __restrict__ Wh,
                                                __half2* __restrict__ XWh, int Nn) {
    constexpr int AST   = 72;
    constexpr int ABYTES = 128 * AST * 2;
    constexpr int BROW  = AST * 2;
    constexpr int BBYTES = OT * BROW;
    extern __shared__ char dynsmem[];
    __half* As = (__half*)dynsmem;
    char*   Bs = dynsmem + ABYTES;

    int tid = threadIdx.x, wid = tid >> 5, lane = tid & 31;
    int g = lane >> 2, t = lane & 3;
    int m0 = blockIdx.x * 128;
    int k0 = blockIdx.y * KPG;
    const float* X = pool() + xoff;
    uint32_t sbA = su32(As);
    uint32_t sbB = su32(Bs);

    int lq  = lane >> 3;
    int lr  = lane & 7;
    int rowq = (lq & 1) * 8 + lr;
    int colq = (lq >> 1) * 8;

    for (int idx = tid; idx < 128 * 32; idx += 256) {
        int r = idx >> 5, p = idx & 31;
        float2 v = make_float2(0.f, 0.f);
        if (m0 + r < Nn) {
            v = *(const float2*)(X + (size_t)(m0 + r) * 64 + p * 2);
            v.x = fixf(v.x); v.y = fixf(v.y);
        }
        *(__half2*)&As[r * AST + 2 * p] = __floats2half2_rn(v.x, v.y);
    }

    {
        const char* src = (const char*)Wh + (size_t)k0 * OT * 128;
        for (int idx = tid; idx < OT * 8; idx += 256) {
            int row = idx >> 3, c = idx & 7;
            cpasync16(sbB + row * BROW + c * 16, src + idx * 16);
        }
        CP_COMMIT();
    }
    __syncthreads();

    int mw = wid * 16;
    uint32_t af[4][4];
#pragma unroll
    for (int ks = 0; ks < 4; ks++) {
        uint32_t addr = sbA + (uint32_t)((mw + rowq) * AST + ks * 16 + colq) * 2;
        ldmx4(af[ks][0], af[ks][1], af[ks][2], af[ks][3], addr);
    }

    for (int j = 0; j < KPG; j++) {
        int buf = j & 1;
        if (j + 1 < KPG) {
            const char* src = (const char*)Wh + (size_t)(k0 + j + 1) * OT * 128;
            uint32_t dstb = sbB + ((j + 1) & 1) * BBYTES;
            for (int idx = tid; idx < OT * 8; idx += 256) {
                int row = idx >> 3, c = idx & 7;
                cpasync16(dstb + row * BROW + c * 16, src + idx * 16);
            }
            CP_COMMIT();
            asm volatile("cp.async.wait_group 1;" ::: "memory");
        } else {
            asm volatile("cp.async.wait_group 0;" ::: "memory");
        }
        __syncthreads();

        float c[OT / 8][4];
#pragma unroll
        for (int nt = 0; nt < OT / 8; nt++) {
            c[nt][0] = 0.f; c[nt][1] = 0.f; c[nt][2] = 0.f; c[nt][3] = 0.f;
        }
        uint32_t bufb = sbB + buf * BBYTES;
#pragma unroll
        for (int ks = 0; ks < 4; ks++) {
#pragma unroll
            for (int p = 0; p < OT / 16; p++) {
                uint32_t baddr = bufb + (uint32_t)(16 * p + rowq) * BROW +
                                 (uint32_t)(ks * 16 + colq) * 2;
                uint32_t b0, b1, b2, b3;
                ldmx4(b0, b1, b2, b3, baddr);
                mma16816(c[2 * p],     af[ks][0], af[ks][1], af[ks][2], af[ks][3], b0, b2);
                mma16816(c[2 * p + 1], af[ks][0], af[ks][1], af[ks][2], af[ks][3], b1, b3);
            }
        }
        int k = k0 + j;
        int mA = m0 + mw + g;
        int mB = mA + 8;
        __half2* dA = XWh + ((size_t)k * Nn + mA) * (OT / 2) + t;
        __half2* dB = XWh + ((size_t)k * Nn + mB) * (OT / 2) + t;
#pragma unroll
        for (int nt = 0; nt < OT / 8; nt++) {
            if (mA < Nn) dA[nt * 4] = __floats2half2_rn(c[nt][0], c[nt][1]);
            if (mB < Nn) dB[nt * 4] = __floats2half2_rn(c[nt][2], c[nt][3]);
        }
        __syncthreads();
    }
}

// ---------------- gather layer2: warp per edge, pair-split halves ----------------
__global__ void gather_64(const int* __restrict__ edge, int E, const float* __restrict__ ps,
                          const __half2* __restrict__ XWh, int Nn, int aggoff, int degoff) {
    int gw = (blockIdx.x * blockDim.x + threadIdx.x) >> 5;
    if (gw >= E) return;
    int lane = threadIdx.x & 31;
    int half = lane >> 4, l16 = lane & 15;
    float g0[2], g1[2], g2[2]; int kb;
    load_pseudo(ps, gw, g0, g1, g2, kb);
    int src = edge[gw];
    int dst = edge[E + gw];
    float gh = g0[half];
    float a0 = 0.f, a1 = 0.f, a2 = 0.f, a3 = 0.f;
#pragma unroll
    for (int p = 0; p < 4; p++) {
        float basis = gh * g1[p & 1] * g2[p >> 1];
        int k = kb + 5 * (p & 1) + 25 * (p >> 1) + half;
        uint2 u = *((const uint2*)(XWh + ((size_t)k * Nn + src) * 32) + l16);
        float2 v0 = __half22float2(*(const __half2*)&u.x);
        float2 v1 = __half22float2(*(const __half2*)&u.y);
        a0 = fmaf(basis, v0.x, a0);
        a1 = fmaf(basis, v0.y, a1);
        a2 = fmaf(basis, v1.x, a2);
        a3 = fmaf(basis, v1.y, a3);
    }
    a0 += __shfl_xor_sync(0xffffffffu, a0, 16);
    a1 += __shfl_xor_sync(0xffffffffu, a1, 16);
    a2 += __shfl_xor_sync(0xffffffffu, a2, 16);
    a3 += __shfl_xor_sync(0xffffffffu, a3, 16);
    float* P = pool();
    if (half == 0)
        redAdd4(P + aggoff + dst * 64 + 4 * l16, a0, a1, a2, a3);
    if (lane == 0) atomicAdd(P + degoff + dst, 1.0f);
}

// ---------------- gather layer3: warp per edge, pair-split halves ----------------
__global__ void gather_128(const int* __restrict__ edge, int E, const float* __restrict__ ps,
                           const __half2* __restrict__ XWh, int Nn, int aggoff, int degoff) {
    int gw = (blockIdx.x * blockDim.x + threadIdx.x) >> 5;
    if (gw >= E) return;
    int lane = threadIdx.x & 31;
    int half = lane >> 4, l16 = lane & 15;
    float g0[2], g1[2], g2[2]; int kb;
    load_pseudo(ps, gw, g0, g1, g2, kb);
    int src = edge[gw];
    int dst = edge[E + gw];
    float gh = g0[half];
    float a[8];
#pragma unroll
    for (int i = 0; i < 8; i++) a[i] = 0.f;
#pragma unroll
    for (int p = 0; p < 4; p++) {
        float basis = gh * g1[p & 1] * g2[p >> 1];
        int k = kb + 5 * (p & 1) + 25 * (p >> 1) + half;
        uint4 u = *((const uint4*)(XWh + ((size_t)k * Nn + src) * 64) + l16);
        float2 v0 = __half22float2(*(const __half2*)&u.x);
        float2 v1 = __half22float2(*(const __half2*)&u.y);
        float2 v2 = __half22float2(*(const __half2*)&u.z);
        float2 v3 = __half22float2(*(const __half2*)&u.w);
        a[0] = fmaf(basis, v0.x, a[0]); a[1] = fmaf(basis, v0.y, a[1]);
        a[2] = fmaf(basis, v1.x, a[2]); a[3] = fmaf(basis, v1.y, a[3]);
        a[4] = fmaf(basis, v2.x, a[4]); a[5] = fmaf(basis, v2.y, a[5]);
        a[6] = fmaf(basis, v3.x, a[6]); a[7] = fmaf(basis, v3.y, a[7]);
    }
#pragma unroll
    for (int i = 0; i < 8; i++)
        a[i] += __shfl_xor_sync(0xffffffffu, a[i], 16);
    float* P = pool();
    if (half == 0) {
        redAdd4(P + aggoff + dst * 128 + 8 * l16,     a[0], a[1], a[2], a[3]);
        redAdd4(P + aggoff + dst * 128 + 8 * l16 + 4, a[4], a[5], a[6], a[7]);
    }
    if (lane == 0) atomicAdd(P + degoff + dst, 1.0f);
}

// ---------------- node update + fused seg-max into next H ----------------
__global__ void node_dense(int hoff, int aggoff, int degoff, const int* __restrict__ cl,
                           int outoff, const float* __restrict__ root,
                           const float* __restrict__ bias, int ntot, int shift) {
    int t = blockIdx.x * blockDim.x + threadIdx.x;
    if (t >= ntot) return;
    int n = t >> shift;
    int o = t & ((1 << shift) - 1);
    float* P = pool();
    const float* h = P + hoff + n * 64;
    float acc = bias[o] + P[aggoff + t] / fmaxf(P[degoff + n], 1.0f);
#pragma unroll 16
    for (int i = 0; i < 64; i++)
        acc = fmaf(fixf(h[i]), root[(i << shift) + o], acc);
    atomicMaxFloat(P + outoff + (cl[n] << shift) + o, eluf(acc));
}

// ---------------- final MLP + log_softmax ----------------
__global__ void fc_kernel(const float* __restrict__ w1, const float* __restrict__ b1,
                          const float* __restrict__ w2, const float* __restrict__ b2,
                          float* __restrict__ out) {
    __shared__ float xrow[1024];
    __shared__ float hrow[256];
    __shared__ float logits[10];
    __shared__ float red[2];
    int b = blockIdx.x;
    int t = threadIdx.x;
    float* P = pool();
    for (int i = t; i < 1024; i += 256) xrow[i] = fixf(P[O_H4 + b * 1024 + i]);
    __syncthreads();

    float a0 = b1[t], a1 = 0.f, a2 = 0.f, a3 = 0.f;
#pragma unroll 4
    for (int i = 0; i < 1024; i += 4) {
        a0 = fmaf(xrow[i + 0], w1[(i + 0) * 256 + t], a0);
        a1 = fmaf(xrow[i + 1], w1[(i + 1) * 256 + t], a1);
        a2 = fmaf(xrow[i + 2], w1[(i + 2) * 256 + t], a2);
        a3 = fmaf(xrow[i + 3], w1[(i + 3) * 256 + t], a3);
    }
    hrow[t] = eluf((a0 + a1) + (a2 + a3));
    __syncthreads();

    if (t < 10) {
        float a = b2[t];
#pragma unroll 8
        for (int i = 0; i < 256; i++)
            a = fmaf(hrow[i], w2[i * 10 + t], a);
        logits[t] = a;
    }
    __syncthreads();
    if (t == 0) {
        float m = logits[0];
        for (int j = 1; j < 10; j++) m = fmaxf(m, logits[j]);
        float s = 0.0f;
        for (int j = 0; j < 10; j++) s += expf(logits[j] - m);
        red[0] = m;
        red[1] = logf(s);
    }
    __syncthreads();
    if (t < 10) out[b * 10 + t] = logits[t] - red[0] - red[1];
}

// ---------------- host ----------------
extern "C" void kernel_launch(void* const* d_in, const int* in_sizes, int n_in,
                              void* d_out, int out_size) {
    const float* x0      = (const float*)d_in[0];
    const int*   cl0     = (const int*)  d_in[1];
    const int*   edge1   = (const int*)  d_in[2];
    const float* pseudo1 = (const float*)d_in[3];
    const float* W1      = (const float*)d_in[4];
    const float* root1   = (const float*)d_in[5];
    const float* b1      = (const float*)d_in[6];
    const int*   cl1     = (const int*)  d_in[7];
    const int*   edge2   = (const int*)  d_in[8];
    const float* pseudo2 = (const float*)d_in[9];
    const float* W2      = (const float*)d_in[10];
    const float* root2   = (const float*)d_in[11];
    const float* b2      = (const float*)d_in[12];
    const int*   cl2     = (const int*)  d_in[13];
    const int*   edge3   = (const int*)  d_in[14];
    const float* pseudo3 = (const float*)d_in[15];
    const float* W3      = (const float*)d_in[16];
    const float* root3   = (const float*)d_in[17];
    const float* b3      = (const float*)d_in[18];
    const int*   cl3     = (const int*)  d_in[19];
    const float* fc1w    = (const float*)d_in[20];
    const float* fc1b    = (const float*)d_in[21];
    const float* fc2w    = (const float*)d_in[22];
    const float* fc2b    = (const float*)d_in[23];
    float* out = (float*)d_out;

    const int TB = 256;

    __half2* xw2h; __half2* xw3h; __half2* w1h; __half2* w2h; __half2* w3h;
    cudaGetSymbolAddress((void**)&xw2h, g_xw2h4);
    cudaGetSymbolAddress((void**)&xw3h, g_xw3h4);
    cudaGetSymbolAddress((void**)&w1h, g_w1h4);
    cudaGetSymbolAddress((void**)&w2h, g_w2h4);
    cudaGetSymbolAddress((void**)&w3h, g_w3h4);

    const int SM64  = 18432 + 2 * 64 * 144;   // 36864
    const int SM128 = 18432 + 2 * 128 * 144;  // 55296
    const int SML1  = 128 * 136 * 2 + 64 * 136 * 2;  // 52224
    cudaFuncSetAttribute(gemm_mma<64, 5>,  cudaFuncAttributeMaxDynamicSharedMemorySize, SM64);
    cudaFuncSetAttribute(gemm_mma<128, 5>, cudaFuncAttributeMaxDynamicSharedMemorySize, SM128);
    cudaFuncSetAttribute(l1_gemm_mma, cudaFuncAttributeMaxDynamicSharedMemorySize, SML1);

    // 1: init + W conversion
    init_and_convert<<<1024, TB>>>(W1, W2, W3, w1h, w2h, w3h);
    // 2: seg_max(x0) -> H1
    segmax_x0_kernel<<<CDIV(cN0, TB), TB>>>(x0, cl0);
    // 3: layer-1 scatter (pair-vectorized)
    l1_scatter<<<CDIV(cE1, TB), TB>>>(edge1, pseudo1);
    // 4: layer-1 mma GEMM + node update + seg-max -> H2 (profile slot)
    l1_gemm_mma<<<CDIV(cN1, 128), 256, SML1>>>(w1h, root1, b1, cl1);
    // 5: layer-2 tensor-core GEMM -> XW2 (f16)
    {
        dim3 g(CDIV(cN2, 128), 25);
        gemm_mma<64, 5><<<g, 256, SM64>>>(O_H2, w2h, xw2h, cN2);
    }
    // 6: layer-2 gather
    gather_64<<<CDIV(cE2 * 32, TB), TB>>>(edge2, cE2, pseudo2, xw2h, cN2, O_AGG2, O_DEG2);
    // 7: layer-2 node update + seg-max -> H3
    node_dense<<<CDIV(cN2 * 64, TB), TB>>>(O_H2, O_AGG2, O_DEG2, cl2, O_H3, root2, b2, cN2 * 64, 6);
    // 8: layer-3 tensor-core GEMM -> XW3 (f16)
    {
        dim3 g(CDIV(cN3, 128), 25);
        gemm_mma<128, 5><<<g, 256, SM128>>>(O_H3, w3h, xw3h, cN3);
    }
    // 9: layer-3 gather
    gather_128<<<CDIV(cE3 * 32, TB), TB>>>(edge3, cE3, pseudo3, xw3h, cN3, O_AGG3, O_DEG3);
    // 10: layer-3 node update + seg-max -> H4
    node_dense<<<CDIV(cN3 * 128, TB), TB>>>(O_H3, O_AGG3, O_DEG3, cl3, O_H4, root3, b3, cN3 * 128, 7);
    // 11: MLP head + log_softmax
    fc_kernel<<<cB, 256>>>(fc1w, fc1b, fc2w, fc2b, out);
}

// round 12
// speedup vs baseline: 4.5182x; 1.0390x over previous
#include <cuda_runtime.h>
#include <cuda_fp16.h>
#include <math.h>
#include <stdint.h>

#define CDIV(a,b) (((a)+(b)-1)/(b))

// Problem constants
constexpr int cN0 = 120000;
constexpr int cN1 = 20000;
constexpr int cN2 = 6000;
constexpr int cN3 = 1600;
constexpr int cB  = 64;
constexpr int cE1 = 480000;
constexpr int cE2 = 144000;
constexpr int cE3 = 38400;
constexpr int cK  = 125;

// ---------------- scratch pool (no cudaMalloc allowed) ----------------
constexpr int AL64(int x) { return (x + 63) & ~63; }
constexpr int O_H1   = 0;
constexpr int O_C1   = O_H1   + AL64(cN1);      // C1v2[dst][256]: slot 2k+off (pair-vectorized)
constexpr int O_DEG1 = O_C1   + cN1 * 256;
constexpr int O_H2   = O_DEG1 + AL64(cN1);
constexpr int O_AGG2 = O_H2   + cN2 * 64;
constexpr int O_DEG2 = O_AGG2 + cN2 * 64;
constexpr int O_H3   = O_DEG2 + AL64(cN2);
constexpr int O_AGG3 = O_H3   + cN3 * 64;
constexpr int O_DEG3 = O_AGG3 + cN3 * 128;
constexpr int O_H4   = O_DEG3 + AL64(cN3);
constexpr int POOLN  = O_H4   + 512 * 128;

__device__ float4 g_pool4[(POOLN + 3) / 4];
__device__ __forceinline__ float* pool() { return (float*)g_pool4; }

// XW scratch in f16: XW2h[k][n][64], XW3h[k][n][128]
__device__ uint4 g_xw2h4[(size_t)cK * cN2 * 64 * 2 / 16];   // 96 MB
__device__ uint4 g_xw3h4[(size_t)cK * cN3 * 128 * 2 / 16];  // 51.2 MB
// f16 W tiles, layout [k][o][kk] = B col-major for mma
__device__ uint4 g_w2h4[cK * 64 * 64 * 2 / 16];    // 1 MB
__device__ uint4 g_w3h4[cK * 128 * 64 * 2 / 16];   // 2 MB
// W1 f16: [o(64)][kk(128, padded)] halves
__device__ uint4 g_w1h4[64 * 128 * 2 / 16];        // 16 KB

// ---------------- helpers ----------------
__device__ __forceinline__ void atomicMaxFloat(float* addr, float val) {
    if (val >= 0.0f)
        atomicMax((int*)addr, __float_as_int(val));
    else
        atomicMin((unsigned int*)addr, __float_as_uint(val));
}
__device__ __forceinline__ void redAdd4(float* addr, float a, float b, float c, float d) {
    asm volatile("red.global.add.v4.f32 [%0], {%1,%2,%3,%4};"
                 :: "l"(addr), "f"(a), "f"(b), "f"(c), "f"(d) : "memory");
}
__device__ __forceinline__ void redAdd2(float* addr, float a, float b) {
    asm volatile("red.global.add.v2.f32 [%0], {%1,%2};"
                 :: "l"(addr), "f"(a), "f"(b) : "memory");
}
__device__ __forceinline__ float eluf(float v) { return v > 0.0f ? v : expm1f(v); }
__device__ __forceinline__ float fixf(float v) { return isfinite(v) ? v : 0.0f; }

__device__ __forceinline__ uint32_t su32(const void* p) {
    uint32_t a;
    asm("{ .reg .u64 t; cvta.to.shared.u64 t, %1; cvt.u32.u64 %0, t; }" : "=r"(a) : "l"(p));
    return a;
}
__device__ __forceinline__ void mma16816(float c[4], uint32_t a0, uint32_t a1,
                                         uint32_t a2, uint32_t a3,
                                         uint32_t b0, uint32_t b1) {
    asm volatile("mma.sync.aligned.m16n8k16.row.col.f32.f16.f16.f32 "
                 "{%0,%1,%2,%3}, {%4,%5,%6,%7}, {%8,%9}, {%0,%1,%2,%3};"
                 : "+f"(c[0]), "+f"(c[1]), "+f"(c[2]), "+f"(c[3])
                 : "r"(a0), "r"(a1), "r"(a2), "r"(a3), "r"(b0), "r"(b1));
}
__device__ __forceinline__ void ldmx4(uint32_t& f0, uint32_t& f1, uint32_t& f2, uint32_t& f3,
                                      uint32_t addr) {
    asm volatile("ldmatrix.sync.aligned.m8n8.x4.shared.b16 {%0,%1,%2,%3}, [%4];"
                 : "=r"(f0), "=r"(f1), "=r"(f2), "=r"(f3) : "r"(addr));
}
__device__ __forceinline__ void cpasync16(uint32_t sdst, const void* gsrc) {
    asm volatile("cp.async.cg.shared.global [%0], [%1], 16;" :: "r"(sdst), "l"(gsrc));
}
#define CP_COMMIT() asm volatile("cp.async.commit_group;" ::: "memory")

// ---------------- init + W conversion (fused, independent work) ----------------
__global__ void init_and_convert(const float* __restrict__ W1, const float* __restrict__ W2,
                                 const float* __restrict__ W3, __half2* __restrict__ Wh1,
                                 __half2* __restrict__ Wh2, __half2* __restrict__ Wh3) {
    float* P = pool();
    const float NI = -INFINITY;
    int t = blockIdx.x * blockDim.x + threadIdx.x;
    int stride = gridDim.x * blockDim.x;
    for (int i = t; i < cN1; i += stride) P[O_H1 + i] = NI;
    for (int i = t; i < cN2 * 64; i += stride) P[O_H2 + i] = NI;
    for (int i = t; i < cN3 * 64; i += stride) P[O_H3 + i] = NI;
    for (int i = t; i < 512 * 128; i += stride) P[O_H4 + i] = NI;
    for (int i = t; i < cN1 * 256; i += stride) P[O_C1 + i] = 0.0f;
    for (int i = t; i < cN1; i += stride) P[O_DEG1 + i] = 0.0f;
    for (int i = t; i < cN2 * 64; i += stride) P[O_AGG2 + i] = 0.0f;
    for (int i = t; i < cN2; i += stride) P[O_DEG2 + i] = 0.0f;
    for (int i = t; i < cN3 * 128; i += stride) P[O_AGG3 + i] = 0.0f;
    for (int i = t; i < cN3; i += stride) P[O_DEG3 + i] = 0.0f;
    // W1 -> f16 [o][kk] (kk padded to 128 with zeros)
    for (int idx = t; idx < 64 * 64; idx += stride) {
        int o = idx >> 6, p = idx & 63;
        float w0 = (2 * p     < cK) ? W1[(2 * p) * 64 + o]     : 0.0f;
        float w1 = (2 * p + 1 < cK) ? W1[(2 * p + 1) * 64 + o] : 0.0f;
        Wh1[o * 64 + p] = __floats2half2_rn(w0, w1);
    }
    // W2 -> f16 [k][o][kk]
    for (int idx = t; idx < cK * 64 * 32; idx += stride) {
        int k = idx / (64 * 32);
        int rem = idx % (64 * 32);
        int o = rem >> 5, ip = rem & 31;
        const float* wk = W2 + (size_t)k * 64 * 64;
        Wh2[((size_t)k * 64 + o) * 32 + ip] =
            __floats2half2_rn(wk[(2 * ip) * 64 + o], wk[(2 * ip + 1) * 64 + o]);
    }
    // W3 -> f16 [k][o][kk]
    for (int idx = t; idx < cK * 128 * 32; idx += stride) {
        int k = idx / (128 * 32);
        int rem = idx % (128 * 32);
        int o = rem >> 5, ip = rem & 31;
        const float* wk = W3 + (size_t)k * 64 * 128;
        Wh3[((size_t)k * 128 + o) * 32 + ip] =
            __floats2half2_rn(wk[(2 * ip) * 128 + o], wk[(2 * ip + 1) * 128 + o]);
    }
}

__global__ void segmax_x0_kernel(const float* __restrict__ x, const int* __restrict__ cl) {
    int t = blockIdx.x * blockDim.x + threadIdx.x;
    if (t >= cN0) return;
    atomicMaxFloat(pool() + O_H1 + cl[t], x[t]);
}

// ---------------- spline basis ----------------
__device__ __forceinline__ void load_pseudo(const float* __restrict__ ps, int e,
                                            float g0[2], float g1[2], float g2[2], int& kbase) {
    float p0 = ps[e * 3 + 0] * 4.0f;
    float p1 = ps[e * 3 + 1] * 4.0f;
    float p2 = ps[e * 3 + 2] * 4.0f;
    float lo0 = fmaxf(fminf(floorf(p0), 3.0f), 0.0f);
    float lo1 = fmaxf(fminf(floorf(p1), 3.0f), 0.0f);
    float lo2 = fmaxf(fminf(floorf(p2), 3.0f), 0.0f);
    float f0 = p0 - lo0, f1 = p1 - lo1, f2 = p2 - lo2;
    g0[0] = 1.0f - f0; g0[1] = f0;
    g1[0] = 1.0f - f1; g1[1] = f1;
    g2[0] = 1.0f - f2; g2[1] = f2;
    kbase = (int)lo0 + 5 * (int)lo1 + 25 * (int)lo2;
}

// ---------------- layer 1 scatter: C1v2[dst][2*pairk + {0,1}] += basis * x_src ----------------
__global__ void l1_scatter(const int* __restrict__ edge, const float* __restrict__ ps) {
    int e = blockIdx.x * blockDim.x + threadIdx.x;
    if (e >= cE1) return;
    float g0[2], g1[2], g2[2]; int kb;
    load_pseudo(ps, e, g0, g1, g2, kb);
    int src = edge[e];
    int dst = edge[cE1 + e];
    float* P = pool();
    float xs = fixf(P[O_H1 + src]);
    float x0s = g0[0] * xs, x1s = g0[1] * xs;
    float* c = P + O_C1 + dst * 256;
#pragma unroll
    for (int p = 0; p < 4; p++) {
        float gb = g1[p & 1] * g2[p >> 1];
        int pairk = kb + 5 * (p & 1) + 25 * (p >> 1);
        redAdd2(c + 2 * pairk, gb * x0s, gb * x1s);
    }
    atomicAdd(P + O_DEG1 + dst, 1.0f);
}

// ---------------- layer 1 GEMM via mma.sync (64-row tiles, 128 threads) ----------------
// A[m][k] = C1v2[m][2k] + C1v2[m][2k-1]  (f16, shuffle reconstruction), B = W1h [o][kk].
__global__ void __launch_bounds__(128) l1_gemm_mma(const __half2* __restrict__ W1h,
                                                   const float* __restrict__ root1,
                                                   const float* __restrict__ b1,
                                                   const int* __restrict__ cl1) {
    constexpr int AST = 136;               // halves per A/B row (272 B)
    extern __shared__ char dynsmem[];
    __half* As = (__half*)dynsmem;                   // 64 x 136 halves
    __half* Bs = (__half*)(dynsmem + 64 * AST * 2);  // 64 x 136 halves

    int tid = threadIdx.x, wid = tid >> 5, lane = tid & 31;
    int g = lane >> 2, t = lane & 3;
    int m0 = blockIdx.x * 64;
    float* P = pool();
    uint32_t sbA = su32(As);
    uint32_t sbB = su32(Bs);

    int lq = lane >> 3, lr = lane & 7;
    int rowq = (lq & 1) * 8 + lr;
    int colq = (lq >> 1) * 8;

    // A conversion: one row per warp iteration, lane L covers k = 4L..4L+3
    for (int r = wid; r < 64; r += 4) {
        int m = m0 + r;
        float4 u0 = make_float4(0.f, 0.f, 0.f, 0.f);
        float4 u1 = make_float4(0.f, 0.f, 0.f, 0.f);
        if (m < cN1) {
            const float4* v4 = (const float4*)(P + O_C1 + (size_t)m * 256);
            u0 = v4[2 * lane];
            u1 = v4[2 * lane + 1];
        }
        float prev = __shfl_up_sync(0xffffffffu, u1.w, 1);
        if (lane == 0) prev = 0.0f;
        float a0 = u0.x + prev;   // k=4L : slots 8L, 8L-1
        float a1 = u0.z + u0.y;   // k=4L+1
        float a2 = u1.x + u0.w;   // k=4L+2
        float a3 = u1.z + u1.y;   // k=4L+3
        uint2 w;
        __half2 h0 = __floats2half2_rn(a0, a1);
        __half2 h1 = __floats2half2_rn(a2, a3);
        w.x = *(const uint32_t*)&h0;
        w.y = *(const uint32_t*)&h1;
        *(uint2*)&As[r * AST + 4 * lane] = w;
    }
    // B load: 64 rows x 64 half2, uint4 vectorized
    for (int idx = tid; idx < 64 * 16; idx += 128) {
        int r = idx >> 4, pq = idx & 15;
        *(uint4*)&Bs[r * AST + pq * 8] = *(const uint4*)(W1h + r * 64 + pq * 4);
    }
    __syncthreads();

    int mw = wid * 16;
    float c[8][4];
#pragma unroll
    for (int nt = 0; nt < 8; nt++) {
        c[nt][0] = 0.f; c[nt][1] = 0.f; c[nt][2] = 0.f; c[nt][3] = 0.f;
    }
#pragma unroll
    for (int ks = 0; ks < 8; ks++) {
        uint32_t a0, a1, a2, a3;
        ldmx4(a0, a1, a2, a3, sbA + (uint32_t)((mw + rowq) * AST + ks * 16 + colq) * 2);
#pragma unroll
        for (int p = 0; p < 4; p++) {
            uint32_t b0, b1v, b2, b3;
            ldmx4(b0, b1v, b2, b3, sbB + (uint32_t)((16 * p + rowq) * AST + ks * 16 + colq) * 2);
            mma16816(c[2 * p],     a0, a1, a2, a3, b0, b2);
            mma16816(c[2 * p + 1], a0, a1, a2, a3, b1v, b3);
        }
    }

    // fused epilogue: node update + seg-max scatter into H2
    int mA = m0 + mw + g;
    int mB = mA + 8;
    float invdA = 0.f, hA = 0.f; int clA = 0;
    float invdB = 0.f, hB = 0.f; int clB = 0;
    if (mA < cN1) {
        invdA = 1.0f / fmaxf(P[O_DEG1 + mA], 1.0f);
        hA = fixf(P[O_H1 + mA]);
        clA = cl1[mA] << 6;
    }
    if (mB < cN1) {
        invdB = 1.0f / fmaxf(P[O_DEG1 + mB], 1.0f);
        hB = fixf(P[O_H1 + mB]);
        clB = cl1[mB] << 6;
    }
#pragma unroll
    for (int nt = 0; nt < 8; nt++) {
        int col = nt * 8 + 2 * t;
        float r0 = root1[col], r1 = root1[col + 1];
        float bb0 = b1[col],  bb1 = b1[col + 1];
        if (mA < cN1) {
            atomicMaxFloat(P + O_H2 + clA + col,     eluf(c[nt][0] * invdA + hA * r0 + bb0));
            atomicMaxFloat(P + O_H2 + clA + col + 1, eluf(c[nt][1] * invdA + hA * r1 + bb1));
        }
        if (mB < cN1) {
            atomicMaxFloat(P + O_H2 + clB + col,     eluf(c[nt][2] * invdB + hB * r0 + bb0));
            atomicMaxFloat(P + O_H2 + clB + col + 1, eluf(c[nt][3] * invdB + hB * r1 + bb1));
        }
    }
}

// ---------------- tensor-core batched GEMM: ldmatrix + cp.async double-buffered B ----------------
template<int OT, int KPG>
__global__ void __launch_bounds__(256) gemm_mma(int xoff, const __half2* __restrict__ Wh,
                                                __half2* __restrict__ XWh, int Nn) {
    constexpr int AST   = 72;
    constexpr int ABYTES = 128 * AST * 2;
    constexpr int BROW  = AST * 2;
    constexpr int BBYTES = OT * BROW;
    extern __shared__ char dynsmem[];
    __half* As = (__half*)dynsmem;
    char*   Bs = dynsmem + ABYTES;

    int tid = threadIdx.x, wid = tid >> 5, lane = tid & 31;
    int g = lane >> 2, t = lane & 3;
    int m0 = blockIdx.x * 128;
    int k0 = blockIdx.y * KPG;
    const float* X = pool() + xoff;
    uint32_t sbA = su32(As);
    uint32_t sbB = su32(Bs);

    int lq  = lane >> 3;
    int lr  = lane & 7;
    int rowq = (lq & 1) * 8 + lr;
    int colq = (lq >> 1) * 8;

    for (int idx = tid; idx < 128 * 32; idx += 256) {
        int r = idx >> 5, p = idx & 31;
        float2 v = make_float2(0.f, 0.f);
        if (m0 + r < Nn) {
            v = *(const float2*)(X + (size_t)(m0 + r) * 64 + p * 2);
            v.x = fixf(v.x); v.y = fixf(v.y);
        }
        *(__half2*)&As[r * AST + 2 * p] = __floats2half2_rn(v.x, v.y);
    }

    {
        const char* src = (const char*)Wh + (size_t)k0 * OT * 128;
        for (int idx = tid; idx < OT * 8; idx += 256) {
            int row = idx >> 3, c = idx & 7;
            cpasync16(sbB + row * BROW + c * 16, src + idx * 16);
        }
        CP_COMMIT();
    }
    __syncthreads();

    int mw = wid * 16;
    uint32_t af[4][4];
#pragma unroll
    for (int ks = 0; ks < 4; ks++) {
        uint32_t addr = sbA + (uint32_t)((mw + rowq) * AST + ks * 16 + colq) * 2;
        ldmx4(af[ks][0], af[ks][1], af[ks][2], af[ks][3], addr);
    }

    for (int j = 0; j < KPG; j++) {
        int buf = j & 1;
        if (j + 1 < KPG) {
            const char* src = (const char*)Wh + (size_t)(k0 + j + 1) * OT * 128;
            uint32_t dstb = sbB + ((j + 1) & 1) * BBYTES;
            for (int idx = tid; idx < OT * 8; idx += 256) {
                int row = idx >> 3, c = idx & 7;
                cpasync16(dstb + row * BROW + c * 16, src + idx * 16);
            }
            CP_COMMIT();
            asm volatile("cp.async.wait_group 1;" ::: "memory");
        } else {
            asm volatile("cp.async.wait_group 0;" ::: "memory");
        }
        __syncthreads();

        float c[OT / 8][4];
#pragma unroll
        for (int nt = 0; nt < OT / 8; nt++) {
            c[nt][0] = 0.f; c[nt][1] = 0.f; c[nt][2] = 0.f; c[nt][3] = 0.f;
        }
        uint32_t bufb = sbB + buf * BBYTES;
#pragma unroll
        for (int ks = 0; ks < 4; ks++) {
#pragma unroll
            for (int p = 0; p < OT / 16; p++) {
                uint32_t baddr = bufb + (uint32_t)(16 * p + rowq) * BROW +
                                 (uint32_t)(ks * 16 + colq) * 2;
                uint32_t b0, b1, b2, b3;
                ldmx4(b0, b1, b2, b3, baddr);
                mma16816(c[2 * p],     af[ks][0], af[ks][1], af[ks][2], af[ks][3], b0, b2);
                mma16816(c[2 * p + 1], af[ks][0], af[ks][1], af[ks][2], af[ks][3], b1, b3);
            }
        }
        int k = k0 + j;
        int mA = m0 + mw + g;
        int mB = mA + 8;
        __half2* dA = XWh + ((size_t)k * Nn + mA) * (OT / 2) + t;
        __half2* dB = XWh + ((size_t)k * Nn + mB) * (OT / 2) + t;
#pragma unroll
        for (int nt = 0; nt < OT / 8; nt++) {
            if (mA < Nn) dA[nt * 4] = __floats2half2_rn(c[nt][0], c[nt][1]);
            if (mB < Nn) dB[nt * 4] = __floats2half2_rn(c[nt][2], c[nt][3]);
        }
        __syncthreads();
    }
}

// ---------------- gather layer2: warp per edge, pair-split halves ----------------
__global__ void gather_64(const int* __restrict__ edge, int E, const float* __restrict__ ps,
                          const __half2* __restrict__ XWh, int Nn, int aggoff, int degoff) {
    int gw = (blockIdx.x * blockDim.x + threadIdx.x) >> 5;
    if (gw >= E) return;
    int lane = threadIdx.x & 31;
    int half = lane >> 4, l16 = lane & 15;
    float g0[2], g1[2], g2[2]; int kb;
    load_pseudo(ps, gw, g0, g1, g2, kb);
    int src = edge[gw];
    int dst = edge[E + gw];
    float gh = g0[half];
    float a0 = 0.f, a1 = 0.f, a2 = 0.f, a3 = 0.f;
#pragma unroll
    for (int p = 0; p < 4; p++) {
        float basis = gh * g1[p & 1] * g2[p >> 1];
        int k = kb + 5 * (p & 1) + 25 * (p >> 1) + half;
        uint2 u = *((const uint2*)(XWh + ((size_t)k * Nn + src) * 32) + l16);
        float2 v0 = __half22float2(*(const __half2*)&u.x);
        float2 v1 = __half22float2(*(const __half2*)&u.y);
        a0 = fmaf(basis, v0.x, a0);
        a1 = fmaf(basis, v0.y, a1);
        a2 = fmaf(basis, v1.x, a2);
        a3 = fmaf(basis, v1.y, a3);
    }
    a0 += __shfl_xor_sync(0xffffffffu, a0, 16);
    a1 += __shfl_xor_sync(0xffffffffu, a1, 16);
    a2 += __shfl_xor_sync(0xffffffffu, a2, 16);
    a3 += __shfl_xor_sync(0xffffffffu, a3, 16);
    float* P = pool();
    if (half == 0)
        redAdd4(P + aggoff + dst * 64 + 4 * l16, a0, a1, a2, a3);
    if (lane == 0) atomicAdd(P + degoff + dst, 1.0f);
}

// ---------------- gather layer3: warp per edge, pair-split halves ----------------
__global__ void gather_128(const int* __restrict__ edge, int E, const float* __restrict__ ps,
                           const __half2* __restrict__ XWh, int Nn, int aggoff, int degoff) {
    int gw = (blockIdx.x * blockDim.x + threadIdx.x) >> 5;
    if (gw >= E) return;
    int lane = threadIdx.x & 31;
    int half = lane >> 4, l16 = lane & 15;
    float g0[2], g1[2], g2[2]; int kb;
    load_pseudo(ps, gw, g0, g1, g2, kb);
    int src = edge[gw];
    int dst = edge[E + gw];
    float gh = g0[half];
    float a[8];
#pragma unroll
    for (int i = 0; i < 8; i++) a[i] = 0.f;
#pragma unroll
    for (int p = 0; p < 4; p++) {
        float basis = gh * g1[p & 1] * g2[p >> 1];
        int k = kb + 5 * (p & 1) + 25 * (p >> 1) + half;
        uint4 u = *((const uint4*)(XWh + ((size_t)k * Nn + src) * 64) + l16);
        float2 v0 = __half22float2(*(const __half2*)&u.x);
        float2 v1 = __half22float2(*(const __half2*)&u.y);
        float2 v2 = __half22float2(*(const __half2*)&u.z);
        float2 v3 = __half22float2(*(const __half2*)&u.w);
        a[0] = fmaf(basis, v0.x, a[0]); a[1] = fmaf(basis, v0.y, a[1]);
        a[2] = fmaf(basis, v1.x, a[2]); a[3] = fmaf(basis, v1.y, a[3]);
        a[4] = fmaf(basis, v2.x, a[4]); a[5] = fmaf(basis, v2.y, a[5]);
        a[6] = fmaf(basis, v3.x, a[6]); a[7] = fmaf(basis, v3.y, a[7]);
    }
#pragma unroll
    for (int i = 0; i < 8; i++)
        a[i] += __shfl_xor_sync(0xffffffffu, a[i], 16);
    float* P = pool();
    if (half == 0) {
        redAdd4(P + aggoff + dst * 128 + 8 * l16,     a[0], a[1], a[2], a[3]);
        redAdd4(P + aggoff + dst * 128 + 8 * l16 + 4, a[4], a[5], a[6], a[7]);
    }
    if (lane == 0) atomicAdd(P + degoff + dst, 1.0f);
}

// ---------------- node update + fused seg-max into next H ----------------
__global__ void node_dense(int hoff, int aggoff, int degoff, const int* __restrict__ cl,
                           int outoff, const float* __restrict__ root,
                           const float* __restrict__ bias, int ntot, int shift) {
    int t = blockIdx.x * blockDim.x + threadIdx.x;
    if (t >= ntot) return;
    int n = t >> shift;
    int o = t & ((1 << shift) - 1);
    float* P = pool();
    const float* h = P + hoff + n * 64;
    float acc = bias[o] + P[aggoff + t] / fmaxf(P[degoff + n], 1.0f);
#pragma unroll 16
    for (int i = 0; i < 64; i++)
        acc = fmaf(fixf(h[i]), root[(i << shift) + o], acc);
    atomicMaxFloat(P + outoff + (cl[n] << shift) + o, eluf(acc));
}

// ---------------- final MLP + log_softmax ----------------
__global__ void fc_kernel(const float* __restrict__ w1, const float* __restrict__ b1,
                          const float* __restrict__ w2, const float* __restrict__ b2,
                          float* __restrict__ out) {
    __shared__ float xrow[1024];
    __shared__ float hrow[256];
    __shared__ float logits[10];
    __shared__ float red[2];
    int b = blockIdx.x;
    int t = threadIdx.x;
    float* P = pool();
    for (int i = t; i < 1024; i += 256) xrow[i] = fixf(P[O_H4 + b * 1024 + i]);
    __syncthreads();

    float a0 = b1[t], a1 = 0.f, a2 = 0.f, a3 = 0.f;
#pragma unroll 4
    for (int i = 0; i < 1024; i += 4) {
        a0 = fmaf(xrow[i + 0], w1[(i + 0) * 256 + t], a0);
        a1 = fmaf(xrow[i + 1], w1[(i + 1) * 256 + t], a1);
        a2 = fmaf(xrow[i + 2], w1[(i + 2) * 256 + t], a2);
        a3 = fmaf(xrow[i + 3], w1[(i + 3) * 256 + t], a3);
    }
    hrow[t] = eluf((a0 + a1) + (a2 + a3));
    __syncthreads();

    if (t < 10) {
        float a = b2[t];
#pragma unroll 8
        for (int i = 0; i < 256; i++)
            a = fmaf(hrow[i], w2[i * 10 + t], a);
        logits[t] = a;
    }
    __syncthreads();
    if (t == 0) {
        float m = logits[0];
        for (int j = 1; j < 10; j++) m = fmaxf(m, logits[j]);
        float s = 0.0f;
        for (int j = 0; j < 10; j++) s += expf(logits[j] - m);
        red[0] = m;
        red[1] = logf(s);
    }
    __syncthreads();
    if (t < 10) out[b * 10 + t] = logits[t] - red[0] - red[1];
}

// ---------------- host ----------------
extern "C" void kernel_launch(void* const* d_in, const int* in_sizes, int n_in,
                              void* d_out, int out_size) {
    const float* x0      = (const float*)d_in[0];
    const int*   cl0     = (const int*)  d_in[1];
    const int*   edge1   = (const int*)  d_in[2];
    const float* pseudo1 = (const float*)d_in[3];
    const float* W1      = (const float*)d_in[4];
    const float* root1   = (const float*)d_in[5];
    const float* b1      = (const float*)d_in[6];
    const int*   cl1     = (const int*)  d_in[7];
    const int*   edge2   = (const int*)  d_in[8];
    const float* pseudo2 = (const float*)d_in[9];
    const float* W2      = (const float*)d_in[10];
    const float* root2   = (const float*)d_in[11];
    const float* b2      = (const float*)d_in[12];
    const int*   cl2     = (const int*)  d_in[13];
    const int*   edge3   = (const int*)  d_in[14];
    const float* pseudo3 = (const float*)d_in[15];
    const float* W3      = (const float*)d_in[16];
    const float* root3   = (const float*)d_in[17];
    const float* b3      = (const float*)d_in[18];
    const int*   cl3     = (const int*)  d_in[19];
    const float* fc1w    = (const float*)d_in[20];
    const float* fc1b    = (const float*)d_in[21];
    const float* fc2w    = (const float*)d_in[22];
    const float* fc2b    = (const float*)d_in[23];
    float* out = (float*)d_out;

    const int TB = 256;

    __half2* xw2h; __half2* xw3h; __half2* w1h; __half2* w2h; __half2* w3h;
    cudaGetSymbolAddress((void**)&xw2h, g_xw2h4);
    cudaGetSymbolAddress((void**)&xw3h, g_xw3h4);
    cudaGetSymbolAddress((void**)&w1h, g_w1h4);
    cudaGetSymbolAddress((void**)&w2h, g_w2h4);
    cudaGetSymbolAddress((void**)&w3h, g_w3h4);

    const int SM64  = 18432 + 2 * 64 * 144;   // 36864
    const int SM128 = 18432 + 2 * 128 * 144;  // 55296
    const int SML1  = 64 * 136 * 2 + 64 * 136 * 2;  // 34816
    cudaFuncSetAttribute(gemm_mma<64, 5>,  cudaFuncAttributeMaxDynamicSharedMemorySize, SM64);
    cudaFuncSetAttribute(gemm_mma<128, 5>, cudaFuncAttributeMaxDynamicSharedMemorySize, SM128);
    cudaFuncSetAttribute(l1_gemm_mma, cudaFuncAttributeMaxDynamicSharedMemorySize, SML1);

    // 1: init + W conversion
    init_and_convert<<<1024, TB>>>(W1, W2, W3, w1h, w2h, w3h);
    // 2: seg_max(x0) -> H1
    segmax_x0_kernel<<<CDIV(cN0, TB), TB>>>(x0, cl0);
    // 3: layer-1 scatter (pair-vectorized)
    l1_scatter<<<CDIV(cE1, TB), TB>>>(edge1, pseudo1);
    // 4: layer-1 mma GEMM + node update + seg-max -> H2 (profile slot)
    l1_gemm_mma<<<CDIV(cN1, 64), 128, SML1>>>(w1h, root1, b1, cl1);
    // 5: layer-2 tensor-core GEMM -> XW2 (f16)
    {
        dim3 g(CDIV(cN2, 128), 25);
        gemm_mma<64, 5><<<g, 256, SM64>>>(O_H2, w2h, xw2h, cN2);
    }
    // 6: layer-2 gather
    gather_64<<<CDIV(cE2 * 32, TB), TB>>>(edge2, cE2, pseudo2, xw2h, cN2, O_AGG2, O_DEG2);
    // 7: layer-2 node update + seg-max -> H3
    node_dense<<<CDIV(cN2 * 64, TB), TB>>>(O_H2, O_AGG2, O_DEG2, cl2, O_H3, root2, b2, cN2 * 64, 6);
    // 8: layer-3 tensor-core GEMM -> XW3 (f16)
    {
        dim3 g(CDIV(cN3, 128), 25);
        gemm_mma<128, 5><<<g, 256, SM128>>>(O_H3, w3h, xw3h, cN3);
    }
    // 9: layer-3 gather
    gather_128<<<CDIV(cE3 * 32, TB), TB>>>(edge3, cE3, pseudo3, xw3h, cN3, O_AGG3, O_DEG3);
    // 10: layer-3 node update + seg-max -> H4
    node_dense<<<CDIV(cN3 * 128, TB), TB>>>(O_H3, O_AGG3, O_DEG3, cl3, O_H4, root3, b3, cN3 * 128, 7);
    // 11: MLP head + log_softmax
    fc_kernel<<<cB, 256>>>(fc1w, fc1b, fc2w, fc2b, out);
}

// round 13
// speedup vs baseline: 4.5580x; 1.0088x over previous
#include <cuda_runtime.h>
#include <cuda_fp16.h>
#include <math.h>
#include <stdint.h>

#define CDIV(a,b) (((a)+(b)-1)/(b))

// Problem constants
constexpr int cN0 = 120000;
constexpr int cN1 = 20000;
constexpr int cN2 = 6000;
constexpr int cN3 = 1600;
constexpr int cB  = 64;
constexpr int cE1 = 480000;
constexpr int cE2 = 144000;
constexpr int cE3 = 38400;
constexpr int cK  = 125;

// ---------------- scratch pool (no cudaMalloc allowed) ----------------
constexpr int AL64(int x) { return (x + 63) & ~63; }
constexpr int O_H1   = 0;
constexpr int O_C1   = O_H1   + AL64(cN1);      // C1h[dst][256] halves (slot 2k+off), f16
constexpr int O_DEG1 = O_C1   + cN1 * 128;      // 256 halves = 128 floats of space
constexpr int O_H2   = O_DEG1 + AL64(cN1);
constexpr int O_AGG2 = O_H2   + cN2 * 64;
constexpr int O_DEG2 = O_AGG2 + cN2 * 64;
constexpr int O_H3   = O_DEG2 + AL64(cN2);
constexpr int O_AGG3 = O_H3   + cN3 * 64;
constexpr int O_DEG3 = O_AGG3 + cN3 * 128;
constexpr int O_H4   = O_DEG3 + AL64(cN3);
constexpr int POOLN  = O_H4   + 512 * 128;

__device__ float4 g_pool4[(POOLN + 3) / 4];
__device__ __forceinline__ float* pool() { return (float*)g_pool4; }

// XW scratch in f16: XW2h[k][n][64], XW3h[k][n][128]
__device__ uint4 g_xw2h4[(size_t)cK * cN2 * 64 * 2 / 16];   // 96 MB
__device__ uint4 g_xw3h4[(size_t)cK * cN3 * 128 * 2 / 16];  // 51.2 MB
// f16 W tiles, layout [k][o][kk] = B col-major for mma
__device__ uint4 g_w2h4[cK * 64 * 64 * 2 / 16];    // 1 MB
__device__ uint4 g_w3h4[cK * 128 * 64 * 2 / 16];   // 2 MB
// W1 f16: [o(64)][kk(128, padded)] halves
__device__ uint4 g_w1h4[64 * 128 * 2 / 16];        // 16 KB

// ---------------- helpers ----------------
__device__ __forceinline__ void atomicMaxFloat(float* addr, float val) {
    if (val >= 0.0f)
        atomicMax((int*)addr, __float_as_int(val));
    else
        atomicMin((unsigned int*)addr, __float_as_uint(val));
}
__device__ __forceinline__ void redAdd4(float* addr, float a, float b, float c, float d) {
    asm volatile("red.global.add.v4.f32 [%0], {%1,%2,%3,%4};"
                 :: "l"(addr), "f"(a), "f"(b), "f"(c), "f"(d) : "memory");
}
__device__ __forceinline__ void redAddH2(__half2* addr, __half2 v) {
    uint32_t u = *(const uint32_t*)&v;
    asm volatile("red.global.add.noftz.f16x2 [%0], %1;" :: "l"(addr), "r"(u) : "memory");
}
__device__ __forceinline__ float eluf(float v) { return v > 0.0f ? v : expm1f(v); }
__device__ __forceinline__ float fixf(float v) { return isfinite(v) ? v : 0.0f; }

__device__ __forceinline__ uint32_t su32(const void* p) {
    uint32_t a;
    asm("{ .reg .u64 t; cvta.to.shared.u64 t, %1; cvt.u32.u64 %0, t; }" : "=r"(a) : "l"(p));
    return a;
}
__device__ __forceinline__ void mma16816(float c[4], uint32_t a0, uint32_t a1,
                                         uint32_t a2, uint32_t a3,
                                         uint32_t b0, uint32_t b1) {
    asm volatile("mma.sync.aligned.m16n8k16.row.col.f32.f16.f16.f32 "
                 "{%0,%1,%2,%3}, {%4,%5,%6,%7}, {%8,%9}, {%0,%1,%2,%3};"
                 : "+f"(c[0]), "+f"(c[1]), "+f"(c[2]), "+f"(c[3])
                 : "r"(a0), "r"(a1), "r"(a2), "r"(a3), "r"(b0), "r"(b1));
}
__device__ __forceinline__ void ldmx4(uint32_t& f0, uint32_t& f1, uint32_t& f2, uint32_t& f3,
                                      uint32_t addr) {
    asm volatile("ldmatrix.sync.aligned.m8n8.x4.shared.b16 {%0,%1,%2,%3}, [%4];"
                 : "=r"(f0), "=r"(f1), "=r"(f2), "=r"(f3) : "r"(addr));
}
__device__ __forceinline__ void cpasync16(uint32_t sdst, const void* gsrc) {
    asm volatile("cp.async.cg.shared.global [%0], [%1], 16;" :: "r"(sdst), "l"(gsrc));
}
#define CP_COMMIT() asm volatile("cp.async.commit_group;" ::: "memory")

// ---------------- init + W conversion (fused, independent work) ----------------
__global__ void init_and_convert(const float* __restrict__ W1, const float* __restrict__ W2,
                                 const float* __restrict__ W3, __half2* __restrict__ Wh1,
                                 __half2* __restrict__ Wh2, __half2* __restrict__ Wh3) {
    float* P = pool();
    const float NI = -INFINITY;
    int t = blockIdx.x * blockDim.x + threadIdx.x;
    int stride = gridDim.x * blockDim.x;
    for (int i = t; i < cN1; i += stride) P[O_H1 + i] = NI;
    for (int i = t; i < cN2 * 64; i += stride) P[O_H2 + i] = NI;
    for (int i = t; i < cN3 * 64; i += stride) P[O_H3 + i] = NI;
    for (int i = t; i < 512 * 128; i += stride) P[O_H4 + i] = NI;
    for (int i = t; i < cN1 * 128; i += stride) P[O_C1 + i] = 0.0f;  // f16 zeros == 0x0
    for (int i = t; i < cN1; i += stride) P[O_DEG1 + i] = 0.0f;
    for (int i = t; i < cN2 * 64; i += stride) P[O_AGG2 + i] = 0.0f;
    for (int i = t; i < cN2; i += stride) P[O_DEG2 + i] = 0.0f;
    for (int i = t; i < cN3 * 128; i += stride) P[O_AGG3 + i] = 0.0f;
    for (int i = t; i < cN3; i += stride) P[O_DEG3 + i] = 0.0f;
    // W1 -> f16 [o][kk] (kk padded to 128 with zeros)
    for (int idx = t; idx < 64 * 64; idx += stride) {
        int o = idx >> 6, p = idx & 63;
        float w0 = (2 * p     < cK) ? W1[(2 * p) * 64 + o]     : 0.0f;
        float w1 = (2 * p + 1 < cK) ? W1[(2 * p + 1) * 64 + o] : 0.0f;
        Wh1[o * 64 + p] = __floats2half2_rn(w0, w1);
    }
    // W2 -> f16 [k][o][kk]
    for (int idx = t; idx < cK * 64 * 32; idx += stride) {
        int k = idx / (64 * 32);
        int rem = idx % (64 * 32);
        int o = rem >> 5, ip = rem & 31;
        const float* wk = W2 + (size_t)k * 64 * 64;
        Wh2[((size_t)k * 64 + o) * 32 + ip] =
            __floats2half2_rn(wk[(2 * ip) * 64 + o], wk[(2 * ip + 1) * 64 + o]);
    }
    // W3 -> f16 [k][o][kk]
    for (int idx = t; idx < cK * 128 * 32; idx += stride) {
        int k = idx / (128 * 32);
        int rem = idx % (128 * 32);
        int o = rem >> 5, ip = rem & 31;
        const float* wk = W3 + (size_t)k * 64 * 128;
        Wh3[((size_t)k * 128 + o) * 32 + ip] =
            __floats2half2_rn(wk[(2 * ip) * 128 + o], wk[(2 * ip + 1) * 128 + o]);
    }
}

__global__ void segmax_x0_kernel(const float* __restrict__ x, const int* __restrict__ cl) {
    int t = blockIdx.x * blockDim.x + threadIdx.x;
    if (t >= cN0) return;
    atomicMaxFloat(pool() + O_H1 + cl[t], x[t]);
}

// ---------------- spline basis ----------------
__device__ __forceinline__ void load_pseudo(const float* __restrict__ ps, int e,
                                            float g0[2], float g1[2], float g2[2], int& kbase) {
    float p0 = ps[e * 3 + 0] * 4.0f;
    float p1 = ps[e * 3 + 1] * 4.0f;
    float p2 = ps[e * 3 + 2] * 4.0f;
    float lo0 = fmaxf(fminf(floorf(p0), 3.0f), 0.0f);
    float lo1 = fmaxf(fminf(floorf(p1), 3.0f), 0.0f);
    float lo2 = fmaxf(fminf(floorf(p2), 3.0f), 0.0f);
    float f0 = p0 - lo0, f1 = p1 - lo1, f2 = p2 - lo2;
    g0[0] = 1.0f - f0; g0[1] = f0;
    g1[0] = 1.0f - f1; g1[1] = f1;
    g2[0] = 1.0f - f2; g2[1] = f2;
    kbase = (int)lo0 + 5 * (int)lo1 + 25 * (int)lo2;
}

// ---------------- layer 1 scatter: C1h[dst][2*pairk + {0,1}] += basis * x_src (f16x2) ----------------
__global__ void l1_scatter(const int* __restrict__ edge, const float* __restrict__ ps) {
    int e = blockIdx.x * blockDim.x + threadIdx.x;
    if (e >= cE1) return;
    float g0[2], g1[2], g2[2]; int kb;
    load_pseudo(ps, e, g0, g1, g2, kb);
    int src = edge[e];
    int dst = edge[cE1 + e];
    float* P = pool();
    float xs = fixf(P[O_H1 + src]);
    float x0s = g0[0] * xs, x1s = g0[1] * xs;
    __half2* c = (__half2*)(P + O_C1) + (size_t)dst * 128;
#pragma unroll
    for (int p = 0; p < 4; p++) {
        float gb = g1[p & 1] * g2[p >> 1];
        int pairk = kb + 5 * (p & 1) + 25 * (p >> 1);
        redAddH2(c + pairk, __floats2half2_rn(gb * x0s, gb * x1s));
    }
    atomicAdd(P + O_DEG1 + dst, 1.0f);
}

// ---------------- layer 1 GEMM via mma.sync (64-row tiles, 128 threads) ----------------
// A[m][k] = C1h[m][2k] + C1h[m][2k-1], f16 source; one uint4 per lane per row, unroll-4 MLP.
__global__ void __launch_bounds__(128) l1_gemm_mma(const __half2* __restrict__ W1h,
                                                   const float* __restrict__ root1,
                                                   const float* __restrict__ b1,
                                                   const int* __restrict__ cl1) {
    constexpr int AST = 136;               // halves per A/B row (272 B)
    extern __shared__ char dynsmem[];
    __half* As = (__half*)dynsmem;                   // 64 x 136 halves
    __half* Bs = (__half*)(dynsmem + 64 * AST * 2);  // 64 x 136 halves

    int tid = threadIdx.x, wid = tid >> 5, lane = tid & 31;
    int g = lane >> 2, t = lane & 3;
    int m0 = blockIdx.x * 64;
    float* P = pool();
    uint32_t sbA = su32(As);
    uint32_t sbB = su32(Bs);

    int lq = lane >> 3, lr = lane & 7;
    int rowq = (lq & 1) * 8 + lr;
    int colq = (lq >> 1) * 8;

    // A conversion: one row per warp iteration, lane L holds slots 8L..8L+7 (one uint4)
    const uint4* C1b = (const uint4*)((const __half2*)(P + O_C1));
#pragma unroll 4
    for (int r = wid; r < 64; r += 4) {
        int m = m0 + r;
        uint4 u = make_uint4(0u, 0u, 0u, 0u);
        if (m < cN1) u = C1b[(size_t)m * 32 + lane];
        float2 f0 = __half22float2(*(const __half2*)&u.x);
        float2 f1 = __half22float2(*(const __half2*)&u.y);
        float2 f2 = __half22float2(*(const __half2*)&u.z);
        float2 f3 = __half22float2(*(const __half2*)&u.w);
        float prev = __shfl_up_sync(0xffffffffu, f3.y, 1);
        if (lane == 0) prev = 0.0f;
        float a0 = f0.x + prev;   // k=4L : slots 8L, 8L-1
        float a1 = f1.x + f0.y;   // k=4L+1
        float a2 = f2.x + f1.y;   // k=4L+2
        float a3 = f3.x + f2.y;   // k=4L+3
        uint2 w;
        __half2 h0 = __floats2half2_rn(a0, a1);
        __half2 h1 = __floats2half2_rn(a2, a3);
        w.x = *(const uint32_t*)&h0;
        w.y = *(const uint32_t*)&h1;
        *(uint2*)&As[r * AST + 4 * lane] = w;
    }
    // B load: 64 rows x 64 half2, uint4 vectorized
    for (int idx = tid; idx < 64 * 16; idx += 128) {
        int r = idx >> 4, pq = idx & 15;
        *(uint4*)&Bs[r * AST + pq * 8] = *(const uint4*)(W1h + r * 64 + pq * 4);
    }
    __syncthreads();

    int mw = wid * 16;
    float c[8][4];
#pragma unroll
    for (int nt = 0; nt < 8; nt++) {
        c[nt][0] = 0.f; c[nt][1] = 0.f; c[nt][2] = 0.f; c[nt][3] = 0.f;
    }
#pragma unroll
    for (int ks = 0; ks < 8; ks++) {
        uint32_t a0, a1, a2, a3;
        ldmx4(a0, a1, a2, a3, sbA + (uint32_t)((mw + rowq) * AST + ks * 16 + colq) * 2);
#pragma unroll
        for (int p = 0; p < 4; p++) {
            uint32_t b0, b1v, b2, b3;
            ldmx4(b0, b1v, b2, b3, sbB + (uint32_t)((16 * p + rowq) * AST + ks * 16 + colq) * 2);
            mma16816(c[2 * p],     a0, a1, a2, a3, b0, b2);
            mma16816(c[2 * p + 1], a0, a1, a2, a3, b1v, b3);
        }
    }

    // fused epilogue: node update + seg-max scatter into H2
    int mA = m0 + mw + g;
    int mB = mA + 8;
    float invdA = 0.f, hA = 0.f; int clA = 0;
    float invdB = 0.f, hB = 0.f; int clB = 0;
    if (mA < cN1) {
        invdA = 1.0f / fmaxf(P[O_DEG1 + mA], 1.0f);
        hA = fixf(P[O_H1 + mA]);
        clA = cl1[mA] << 6;
    }
    if (mB < cN1) {
        invdB = 1.0f / fmaxf(P[O_DEG1 + mB], 1.0f);
        hB = fixf(P[O_H1 + mB]);
        clB = cl1[mB] << 6;
    }
#pragma unroll
    for (int nt = 0; nt < 8; nt++) {
        int col = nt * 8 + 2 * t;
        float r0 = root1[col], r1 = root1[col + 1];
        float bb0 = b1[col],  bb1 = b1[col + 1];
        if (mA < cN1) {
            atomicMaxFloat(P + O_H2 + clA + col,     eluf(c[nt][0] * invdA + hA * r0 + bb0));
            atomicMaxFloat(P + O_H2 + clA + col + 1, eluf(c[nt][1] * invdA + hA * r1 + bb1));
        }
        if (mB < cN1) {
            atomicMaxFloat(P + O_H2 + clB + col,     eluf(c[nt][2] * invdB + hB * r0 + bb0));
            atomicMaxFloat(P + O_H2 + clB + col + 1, eluf(c[nt][3] * invdB + hB * r1 + bb1));
        }
    }
}

// ---------------- tensor-core batched GEMM: ldmatrix + cp.async double-buffered B ----------------
template<int OT, int KPG>
__global__ void __launch_bounds__(256) gemm_mma(int xoff, const __half2* __restrict__ Wh,
                                                __half2* __restrict__ XWh, int Nn) {
    constexpr int AST   = 72;
    constexpr int ABYTES = 128 * AST * 2;
    constexpr int BROW  = AST * 2;
    constexpr int BBYTES = OT * BROW;
    extern __shared__ char dynsmem[];
    __half* As = (__half*)dynsmem;
    char*   Bs = dynsmem + ABYTES;

    int tid = threadIdx.x, wid = tid >> 5, lane = tid & 31;
    int g = lane >> 2, t = lane & 3;
    int m0 = blockIdx.x * 128;
    int k0 = blockIdx.y * KPG;
    const float* X = pool() + xoff;
    uint32_t sbA = su32(As);
    uint32_t sbB = su32(Bs);

    int lq  = lane >> 3;
    int lr  = lane & 7;
    int rowq = (lq & 1) * 8 + lr;
    int colq = (lq >> 1) * 8;

    for (int idx = tid; idx < 128 * 32; idx += 256) {
        int r = idx >> 5, p = idx & 31;
        float2 v = make_float2(0.f, 0.f);
        if (m0 + r < Nn) {
            v = *(const float2*)(X + (size_t)(m0 + r) * 64 + p * 2);
            v.x = fixf(v.x); v.y = fixf(v.y);
        }
        *(__half2*)&As[r * AST + 2 * p] = __floats2half2_rn(v.x, v.y);
    }

    {
        const char* src = (const char*)Wh + (size_t)k0 * OT * 128;
        for (int idx = tid; idx < OT * 8; idx += 256) {
            int row = idx >> 3, c = idx & 7;
            cpasync16(sbB + row * BROW + c * 16, src + idx * 16);
        }
        CP_COMMIT();
    }
    __syncthreads();

    int mw = wid * 16;
    uint32_t af[4][4];
#pragma unroll
    for (int ks = 0; ks < 4; ks++) {
        uint32_t addr = sbA + (uint32_t)((mw + rowq) * AST + ks * 16 + colq) * 2;
        ldmx4(af[ks][0], af[ks][1], af[ks][2], af[ks][3], addr);
    }

    for (int j = 0; j < KPG; j++) {
        int buf = j & 1;
        if (j + 1 < KPG) {
            const char* src = (const char*)Wh + (size_t)(k0 + j + 1) * OT * 128;
            uint32_t dstb = sbB + ((j + 1) & 1) * BBYTES;
            for (int idx = tid; idx < OT * 8; idx += 256) {
                int row = idx >> 3, c = idx & 7;
                cpasync16(dstb + row * BROW + c * 16, src + idx * 16);
            }
            CP_COMMIT();
            asm volatile("cp.async.wait_group 1;" ::: "memory");
        } else {
            asm volatile("cp.async.wait_group 0;" ::: "memory");
        }
        __syncthreads();

        float c[OT / 8][4];
#pragma unroll
        for (int nt = 0; nt < OT / 8; nt++) {
            c[nt][0] = 0.f; c[nt][1] = 0.f; c[nt][2] = 0.f; c[nt][3] = 0.f;
        }
        uint32_t bufb = sbB + buf * BBYTES;
#pragma unroll
        for (int ks = 0; ks < 4; ks++) {
#pragma unroll
            for (int p = 0; p < OT / 16; p++) {
                uint32_t baddr = bufb + (uint32_t)(16 * p + rowq) * BROW +
                                 (uint32_t)(ks * 16 + colq) * 2;
                uint32_t b0, b1, b2, b3;
                ldmx4(b0, b1, b2, b3, baddr);
                mma16816(c[2 * p],     af[ks][0], af[ks][1], af[ks][2], af[ks][3], b0, b2);
                mma16816(c[2 * p + 1], af[ks][0], af[ks][1], af[ks][2], af[ks][3], b1, b3);
            }
        }
        int k = k0 + j;
        int mA = m0 + mw + g;
        int mB = mA + 8;
        __half2* dA = XWh + ((size_t)k * Nn + mA) * (OT / 2) + t;
        __half2* dB = XWh + ((size_t)k * Nn + mB) * (OT / 2) + t;
#pragma unroll
        for (int nt = 0; nt < OT / 8; nt++) {
            if (mA < Nn) dA[nt * 4] = __floats2half2_rn(c[nt][0], c[nt][1]);
            if (mB < Nn) dB[nt * 4] = __floats2half2_rn(c[nt][2], c[nt][3]);
        }
        __syncthreads();
    }
}

// ---------------- gather layer2: warp per edge, pair-split halves ----------------
__global__ void gather_64(const int* __restrict__ edge, int E, const float* __restrict__ ps,
                          const __half2* __restrict__ XWh, int Nn, int aggoff, int degoff) {
    int gw = (blockIdx.x * blockDim.x + threadIdx.x) >> 5;
    if (gw >= E) return;
    int lane = threadIdx.x & 31;
    int half = lane >> 4, l16 = lane & 15;
    float g0[2], g1[2], g2[2]; int kb;
    load_pseudo(ps, gw, g0, g1, g2, kb);
    int src = edge[gw];
    int dst = edge[E + gw];
    float gh = g0[half];
    float a0 = 0.f, a1 = 0.f, a2 = 0.f, a3 = 0.f;
#pragma unroll
    for (int p = 0; p < 4; p++) {
        float basis = gh * g1[p & 1] * g2[p >> 1];
        int k = kb + 5 * (p & 1) + 25 * (p >> 1) + half;
        uint2 u = *((const uint2*)(XWh + ((size_t)k * Nn + src) * 32) + l16);
        float2 v0 = __half22float2(*(const __half2*)&u.x);
        float2 v1 = __half22float2(*(const __half2*)&u.y);
        a0 = fmaf(basis, v0.x, a0);
        a1 = fmaf(basis, v0.y, a1);
        a2 = fmaf(basis, v1.x, a2);
        a3 = fmaf(basis, v1.y, a3);
    }
    a0 += __shfl_xor_sync(0xffffffffu, a0, 16);
    a1 += __shfl_xor_sync(0xffffffffu, a1, 16);
    a2 += __shfl_xor_sync(0xffffffffu, a2, 16);
    a3 += __shfl_xor_sync(0xffffffffu, a3, 16);
    float* P = pool();
    if (half == 0)
        redAdd4(P + aggoff + dst * 64 + 4 * l16, a0, a1, a2, a3);
    if (lane == 0) atomicAdd(P + degoff + dst, 1.0f);
}

// ---------------- gather layer3: warp per edge, pair-split halves ----------------
__global__ void gather_128(const int* __restrict__ edge, int E, const float* __restrict__ ps,
                           const __half2* __restrict__ XWh, int Nn, int aggoff, int degoff) {
    int gw = (blockIdx.x * blockDim.x + threadIdx.x) >> 5;
    if (gw >= E) return;
    int lane = threadIdx.x & 31;
    int half = lane >> 4, l16 = lane & 15;
    float g0[2], g1[2], g2[2]; int kb;
    load_pseudo(ps, gw, g0, g1, g2, kb);
    int src = edge[gw];
    int dst = edge[E + gw];
    float gh = g0[half];
    float a[8];
#pragma unroll
    for (int i = 0; i < 8; i++) a[i] = 0.f;
#pragma unroll
    for (int p = 0; p < 4; p++) {
        float basis = gh * g1[p & 1] * g2[p >> 1];
        int k = kb + 5 * (p & 1) + 25 * (p >> 1) + half;
        uint4 u = *((const uint4*)(XWh + ((size_t)k * Nn + src) * 64) + l16);
        float2 v0 = __half22float2(*(const __half2*)&u.x);
        float2 v1 = __half22float2(*(const __half2*)&u.y);
        float2 v2 = __half22float2(*(const __half2*)&u.z);
        float2 v3 = __half22float2(*(const __half2*)&u.w);
        a[0] = fmaf(basis, v0.x, a[0]); a[1] = fmaf(basis, v0.y, a[1]);
        a[2] = fmaf(basis, v1.x, a[2]); a[3] = fmaf(basis, v1.y, a[3]);
        a[4] = fmaf(basis, v2.x, a[4]); a[5] = fmaf(basis, v2.y, a[5]);
        a[6] = fmaf(basis, v3.x, a[6]); a[7] = fmaf(basis, v3.y, a[7]);
    }
#pragma unroll
    for (int i = 0; i < 8; i++)
        a[i] += __shfl_xor_sync(0xffffffffu, a[i], 16);
    float* P = pool();
    if (half == 0) {
        redAdd4(P + aggoff + dst * 128 + 8 * l16,     a[0], a[1], a[2], a[3]);
        redAdd4(P + aggoff + dst * 128 + 8 * l16 + 4, a[4], a[5], a[6], a[7]);
    }
    if (lane == 0) atomicAdd(P + degoff + dst, 1.0f);
}

// ---------------- node update + fused seg-max into next H ----------------
__global__ void node_dense(int hoff, int aggoff, int degoff, const int* __restrict__ cl,
                           int outoff, const float* __restrict__ root,
                           const float* __restrict__ bias, int ntot, int shift) {
    int t = blockIdx.x * blockDim.x + threadIdx.x;
    if (t >= ntot) return;
    int n = t >> shift;
    int o = t & ((1 << shift) - 1);
    float* P = pool();
    const float* h = P + hoff + n * 64;
    float acc = bias[o] + P[aggoff + t] / fmaxf(P[degoff + n], 1.0f);
#pragma unroll 16
    for (int i = 0; i < 64; i++)
        acc = fmaf(fixf(h[i]), root[(i << shift) + o], acc);
    atomicMaxFloat(P + outoff + (cl[n] << shift) + o, eluf(acc));
}

// ---------------- final MLP + log_softmax ----------------
__global__ void fc_kernel(const float* __restrict__ w1, const float* __restrict__ b1,
                          const float* __restrict__ w2, const float* __restrict__ b2,
                          float* __restrict__ out) {
    __shared__ float xrow[1024];
    __shared__ float hrow[256];
    __shared__ float logits[10];
    __shared__ float red[2];
    int b = blockIdx.x;
    int t = threadIdx.x;
    float* P = pool();
    for (int i = t; i < 1024; i += 256) xrow[i] = fixf(P[O_H4 + b * 1024 + i]);
    __syncthreads();

    float a0 = b1[t], a1 = 0.f, a2 = 0.f, a3 = 0.f;
#pragma unroll 4
    for (int i = 0; i < 1024; i += 4) {
        a0 = fmaf(xrow[i + 0], w1[(i + 0) * 256 + t], a0);
        a1 = fmaf(xrow[i + 1], w1[(i + 1) * 256 + t], a1);
        a2 = fmaf(xrow[i + 2], w1[(i + 2) * 256 + t], a2);
        a3 = fmaf(xrow[i + 3], w1[(i + 3) * 256 + t], a3);
    }
    hrow[t] = eluf((a0 + a1) + (a2 + a3));
    __syncthreads();

    if (t < 10) {
        float a = b2[t];
#pragma unroll 8
        for (int i = 0; i < 256; i++)
            a = fmaf(hrow[i], w2[i * 10 + t], a);
        logits[t] = a;
    }
    __syncthreads();
    if (t == 0) {
        float m = logits[0];
        for (int j = 1; j < 10; j++) m = fmaxf(m, logits[j]);
        float s = 0.0f;
        for (int j = 0; j < 10; j++) s += expf(logits[j] - m);
        red[0] = m;
        red[1] = logf(s);
    }
    __syncthreads();
    if (t < 10) out[b * 10 + t] = logits[t] - red[0] - red[1];
}

// ---------------- host ----------------
extern "C" void kernel_launch(void* const* d_in, const int* in_sizes, int n_in,
                              void* d_out, int out_size) {
    const float* x0      = (const float*)d_in[0];
    const int*   cl0     = (const int*)  d_in[1];
    const int*   edge1   = (const int*)  d_in[2];
    const float* pseudo1 = (const float*)d_in[3];
    const float* W1      = (const float*)d_in[4];
    const float* root1   = (const float*)d_in[5];
    const float* b1      = (const float*)d_in[6];
    const int*   cl1     = (const int*)  d_in[7];
    const int*   edge2   = (const int*)  d_in[8];
    const float* pseudo2 = (const float*)d_in[9];
    const float* W2      = (const float*)d_in[10];
    const float* root2   = (const float*)d_in[11];
    const float* b2      = (const float*)d_in[12];
    const int*   cl2     = (const int*)  d_in[13];
    const int*   edge3   = (const int*)  d_in[14];
    const float* pseudo3 = (const float*)d_in[15];
    const float* W3      = (const float*)d_in[16];
    const float* root3   = (const float*)d_in[17];
    const float* b3      = (const float*)d_in[18];
    const int*   cl3     = (const int*)  d_in[19];
    const float* fc1w    = (const float*)d_in[20];
    const float* fc1b    = (const float*)d_in[21];
    const float* fc2w    = (const float*)d_in[22];
    const float* fc2b    = (const float*)d_in[23];
    float* out = (float*)d_out;

    const int TB = 256;

    __half2* xw2h; __half2* xw3h; __half2* w1h; __half2* w2h; __half2* w3h;
    cudaGetSymbolAddress((void**)&xw2h, g_xw2h4);
    cudaGetSymbolAddress((void**)&xw3h, g_xw3h4);
    cudaGetSymbolAddress((void**)&w1h, g_w1h4);
    cudaGetSymbolAddress((void**)&w2h, g_w2h4);
    cudaGetSymbolAddress((void**)&w3h, g_w3h4);

    const int SM64  = 18432 + 2 * 64 * 144;   // 36864
    const int SM128 = 18432 + 2 * 128 * 144;  // 55296
    const int SML1  = 64 * 136 * 2 + 64 * 136 * 2;  // 34816
    cudaFuncSetAttribute(gemm_mma<64, 5>,  cudaFuncAttributeMaxDynamicSharedMemorySize, SM64);
    cudaFuncSetAttribute(gemm_mma<128, 5>, cudaFuncAttributeMaxDynamicSharedMemorySize, SM128);
    cudaFuncSetAttribute(l1_gemm_mma, cudaFuncAttributeMaxDynamicSharedMemorySize, SML1);

    // 1: init + W conversion
    init_and_convert<<<1024, TB>>>(W1, W2, W3, w1h, w2h, w3h);
    // 2: seg_max(x0) -> H1
    segmax_x0_kernel<<<CDIV(cN0, TB), TB>>>(x0, cl0);
    // 3: layer-1 scatter (f16x2 atomics)
    l1_scatter<<<CDIV(cE1, TB), TB>>>(edge1, pseudo1);
    // 4: layer-1 mma GEMM + node update + seg-max -> H2 (profile slot)
    l1_gemm_mma<<<CDIV(cN1, 64), 128, SML1>>>(w1h, root1, b1, cl1);
    // 5: layer-2 tensor-core GEMM -> XW2 (f16)
    {
        dim3 g(CDIV(cN2, 128), 25);
        gemm_mma<64, 5><<<g, 256, SM64>>>(O_H2, w2h, xw2h, cN2);
    }
    // 6: layer-2 gather
    gather_64<<<CDIV(cE2 * 32, TB), TB>>>(edge2, cE2, pseudo2, xw2h, cN2, O_AGG2, O_DEG2);
    // 7: layer-2 node update + seg-max -> H3
    node_dense<<<CDIV(cN2 * 64, TB), TB>>>(O_H2, O_AGG2, O_DEG2, cl2, O_H3, root2, b2, cN2 * 64, 6);
    // 8: layer-3 tensor-core GEMM -> XW3 (f16)
    {
        dim3 g(CDIV(cN3, 128), 25);
        gemm_mma<128, 5><<<g, 256, SM128>>>(O_H3, w3h, xw3h, cN3);
    }
    // 9: layer-3 gather
    gather_128<<<CDIV(cE3 * 32, TB), TB>>>(edge3, cE3, pseudo3, xw3h, cN3, O_AGG3, O_DEG3);
    // 10: layer-3 node update + seg-max -> H4
    node_dense<<<CDIV(cN3 * 128, TB), TB>>>(O_H3, O_AGG3, O_DEG3, cl3, O_H4, root3, b3, cN3 * 128, 7);
    // 11: MLP head + log_softmax
    fc_kernel<<<cB, 256>>>(fc1w, fc1b, fc2w, fc2b, out);
}

// round 14
// speedup vs baseline: 4.6659x; 1.0237x over previous
#include <cuda_runtime.h>
#include <cuda_fp16.h>
#include <math.h>
#include <stdint.h>

#define CDIV(a,b) (((a)+(b)-1)/(b))

// Problem constants
constexpr int cN0 = 120000;
constexpr int cN1 = 20000;
constexpr int cN2 = 6000;
constexpr int cN3 = 1600;
constexpr int cB  = 64;
constexpr int cE1 = 480000;
constexpr int cE2 = 144000;
constexpr int cE3 = 38400;
constexpr int cK  = 125;

// ---------------- scratch pool (no cudaMalloc allowed) ----------------
constexpr int AL64(int x) { return (x + 63) & ~63; }
constexpr int O_H1   = 0;
constexpr int O_C1   = O_H1   + AL64(cN1);      // C1h[dst][256] halves (slot 2k+off), f16
constexpr int O_DEG1 = O_C1   + cN1 * 128;      // 256 halves = 128 floats of space
constexpr int O_H2   = O_DEG1 + AL64(cN1);
constexpr int O_AGG2 = O_H2   + cN2 * 64;
constexpr int O_DEG2 = O_AGG2 + cN2 * 64;
constexpr int O_H3   = O_DEG2 + AL64(cN2);
constexpr int O_AGG3 = O_H3   + cN3 * 64;
constexpr int O_DEG3 = O_AGG3 + cN3 * 128;
constexpr int O_H4   = O_DEG3 + AL64(cN3);
constexpr int POOLN  = O_H4   + 512 * 128;

__device__ float4 g_pool4[(POOLN + 3) / 4];
__device__ __forceinline__ float* pool() { return (float*)g_pool4; }

// XW scratch in f16: XW2h[k][n][64], XW3h[k][n][128]
__device__ uint4 g_xw2h4[(size_t)cK * cN2 * 64 * 2 / 16];   // 96 MB
__device__ uint4 g_xw3h4[(size_t)cK * cN3 * 128 * 2 / 16];  // 51.2 MB
// f16 W tiles, layout [k][o][kk] = B col-major for mma
__device__ uint4 g_w2h4[cK * 64 * 64 * 2 / 16];    // 1 MB
__device__ uint4 g_w3h4[cK * 128 * 64 * 2 / 16];   // 2 MB
// W1 f16: [o(64)][kk(128, padded)] halves
__device__ uint4 g_w1h4[64 * 128 * 2 / 16];        // 16 KB

// ---------------- helpers ----------------
__device__ __forceinline__ void atomicMaxFloat(float* addr, float val) {
    if (val >= 0.0f)
        atomicMax((int*)addr, __float_as_int(val));
    else
        atomicMin((unsigned int*)addr, __float_as_uint(val));
}
__device__ __forceinline__ void redAdd4(float* addr, float a, float b, float c, float d) {
    asm volatile("red.global.add.v4.f32 [%0], {%1,%2,%3,%4};"
                 :: "l"(addr), "f"(a), "f"(b), "f"(c), "f"(d) : "memory");
}
__device__ __forceinline__ void redAddH2(__half2* addr, __half2 v) {
    uint32_t u = *(const uint32_t*)&v;
    asm volatile("red.global.add.noftz.f16x2 [%0], %1;" :: "l"(addr), "r"(u) : "memory");
}
__device__ __forceinline__ float eluf(float v) { return v > 0.0f ? v : expm1f(v); }
__device__ __forceinline__ float fixf(float v) { return isfinite(v) ? v : 0.0f; }

__device__ __forceinline__ uint32_t su32(const void* p) {
    uint32_t a;
    asm("{ .reg .u64 t; cvta.to.shared.u64 t, %1; cvt.u32.u64 %0, t; }" : "=r"(a) : "l"(p));
    return a;
}
__device__ __forceinline__ void mma16816(float c[4], uint32_t a0, uint32_t a1,
                                         uint32_t a2, uint32_t a3,
                                         uint32_t b0, uint32_t b1) {
    asm volatile("mma.sync.aligned.m16n8k16.row.col.f32.f16.f16.f32 "
                 "{%0,%1,%2,%3}, {%4,%5,%6,%7}, {%8,%9}, {%0,%1,%2,%3};"
                 : "+f"(c[0]), "+f"(c[1]), "+f"(c[2]), "+f"(c[3])
                 : "r"(a0), "r"(a1), "r"(a2), "r"(a3), "r"(b0), "r"(b1));
}
__device__ __forceinline__ void ldmx4(uint32_t& f0, uint32_t& f1, uint32_t& f2, uint32_t& f3,
                                      uint32_t addr) {
    asm volatile("ldmatrix.sync.aligned.m8n8.x4.shared.b16 {%0,%1,%2,%3}, [%4];"
                 : "=r"(f0), "=r"(f1), "=r"(f2), "=r"(f3) : "r"(addr));
}
__device__ __forceinline__ void cpasync16(uint32_t sdst, const void* gsrc) {
    asm volatile("cp.async.cg.shared.global [%0], [%1], 16;" :: "r"(sdst), "l"(gsrc));
}
#define CP_COMMIT() asm volatile("cp.async.commit_group;" ::: "memory")

// ---------------- init + W conversion (fused, independent work) ----------------
__global__ void init_and_convert(const float* __restrict__ W1, const float* __restrict__ W2,
                                 const float* __restrict__ W3, __half2* __restrict__ Wh1,
                                 __half2* __restrict__ Wh2, __half2* __restrict__ Wh3) {
    float* P = pool();
    const float NI = -INFINITY;
    int t = blockIdx.x * blockDim.x + threadIdx.x;
    int stride = gridDim.x * blockDim.x;
    for (int i = t; i < cN1; i += stride) P[O_H1 + i] = NI;
    for (int i = t; i < cN2 * 64; i += stride) P[O_H2 + i] = NI;
    for (int i = t; i < cN3 * 64; i += stride) P[O_H3 + i] = NI;
    for (int i = t; i < 512 * 128; i += stride) P[O_H4 + i] = NI;
    for (int i = t; i < cN1 * 128; i += stride) P[O_C1 + i] = 0.0f;  // f16 zeros == 0x0
    for (int i = t; i < cN1; i += stride) P[O_DEG1 + i] = 0.0f;
    for (int i = t; i < cN2 * 64; i += stride) P[O_AGG2 + i] = 0.0f;
    for (int i = t; i < cN2; i += stride) P[O_DEG2 + i] = 0.0f;
    for (int i = t; i < cN3 * 128; i += stride) P[O_AGG3 + i] = 0.0f;
    for (int i = t; i < cN3; i += stride) P[O_DEG3 + i] = 0.0f;
    // W1 -> f16 [o][kk] (kk padded to 128 with zeros)
    for (int idx = t; idx < 64 * 64; idx += stride) {
        int o = idx >> 6, p = idx & 63;
        float w0 = (2 * p     < cK) ? W1[(2 * p) * 64 + o]     : 0.0f;
        float w1 = (2 * p + 1 < cK) ? W1[(2 * p + 1) * 64 + o] : 0.0f;
        Wh1[o * 64 + p] = __floats2half2_rn(w0, w1);
    }
    // W2 -> f16 [k][o][kk]
    for (int idx = t; idx < cK * 64 * 32; idx += stride) {
        int k = idx / (64 * 32);
        int rem = idx % (64 * 32);
        int o = rem >> 5, ip = rem & 31;
        const float* wk = W2 + (size_t)k * 64 * 64;
        Wh2[((size_t)k * 64 + o) * 32 + ip] =
            __floats2half2_rn(wk[(2 * ip) * 64 + o], wk[(2 * ip + 1) * 64 + o]);
    }
    // W3 -> f16 [k][o][kk]
    for (int idx = t; idx < cK * 128 * 32; idx += stride) {
        int k = idx / (128 * 32);
        int rem = idx % (128 * 32);
        int o = rem >> 5, ip = rem & 31;
        const float* wk = W3 + (size_t)k * 64 * 128;
        Wh3[((size_t)k * 128 + o) * 32 + ip] =
            __floats2half2_rn(wk[(2 * ip) * 128 + o], wk[(2 * ip + 1) * 128 + o]);
    }
}

__global__ void segmax_x0_kernel(const float* __restrict__ x, const int* __restrict__ cl) {
    int t = blockIdx.x * blockDim.x + threadIdx.x;
    if (t >= cN0) return;
    atomicMaxFloat(pool() + O_H1 + cl[t], x[t]);
}

// ---------------- spline basis ----------------
__device__ __forceinline__ void load_pseudo(const float* __restrict__ ps, int e,
                                            float g0[2], float g1[2], float g2[2], int& kbase) {
    float p0 = ps[e * 3 + 0] * 4.0f;
    float p1 = ps[e * 3 + 1] * 4.0f;
    float p2 = ps[e * 3 + 2] * 4.0f;
    float lo0 = fmaxf(fminf(floorf(p0), 3.0f), 0.0f);
    float lo1 = fmaxf(fminf(floorf(p1), 3.0f), 0.0f);
    float lo2 = fmaxf(fminf(floorf(p2), 3.0f), 0.0f);
    float f0 = p0 - lo0, f1 = p1 - lo1, f2 = p2 - lo2;
    g0[0] = 1.0f - f0; g0[1] = f0;
    g1[0] = 1.0f - f1; g1[1] = f1;
    g2[0] = 1.0f - f2; g2[1] = f2;
    kbase = (int)lo0 + 5 * (int)lo1 + 25 * (int)lo2;
}

// ---------------- layer 1 scatter: C1h[dst][2*pairk + {0,1}] += basis * x_src (f16x2) ----------------
__global__ void l1_scatter(const int* __restrict__ edge, const float* __restrict__ ps) {
    int e = blockIdx.x * blockDim.x + threadIdx.x;
    if (e >= cE1) return;
    float g0[2], g1[2], g2[2]; int kb;
    load_pseudo(ps, e, g0, g1, g2, kb);
    int src = edge[e];
    int dst = edge[cE1 + e];
    float* P = pool();
    float xs = fixf(P[O_H1 + src]);
    float x0s = g0[0] * xs, x1s = g0[1] * xs;
    __half2* c = (__half2*)(P + O_C1) + (size_t)dst * 128;
#pragma unroll
    for (int p = 0; p < 4; p++) {
        float gb = g1[p & 1] * g2[p >> 1];
        int pairk = kb + 5 * (p & 1) + 25 * (p >> 1);
        redAddH2(c + pairk, __floats2half2_rn(gb * x0s, gb * x1s));
    }
    atomicAdd(P + O_DEG1 + dst, 1.0f);
}

// ---------------- layer 1 GEMM via mma.sync (64-row tiles, 256 threads, N-split warps) ----------------
// warps 0-3: rows (w&3)*16, cols [0,32); warps 4-7: same rows, cols [32,64).
__global__ void __launch_bounds__(256) l1_gemm_mma(const __half2* __restrict__ W1h,
                                                   const float* __restrict__ root1,
                                                   const float* __restrict__ b1,
                                                   const int* __restrict__ cl1) {
    constexpr int AST = 136;               // halves per A/B row (272 B)
    extern __shared__ char dynsmem[];
    __half* As = (__half*)dynsmem;                   // 64 x 136 halves
    __half* Bs = (__half*)(dynsmem + 64 * AST * 2);  // 64 x 136 halves

    int tid = threadIdx.x, wid = tid >> 5, lane = tid & 31;
    int g = lane >> 2, t = lane & 3;
    int m0 = blockIdx.x * 64;
    float* P = pool();
    uint32_t sbA = su32(As);
    uint32_t sbB = su32(Bs);

    int lq = lane >> 3, lr = lane & 7;
    int rowq = (lq & 1) * 8 + lr;
    int colq = (lq >> 1) * 8;

    // A conversion: 8 warps, 8 rows each; lane L holds slots 8L..8L+7 (one uint4)
    const uint4* C1b = (const uint4*)((const __half2*)(P + O_C1));
#pragma unroll 8
    for (int r = wid; r < 64; r += 8) {
        int m = m0 + r;
        uint4 u = make_uint4(0u, 0u, 0u, 0u);
        if (m < cN1) u = C1b[(size_t)m * 32 + lane];
        float2 f0 = __half22float2(*(const __half2*)&u.x);
        float2 f1 = __half22float2(*(const __half2*)&u.y);
        float2 f2 = __half22float2(*(const __half2*)&u.z);
        float2 f3 = __half22float2(*(const __half2*)&u.w);
        float prev = __shfl_up_sync(0xffffffffu, f3.y, 1);
        if (lane == 0) prev = 0.0f;
        float a0 = f0.x + prev;   // k=4L : slots 8L, 8L-1
        float a1 = f1.x + f0.y;   // k=4L+1
        float a2 = f2.x + f1.y;   // k=4L+2
        float a3 = f3.x + f2.y;   // k=4L+3
        uint2 w;
        __half2 h0 = __floats2half2_rn(a0, a1);
        __half2 h1 = __floats2half2_rn(a2, a3);
        w.x = *(const uint32_t*)&h0;
        w.y = *(const uint32_t*)&h1;
        *(uint2*)&As[r * AST + 4 * lane] = w;
    }
    // B load: 64 rows x 64 half2, uint4 vectorized
    for (int idx = tid; idx < 64 * 16; idx += 256) {
        int r = idx >> 4, pq = idx & 15;
        *(uint4*)&Bs[r * AST + pq * 8] = *(const uint4*)(W1h + r * 64 + pq * 4);
    }
    __syncthreads();

    int mw = (wid & 3) * 16;     // row group
    int ncol0 = (wid >> 2) * 32; // N half
    float c[4][4];
#pragma unroll
    for (int nt = 0; nt < 4; nt++) {
        c[nt][0] = 0.f; c[nt][1] = 0.f; c[nt][2] = 0.f; c[nt][3] = 0.f;
    }
#pragma unroll
    for (int ks = 0; ks < 8; ks++) {
        uint32_t a0, a1, a2, a3;
        ldmx4(a0, a1, a2, a3, sbA + (uint32_t)((mw + rowq) * AST + ks * 16 + colq) * 2);
#pragma unroll
        for (int p = 0; p < 2; p++) {
            uint32_t b0, b1v, b2, b3;
            ldmx4(b0, b1v, b2, b3,
                  sbB + (uint32_t)((ncol0 + 16 * p + rowq) * AST + ks * 16 + colq) * 2);
            mma16816(c[2 * p],     a0, a1, a2, a3, b0, b2);
            mma16816(c[2 * p + 1], a0, a1, a2, a3, b1v, b3);
        }
    }

    // fused epilogue: node update + seg-max scatter into H2
    int mA = m0 + mw + g;
    int mB = mA + 8;
    float invdA = 0.f, hA = 0.f; int clA = 0;
    float invdB = 0.f, hB = 0.f; int clB = 0;
    if (mA < cN1) {
        invdA = 1.0f / fmaxf(P[O_DEG1 + mA], 1.0f);
        hA = fixf(P[O_H1 + mA]);
        clA = cl1[mA] << 6;
    }
    if (mB < cN1) {
        invdB = 1.0f / fmaxf(P[O_DEG1 + mB], 1.0f);
        hB = fixf(P[O_H1 + mB]);
        clB = cl1[mB] << 6;
    }
#pragma unroll
    for (int nt = 0; nt < 4; nt++) {
        int col = ncol0 + nt * 8 + 2 * t;
        float r0 = root1[col], r1 = root1[col + 1];
        float bb0 = b1[col],  bb1 = b1[col + 1];
        if (mA < cN1) {
            atomicMaxFloat(P + O_H2 + clA + col,     eluf(c[nt][0] * invdA + hA * r0 + bb0));
            atomicMaxFloat(P + O_H2 + clA + col + 1, eluf(c[nt][1] * invdA + hA * r1 + bb1));
        }
        if (mB < cN1) {
            atomicMaxFloat(P + O_H2 + clB + col,     eluf(c[nt][2] * invdB + hB * r0 + bb0));
            atomicMaxFloat(P + O_H2 + clB + col + 1, eluf(c[nt][3] * invdB + hB * r1 + bb1));
        }
    }
}

// ---------------- tensor-core batched GEMM: ldmatrix + cp.async double-buffered B ----------------
template<int OT, int KPG>
__global__ void __launch_bounds__(256) gemm_mma(int xoff, const __half2* __restrict__ Wh,
                                                __half2* __restrict__ XWh, int Nn) {
    constexpr int AST   = 72;
    constexpr int ABYTES = 128 * AST * 2;
    constexpr int BROW  = AST * 2;
    constexpr int BBYTES = OT * BROW;
    extern __shared__ char dynsmem[];
    __half* As = (__half*)dynsmem;
    char*   Bs = dynsmem + ABYTES;

    int tid = threadIdx.x, wid = tid >> 5, lane = tid & 31;
    int g = lane >> 2, t = lane & 3;
    int m0 = blockIdx.x * 128;
    int k0 = blockIdx.y * KPG;
    const float* X = pool() + xoff;
    uint32_t sbA = su32(As);
    uint32_t sbB = su32(Bs);

    int lq  = lane >> 3;
    int lr  = lane & 7;
    int rowq = (lq & 1) * 8 + lr;
    int colq = (lq >> 1) * 8;

    for (int idx = tid; idx < 128 * 32; idx += 256) {
        int r = idx >> 5, p = idx & 31;
        float2 v = make_float2(0.f, 0.f);
        if (m0 + r < Nn) {
            v = *(const float2*)(X + (size_t)(m0 + r) * 64 + p * 2);
            v.x = fixf(v.x); v.y = fixf(v.y);
        }
        *(__half2*)&As[r * AST + 2 * p] = __floats2half2_rn(v.x, v.y);
    }

    {
        const char* src = (const char*)Wh + (size_t)k0 * OT * 128;
        for (int idx = tid; idx < OT * 8; idx += 256) {
            int row = idx >> 3, c = idx & 7;
            cpasync16(sbB + row * BROW + c * 16, src + idx * 16);
        }
        CP_COMMIT();
    }
    __syncthreads();

    int mw = wid * 16;
    uint32_t af[4][4];
#pragma unroll
    for (int ks = 0; ks < 4; ks++) {
        uint32_t addr = sbA + (uint32_t)((mw + rowq) * AST + ks * 16 + colq) * 2;
        ldmx4(af[ks][0], af[ks][1], af[ks][2], af[ks][3], addr);
    }

    for (int j = 0; j < KPG; j++) {
        int buf = j & 1;
        if (j + 1 < KPG) {
            const char* src = (const char*)Wh + (size_t)(k0 + j + 1) * OT * 128;
            uint32_t dstb = sbB + ((j + 1) & 1) * BBYTES;
            for (int idx = tid; idx < OT * 8; idx += 256) {
                int row = idx >> 3, c = idx & 7;
                cpasync16(dstb + row * BROW + c * 16, src + idx * 16);
            }
            CP_COMMIT();
            asm volatile("cp.async.wait_group 1;" ::: "memory");
        } else {
            asm volatile("cp.async.wait_group 0;" ::: "memory");
        }
        __syncthreads();

        float c[OT / 8][4];
#pragma unroll
        for (int nt = 0; nt < OT / 8; nt++) {
            c[nt][0] = 0.f; c[nt][1] = 0.f; c[nt][2] = 0.f; c[nt][3] = 0.f;
        }
        uint32_t bufb = sbB + buf * BBYTES;
#pragma unroll
        for (int ks = 0; ks < 4; ks++) {
#pragma unroll
            for (int p = 0; p < OT / 16; p++) {
                uint32_t baddr = bufb + (uint32_t)(16 * p + rowq) * BROW +
                                 (uint32_t)(ks * 16 + colq) * 2;
                uint32_t b0, b1, b2, b3;
                ldmx4(b0, b1, b2, b3, baddr);
                mma16816(c[2 * p],     af[ks][0], af[ks][1], af[ks][2], af[ks][3], b0, b2);
                mma16816(c[2 * p + 1], af[ks][0], af[ks][1], af[ks][2], af[ks][3], b1, b3);
            }
        }
        int k = k0 + j;
        int mA = m0 + mw + g;
        int mB = mA + 8;
        __half2* dA = XWh + ((size_t)k * Nn + mA) * (OT / 2) + t;
        __half2* dB = XWh + ((size_t)k * Nn + mB) * (OT / 2) + t;
#pragma unroll
        for (int nt = 0; nt < OT / 8; nt++) {
            if (mA < Nn) dA[nt * 4] = __floats2half2_rn(c[nt][0], c[nt][1]);
            if (mB < Nn) dB[nt * 4] = __floats2half2_rn(c[nt][2], c[nt][3]);
        }
        __syncthreads();
    }
}

// ---------------- gather layer2: warp per edge, pair-split halves ----------------
__global__ void gather_64(const int* __restrict__ edge, int E, const float* __restrict__ ps,
                          const __half2* __restrict__ XWh, int Nn, int aggoff, int degoff) {
    int gw = (blockIdx.x * blockDim.x + threadIdx.x) >> 5;
    if (gw >= E) return;
    int lane = threadIdx.x & 31;
    int half = lane >> 4, l16 = lane & 15;
    float g0[2], g1[2], g2[2]; int kb;
    load_pseudo(ps, gw, g0, g1, g2, kb);
    int src = edge[gw];
    int dst = edge[E + gw];
    float gh = g0[half];
    float a0 = 0.f, a1 = 0.f, a2 = 0.f, a3 = 0.f;
#pragma unroll
    for (int p = 0; p < 4; p++) {
        float basis = gh * g1[p & 1] * g2[p >> 1];
        int k = kb + 5 * (p & 1) + 25 * (p >> 1) + half;
        uint2 u = *((const uint2*)(XWh + ((size_t)k * Nn + src) * 32) + l16);
        float2 v0 = __half22float2(*(const __half2*)&u.x);
        float2 v1 = __half22float2(*(const __half2*)&u.y);
        a0 = fmaf(basis, v0.x, a0);
        a1 = fmaf(basis, v0.y, a1);
        a2 = fmaf(basis, v1.x, a2);
        a3 = fmaf(basis, v1.y, a3);
    }
    a0 += __shfl_xor_sync(0xffffffffu, a0, 16);
    a1 += __shfl_xor_sync(0xffffffffu, a1, 16);
    a2 += __shfl_xor_sync(0xffffffffu, a2, 16);
    a3 += __shfl_xor_sync(0xffffffffu, a3, 16);
    float* P = pool();
    if (half == 0)
        redAdd4(P + aggoff + dst * 64 + 4 * l16, a0, a1, a2, a3);
    if (lane == 0) atomicAdd(P + degoff + dst, 1.0f);
}

// ---------------- gather layer3: warp per edge, pair-split halves ----------------
__global__ void gather_128(const int* __restrict__ edge, int E, const float* __restrict__ ps,
                           const __half2* __restrict__ XWh, int Nn, int aggoff, int degoff) {
    int gw = (blockIdx.x * blockDim.x + threadIdx.x) >> 5;
    if (gw >= E) return;
    int lane = threadIdx.x & 31;
    int half = lane >> 4, l16 = lane & 15;
    float g0[2], g1[2], g2[2]; int kb;
    load_pseudo(ps, gw, g0, g1, g2, kb);
    int src = edge[gw];
    int dst = edge[E + gw];
    float gh = g0[half];
    float a[8];
#pragma unroll
    for (int i = 0; i < 8; i++) a[i] = 0.f;
#pragma unroll
    for (int p = 0; p < 4; p++) {
        float basis = gh * g1[p & 1] * g2[p >> 1];
        int k = kb + 5 * (p & 1) + 25 * (p >> 1) + half;
        uint4 u = *((const uint4*)(XWh + ((size_t)k * Nn + src) * 64) + l16);
        float2 v0 = __half22float2(*(const __half2*)&u.x);
        float2 v1 = __half22float2(*(const __half2*)&u.y);
        float2 v2 = __half22float2(*(const __half2*)&u.z);
        float2 v3 = __half22float2(*(const __half2*)&u.w);
        a[0] = fmaf(basis, v0.x, a[0]); a[1] = fmaf(basis, v0.y, a[1]);
        a[2] = fmaf(basis, v1.x, a[2]); a[3] = fmaf(basis, v1.y, a[3]);
        a[4] = fmaf(basis, v2.x, a[4]); a[5] = fmaf(basis, v2.y, a[5]);
        a[6] = fmaf(basis, v3.x, a[6]); a[7] = fmaf(basis, v3.y, a[7]);
    }
#pragma unroll
    for (int i = 0; i < 8; i++)
        a[i] += __shfl_xor_sync(0xffffffffu, a[i], 16);
    float* P = pool();
    if (half == 0) {
        redAdd4(P + aggoff + dst * 128 + 8 * l16,     a[0], a[1], a[2], a[3]);
        redAdd4(P + aggoff + dst * 128 + 8 * l16 + 4, a[4], a[5], a[6], a[7]);
    }
    if (lane == 0) atomicAdd(P + degoff + dst, 1.0f);
}

// ---------------- node update + fused seg-max into next H ----------------
__global__ void node_dense(int hoff, int aggoff, int degoff, const int* __restrict__ cl,
                           int outoff, const float* __restrict__ root,
                           const float* __restrict__ bias, int ntot, int shift) {
    int t = blockIdx.x * blockDim.x + threadIdx.x;
    if (t >= ntot) return;
    int n = t >> shift;
    int o = t & ((1 << shift) - 1);
    float* P = pool();
    const float* h = P + hoff + n * 64;
    float acc = bias[o] + P[aggoff + t] / fmaxf(P[degoff + n], 1.0f);
#pragma unroll 16
    for (int i = 0; i < 64; i++)
        acc = fmaf(fixf(h[i]), root[(i << shift) + o], acc);
    atomicMaxFloat(P + outoff + (cl[n] << shift) + o, eluf(acc));
}

// ---------------- final MLP + log_softmax ----------------
__global__ void fc_kernel(const float* __restrict__ w1, const float* __restrict__ b1,
                          const float* __restrict__ w2, const float* __restrict__ b2,
                          float* __restrict__ out) {
    __shared__ float xrow[1024];
    __shared__ float hrow[256];
    __shared__ float logits[10];
    __shared__ float red[2];
    int b = blockIdx.x;
    int t = threadIdx.x;
    float* P = pool();
    for (int i = t; i < 1024; i += 256) xrow[i] = fixf(P[O_H4 + b * 1024 + i]);
    __syncthreads();

    float a0 = b1[t], a1 = 0.f, a2 = 0.f, a3 = 0.f;
#pragma unroll 4
    for (int i = 0; i < 1024; i += 4) {
        a0 = fmaf(xrow[i + 0], w1[(i + 0) * 256 + t], a0);
        a1 = fmaf(xrow[i + 1], w1[(i + 1) * 256 + t], a1);
        a2 = fmaf(xrow[i + 2], w1[(i + 2) * 256 + t], a2);
        a3 = fmaf(xrow[i + 3], w1[(i + 3) * 256 + t], a3);
    }
    hrow[t] = eluf((a0 + a1) + (a2 + a3));
    __syncthreads();

    if (t < 10) {
        float a = b2[t];
#pragma unroll 8
        for (int i = 0; i < 256; i++)
            a = fmaf(hrow[i], w2[i * 10 + t], a);
        logits[t] = a;
    }
    __syncthreads();
    if (t == 0) {
        float m = logits[0];
        for (int j = 1; j < 10; j++) m = fmaxf(m, logits[j]);
        float s = 0.0f;
        for (int j = 0; j < 10; j++) s += expf(logits[j] - m);
        red[0] = m;
        red[1] = logf(s);
    }
    __syncthreads();
    if (t < 10) out[b * 10 + t] = logits[t] - red[0] - red[1];
}

// ---------------- host ----------------
extern "C" void kernel_launch(void* const* d_in, const int* in_sizes, int n_in,
                              void* d_out, int out_size) {
    const float* x0      = (const float*)d_in[0];
    const int*   cl0     = (const int*)  d_in[1];
    const int*   edge1   = (const int*)  d_in[2];
    const float* pseudo1 = (const float*)d_in[3];
    const float* W1      = (const float*)d_in[4];
    const float* root1   = (const float*)d_in[5];
    const float* b1      = (const float*)d_in[6];
    const int*   cl1     = (const int*)  d_in[7];
    const int*   edge2   = (const int*)  d_in[8];
    const float* pseudo2 = (const float*)d_in[9];
    const float* W2      = (const float*)d_in[10];
    const float* root2   = (const float*)d_in[11];
    const float* b2      = (const float*)d_in[12];
    const int*   cl2     = (const int*)  d_in[13];
    const int*   edge3   = (const int*)  d_in[14];
    const float* pseudo3 = (const float*)d_in[15];
    const float* W3      = (const float*)d_in[16];
    const float* root3   = (const float*)d_in[17];
    const float* b3      = (const float*)d_in[18];
    const int*   cl3     = (const int*)  d_in[19];
    const float* fc1w    = (const float*)d_in[20];
    const float* fc1b    = (const float*)d_in[21];
    const float* fc2w    = (const float*)d_in[22];
    const float* fc2b    = (const float*)d_in[23];
    float* out = (float*)d_out;

    const int TB = 256;

    __half2* xw2h; __half2* xw3h; __half2* w1h; __half2* w2h; __half2* w3h;
    cudaGetSymbolAddress((void**)&xw2h, g_xw2h4);
    cudaGetSymbolAddress((void**)&xw3h, g_xw3h4);
    cudaGetSymbolAddress((void**)&w1h, g_w1h4);
    cudaGetSymbolAddress((void**)&w2h, g_w2h4);
    cudaGetSymbolAddress((void**)&w3h, g_w3h4);

    const int SM64  = 18432 + 2 * 64 * 144;   // 36864
    const int SM128 = 18432 + 2 * 128 * 144;  // 55296
    const int SML1  = 64 * 136 * 2 + 64 * 136 * 2;  // 34816
    cudaFuncSetAttribute(gemm_mma<64, 5>,  cudaFuncAttributeMaxDynamicSharedMemorySize, SM64);
    cudaFuncSetAttribute(gemm_mma<128, 5>, cudaFuncAttributeMaxDynamicSharedMemorySize, SM128);
    cudaFuncSetAttribute(l1_gemm_mma, cudaFuncAttributeMaxDynamicSharedMemorySize, SML1);

    // 1: init + W conversion
    init_and_convert<<<1024, TB>>>(W1, W2, W3, w1h, w2h, w3h);
    // 2: seg_max(x0) -> H1
    segmax_x0_kernel<<<CDIV(cN0, TB), TB>>>(x0, cl0);
    // 3: layer-1 scatter (f16x2 atomics)
    l1_scatter<<<CDIV(cE1, TB), TB>>>(edge1, pseudo1);
    // 4: layer-1 mma GEMM + node update + seg-max -> H2 (profile slot)
    l1_gemm_mma<<<CDIV(cN1, 64), 256, SML1>>>(w1h, root1, b1, cl1);
    // 5: layer-2 tensor-core GEMM -> XW2 (f16)
    {
        dim3 g(CDIV(cN2, 128), 25);
        gemm_mma<64, 5><<<g, 256, SM64>>>(O_H2, w2h, xw2h, cN2);
    }
    // 6: layer-2 gather
    gather_64<<<CDIV(cE2 * 32, TB), TB>>>(edge2, cE2, pseudo2, xw2h, cN2, O_AGG2, O_DEG2);
    // 7: layer-2 node update + seg-max -> H3
    node_dense<<<CDIV(cN2 * 64, TB), TB>>>(O_H2, O_AGG2, O_DEG2, cl2, O_H3, root2, b2, cN2 * 64, 6);
    // 8: layer-3 tensor-core GEMM -> XW3 (f16)
    {
        dim3 g(CDIV(cN3, 128), 25);
        gemm_mma<128, 5><<<g, 256, SM128>>>(O_H3, w3h, xw3h, cN3);
    }
    // 9: layer-3 gather
    gather_128<<<CDIV(cE3 * 32, TB), TB>>>(edge3, cE3, pseudo3, xw3h, cN3, O_AGG3, O_DEG3);
    // 10: layer-3 node update + seg-max -> H4
    node_dense<<<CDIV(cN3 * 128, TB), TB>>>(O_H3, O_AGG3, O_DEG3, cl3, O_H4, root3, b3, cN3 * 128, 7);
    // 11: MLP head + log_softmax
    fc_kernel<<<cB, 256>>>(fc1w, fc1b, fc2w, fc2b, out);
}

// round 15
// speedup vs baseline: 4.7848x; 1.0255x over previous
#include <cuda_runtime.h>
#include <cuda_fp16.h>
#include <cuda_fp8.h>
#include <math.h>
#include <stdint.h>

#define CDIV(a,b) (((a)+(b)-1)/(b))

// Problem constants
constexpr int cN0 = 120000;
constexpr int cN1 = 20000;
constexpr int cN2 = 6000;
constexpr int cN3 = 1600;
constexpr int cB  = 64;
constexpr int cE1 = 480000;
constexpr int cE2 = 144000;
constexpr int cE3 = 38400;
constexpr int cK  = 125;

// ---------------- scratch pool (no cudaMalloc allowed) ----------------
constexpr int AL64(int x) { return (x + 63) & ~63; }
constexpr int O_H1   = 0;
constexpr int O_C1   = O_H1   + AL64(cN1);      // C1h[dst][256] halves (slot 2k+off), f16
constexpr int O_DEG1 = O_C1   + cN1 * 128;
constexpr int O_H2   = O_DEG1 + AL64(cN1);
constexpr int O_AGG2 = O_H2   + cN2 * 64;
constexpr int O_DEG2 = O_AGG2 + cN2 * 64;
constexpr int O_H3   = O_DEG2 + AL64(cN2);
constexpr int O_AGG3 = O_H3   + cN3 * 64;
constexpr int O_DEG3 = O_AGG3 + cN3 * 128;
constexpr int O_H4   = O_DEG3 + AL64(cN3);
constexpr int POOLN  = O_H4   + 512 * 128;

__device__ float4 g_pool4[(POOLN + 3) / 4];
__device__ __forceinline__ float* pool() { return (float*)g_pool4; }

// XW2 in fp8 e4m3: [k][n][64] bytes; XW3 in f16: [k][n][128]
__device__ uint4 g_xw2q4[(size_t)cK * cN2 * 64 / 16];        // 48 MB
__device__ uint4 g_xw3h4[(size_t)cK * cN3 * 128 * 2 / 16];   // 51.2 MB
// f16 W tiles, layout [k][o][kk] = B col-major for mma
__device__ uint4 g_w2h4[cK * 64 * 64 * 2 / 16];    // 1 MB
__device__ uint4 g_w3h4[cK * 128 * 64 * 2 / 16];   // 2 MB
// W1 f16: [o(64)][kk(128, padded)] halves
__device__ uint4 g_w1h4[64 * 128 * 2 / 16];        // 16 KB

// ---------------- helpers ----------------
__device__ __forceinline__ void atomicMaxFloat(float* addr, float val) {
    if (val >= 0.0f)
        atomicMax((int*)addr, __float_as_int(val));
    else
        atomicMin((unsigned int*)addr, __float_as_uint(val));
}
__device__ __forceinline__ void redAdd4(float* addr, float a, float b, float c, float d) {
    asm volatile("red.global.add.v4.f32 [%0], {%1,%2,%3,%4};"
                 :: "l"(addr), "f"(a), "f"(b), "f"(c), "f"(d) : "memory");
}
__device__ __forceinline__ void redAddH2(__half2* addr, __half2 v) {
    uint32_t u = *(const uint32_t*)&v;
    asm volatile("red.global.add.noftz.f16x2 [%0], %1;" :: "l"(addr), "r"(u) : "memory");
}
__device__ __forceinline__ float eluf(float v) { return v > 0.0f ? v : expm1f(v); }
__device__ __forceinline__ float fixf(float v) { return isfinite(v) ? v : 0.0f; }

__device__ __forceinline__ uint32_t su32(const void* p) {
    uint32_t a;
    asm("{ .reg .u64 t; cvta.to.shared.u64 t, %1; cvt.u32.u64 %0, t; }" : "=r"(a) : "l"(p));
    return a;
}
__device__ __forceinline__ void mma16816(float c[4], uint32_t a0, uint32_t a1,
                                         uint32_t a2, uint32_t a3,
                                         uint32_t b0, uint32_t b1) {
    asm volatile("mma.sync.aligned.m16n8k16.row.col.f32.f16.f16.f32 "
                 "{%0,%1,%2,%3}, {%4,%5,%6,%7}, {%8,%9}, {%0,%1,%2,%3};"
                 : "+f"(c[0]), "+f"(c[1]), "+f"(c[2]), "+f"(c[3])
                 : "r"(a0), "r"(a1), "r"(a2), "r"(a3), "r"(b0), "r"(b1));
}
__device__ __forceinline__ void ldmx4(uint32_t& f0, uint32_t& f1, uint32_t& f2, uint32_t& f3,
                                      uint32_t addr) {
    asm volatile("ldmatrix.sync.aligned.m8n8.x4.shared.b16 {%0,%1,%2,%3}, [%4];"
                 : "=r"(f0), "=r"(f1), "=r"(f2), "=r"(f3) : "r"(addr));
}
__device__ __forceinline__ void cpasync16(uint32_t sdst, const void* gsrc) {
    asm volatile("cp.async.cg.shared.global [%0], [%1], 16;" :: "r"(sdst), "l"(gsrc));
}
#define CP_COMMIT() asm volatile("cp.async.commit_group;" ::: "memory")

// fp8 helpers
__device__ __forceinline__ uint16_t f2q2(float a, float b) {
    return (uint16_t)__nv_cvt_float2_to_fp8x2(make_float2(a, b), __NV_SATFINITE, __NV_E4M3);
}
__device__ __forceinline__ float2 q2f2(uint16_t q) {
    __half2_raw r = __nv_cvt_fp8x2_to_halfraw2((__nv_fp8x2_storage_t)q, __NV_E4M3);
    return __half22float2(*(__half2*)&r);
}

// ---------------- init + W conversion (fused, independent work) ----------------
__global__ void init_and_convert(const float* __restrict__ W1, const float* __restrict__ W2,
                                 const float* __restrict__ W3, __half2* __restrict__ Wh1,
                                 __half2* __restrict__ Wh2, __half2* __restrict__ Wh3) {
    float* P = pool();
    const float NI = -INFINITY;
    int t = blockIdx.x * blockDim.x + threadIdx.x;
    int stride = gridDim.x * blockDim.x;
    for (int i = t; i < cN1; i += stride) P[O_H1 + i] = NI;
    for (int i = t; i < cN2 * 64; i += stride) P[O_H2 + i] = NI;
    for (int i = t; i < cN3 * 64; i += stride) P[O_H3 + i] = NI;
    for (int i = t; i < 512 * 128; i += stride) P[O_H4 + i] = NI;
    for (int i = t; i < cN1 * 128; i += stride) P[O_C1 + i] = 0.0f;  // f16 zeros == 0x0
    for (int i = t; i < cN1; i += stride) P[O_DEG1 + i] = 0.0f;
    for (int i = t; i < cN2 * 64; i += stride) P[O_AGG2 + i] = 0.0f;
    for (int i = t; i < cN2; i += stride) P[O_DEG2 + i] = 0.0f;
    for (int i = t; i < cN3 * 128; i += stride) P[O_AGG3 + i] = 0.0f;
    for (int i = t; i < cN3; i += stride) P[O_DEG3 + i] = 0.0f;
    // W1 -> f16 [o][kk] (kk padded to 128 with zeros)
    for (int idx = t; idx < 64 * 64; idx += stride) {
        int o = idx >> 6, p = idx & 63;
        float w0 = (2 * p     < cK) ? W1[(2 * p) * 64 + o]     : 0.0f;
        float w1 = (2 * p + 1 < cK) ? W1[(2 * p + 1) * 64 + o] : 0.0f;
        Wh1[o * 64 + p] = __floats2half2_rn(w0, w1);
    }
    // W2 -> f16 [k][o][kk]
    for (int idx = t; idx < cK * 64 * 32; idx += stride) {
        int k = idx / (64 * 32);
        int rem = idx % (64 * 32);
        int o = rem >> 5, ip = rem & 31;
        const float* wk = W2 + (size_t)k * 64 * 64;
        Wh2[((size_t)k * 64 + o) * 32 + ip] =
            __floats2half2_rn(wk[(2 * ip) * 64 + o], wk[(2 * ip + 1) * 64 + o]);
    }
    // W3 -> f16 [k][o][kk]
    for (int idx = t; idx < cK * 128 * 32; idx += stride) {
        int k = idx / (128 * 32);
        int rem = idx % (128 * 32);
        int o = rem >> 5, ip = rem & 31;
        const float* wk = W3 + (size_t)k * 64 * 128;
        Wh3[((size_t)k * 128 + o) * 32 + ip] =
            __floats2half2_rn(wk[(2 * ip) * 128 + o], wk[(2 * ip + 1) * 128 + o]);
    }
}

__global__ void segmax_x0_kernel(const float* __restrict__ x, const int* __restrict__ cl) {
    int t = blockIdx.x * blockDim.x + threadIdx.x;
    if (t >= cN0) return;
    atomicMaxFloat(pool() + O_H1 + cl[t], x[t]);
}

// ---------------- spline basis ----------------
__device__ __forceinline__ void load_pseudo(const float* __restrict__ ps, int e,
                                            float g0[2], float g1[2], float g2[2], int& kbase) {
    float p0 = ps[e * 3 + 0] * 4.0f;
    float p1 = ps[e * 3 + 1] * 4.0f;
    float p2 = ps[e * 3 + 2] * 4.0f;
    float lo0 = fmaxf(fminf(floorf(p0), 3.0f), 0.0f);
    float lo1 = fmaxf(fminf(floorf(p1), 3.0f), 0.0f);
    float lo2 = fmaxf(fminf(floorf(p2), 3.0f), 0.0f);
    float f0 = p0 - lo0, f1 = p1 - lo1, f2 = p2 - lo2;
    g0[0] = 1.0f - f0; g0[1] = f0;
    g1[0] = 1.0f - f1; g1[1] = f1;
    g2[0] = 1.0f - f2; g2[1] = f2;
    kbase = (int)lo0 + 5 * (int)lo1 + 25 * (int)lo2;
}

// ---------------- layer 1 scatter: C1h[dst][2*pairk + {0,1}] += basis * x_src (f16x2) ----------------
__global__ void l1_scatter(const int* __restrict__ edge, const float* __restrict__ ps) {
    int e = blockIdx.x * blockDim.x + threadIdx.x;
    if (e >= cE1) return;
    float g0[2], g1[2], g2[2]; int kb;
    load_pseudo(ps, e, g0, g1, g2, kb);
    int src = edge[e];
    int dst = edge[cE1 + e];
    float* P = pool();
    float xs = fixf(P[O_H1 + src]);
    float x0s = g0[0] * xs, x1s = g0[1] * xs;
    __half2* c = (__half2*)(P + O_C1) + (size_t)dst * 128;
#pragma unroll
    for (int p = 0; p < 4; p++) {
        float gb = g1[p & 1] * g2[p >> 1];
        int pairk = kb + 5 * (p & 1) + 25 * (p >> 1);
        redAddH2(c + pairk, __floats2half2_rn(gb * x0s, gb * x1s));
    }
    atomicAdd(P + O_DEG1 + dst, 1.0f);
}

// ---------------- layer 1 GEMM via mma.sync (32-row tiles, 256 threads) ----------------
// warps: (wid&1) -> row group of 16, (wid>>1) -> 16-col group.
__global__ void __launch_bounds__(256) l1_gemm_mma(const __half2* __restrict__ W1h,
                                                   const float* __restrict__ root1,
                                                   const float* __restrict__ b1,
                                                   const int* __restrict__ cl1) {
    constexpr int AST = 136;               // halves per A/B row (272 B)
    extern __shared__ char dynsmem[];
    __half* As = (__half*)dynsmem;                   // 32 x 136 halves
    __half* Bs = (__half*)(dynsmem + 32 * AST * 2);  // 64 x 136 halves

    int tid = threadIdx.x, wid = tid >> 5, lane = tid & 31;
    int g = lane >> 2, t = lane & 3;
    int m0 = blockIdx.x * 32;
    float* P = pool();
    uint32_t sbA = su32(As);
    uint32_t sbB = su32(Bs);

    int lq = lane >> 3, lr = lane & 7;
    int rowq = (lq & 1) * 8 + lr;
    int colq = (lq >> 1) * 8;

    // A conversion: 8 warps, 4 rows each; lane L holds slots 8L..8L+7 (one uint4)
    const uint4* C1b = (const uint4*)((const __half2*)(P + O_C1));
#pragma unroll 4
    for (int r = wid; r < 32; r += 8) {
        int m = m0 + r;
        uint4 u = make_uint4(0u, 0u, 0u, 0u);
        if (m < cN1) u = C1b[(size_t)m * 32 + lane];
        float2 f0 = __half22float2(*(const __half2*)&u.x);
        float2 f1 = __half22float2(*(const __half2*)&u.y);
        float2 f2 = __half22float2(*(const __half2*)&u.z);
        float2 f3 = __half22float2(*(const __half2*)&u.w);
        float prev = __shfl_up_sync(0xffffffffu, f3.y, 1);
        if (lane == 0) prev = 0.0f;
        float a0 = f0.x + prev;
        float a1 = f1.x + f0.y;
        float a2 = f2.x + f1.y;
        float a3 = f3.x + f2.y;
        uint2 w;
        __half2 h0 = __floats2half2_rn(a0, a1);
        __half2 h1 = __floats2half2_rn(a2, a3);
        w.x = *(const uint32_t*)&h0;
        w.y = *(const uint32_t*)&h1;
        *(uint2*)&As[r * AST + 4 * lane] = w;
    }
    // B load: 64 rows x 64 half2, uint4 vectorized
    for (int idx = tid; idx < 64 * 16; idx += 256) {
        int r = idx >> 4, pq = idx & 15;
        *(uint4*)&Bs[r * AST + pq * 8] = *(const uint4*)(W1h + r * 64 + pq * 4);
    }
    __syncthreads();

    int mw = (wid & 1) * 16;     // row group
    int ncol0 = (wid >> 1) * 16; // 16-col group
    float c[2][4];
    c[0][0] = c[0][1] = c[0][2] = c[0][3] = 0.f;
    c[1][0] = c[1][1] = c[1][2] = c[1][3] = 0.f;
#pragma unroll
    for (int ks = 0; ks < 8; ks++) {
        uint32_t a0, a1, a2, a3;
        ldmx4(a0, a1, a2, a3, sbA + (uint32_t)((mw + rowq) * AST + ks * 16 + colq) * 2);
        uint32_t b0, b1v, b2, b3;
        ldmx4(b0, b1v, b2, b3, sbB + (uint32_t)((ncol0 + rowq) * AST + ks * 16 + colq) * 2);
        mma16816(c[0], a0, a1, a2, a3, b0, b2);
        mma16816(c[1], a0, a1, a2, a3, b1v, b3);
    }

    // fused epilogue: node update + seg-max scatter into H2
    int mA = m0 + mw + g;
    int mB = mA + 8;
    float invdA = 0.f, hA = 0.f; int clA = 0;
    float invdB = 0.f, hB = 0.f; int clB = 0;
    if (mA < cN1) {
        invdA = 1.0f / fmaxf(P[O_DEG1 + mA], 1.0f);
        hA = fixf(P[O_H1 + mA]);
        clA = cl1[mA] << 6;
    }
    if (mB < cN1) {
        invdB = 1.0f / fmaxf(P[O_DEG1 + mB], 1.0f);
        hB = fixf(P[O_H1 + mB]);
        clB = cl1[mB] << 6;
    }
#pragma unroll
    for (int nt = 0; nt < 2; nt++) {
        int col = ncol0 + nt * 8 + 2 * t;
        float r0 = root1[col], r1 = root1[col + 1];
        float bb0 = b1[col],  bb1 = b1[col + 1];
        if (mA < cN1) {
            atomicMaxFloat(P + O_H2 + clA + col,     eluf(c[nt][0] * invdA + hA * r0 + bb0));
            atomicMaxFloat(P + O_H2 + clA + col + 1, eluf(c[nt][1] * invdA + hA * r1 + bb1));
        }
        if (mB < cN1) {
            atomicMaxFloat(P + O_H2 + clB + col,     eluf(c[nt][2] * invdB + hB * r0 + bb0));
            atomicMaxFloat(P + O_H2 + clB + col + 1, eluf(c[nt][3] * invdB + hB * r1 + bb1));
        }
    }
}

// ---------------- tensor-core batched GEMM: ldmatrix + cp.async double-buffered B ----------------
// QOUT=true -> fp8 e4m3 output (XWq, 1 B/elem); false -> f16 output (XWh, 2 B/elem).
template<int OT, int KPG, bool QOUT>
__global__ void __launch_bounds__(256) gemm_mma(int xoff, const __half2* __restrict__ Wh,
                                                void* __restrict__ XWout, int Nn) {
    constexpr int AST   = 72;
    constexpr int ABYTES = 128 * AST * 2;
    constexpr int BROW  = AST * 2;
    constexpr int BBYTES = OT * BROW;
    extern __shared__ char dynsmem[];
    __half* As = (__half*)dynsmem;
    char*   Bs = dynsmem + ABYTES;

    int tid = threadIdx.x, wid = tid >> 5, lane = tid & 31;
    int g = lane >> 2, t = lane & 3;
    int m0 = blockIdx.x * 128;
    int k0 = blockIdx.y * KPG;
    const float* X = pool() + xoff;
    uint32_t sbA = su32(As);
    uint32_t sbB = su32(Bs);

    int lq  = lane >> 3;
    int lr  = lane & 7;
    int rowq = (lq & 1) * 8 + lr;
    int colq = (lq >> 1) * 8;

    for (int idx = tid; idx < 128 * 32; idx += 256) {
        int r = idx >> 5, p = idx & 31;
        float2 v = make_float2(0.f, 0.f);
        if (m0 + r < Nn) {
            v = *(const float2*)(X + (size_t)(m0 + r) * 64 + p * 2);
            v.x = fixf(v.x); v.y = fixf(v.y);
        }
        *(__half2*)&As[r * AST + 2 * p] = __floats2half2_rn(v.x, v.y);
    }

    {
        const char* src = (const char*)Wh + (size_t)k0 * OT * 128;
        for (int idx = tid; idx < OT * 8; idx += 256) {
            int row = idx >> 3, c = idx & 7;
            cpasync16(sbB + row * BROW + c * 16, src + idx * 16);
        }
        CP_COMMIT();
    }
    __syncthreads();

    int mw = wid * 16;
    uint32_t af[4][4];
#pragma unroll
    for (int ks = 0; ks < 4; ks++) {
        uint32_t addr = sbA + (uint32_t)((mw + rowq) * AST + ks * 16 + colq) * 2;
        ldmx4(af[ks][0], af[ks][1], af[ks][2], af[ks][3], addr);
    }

    for (int j = 0; j < KPG; j++) {
        int buf = j & 1;
        if (j + 1 < KPG) {
            const char* src = (const char*)Wh + (size_t)(k0 + j + 1) * OT * 128;
            uint32_t dstb = sbB + ((j + 1) & 1) * BBYTES;
            for (int idx = tid; idx < OT * 8; idx += 256) {
                int row = idx >> 3, c = idx & 7;
                cpasync16(dstb + row * BROW + c * 16, src + idx * 16);
            }
            CP_COMMIT();
            asm volatile("cp.async.wait_group 1;" ::: "memory");
        } else {
            asm volatile("cp.async.wait_group 0;" ::: "memory");
        }
        __syncthreads();

        float c[OT / 8][4];
#pragma unroll
        for (int nt = 0; nt < OT / 8; nt++) {
            c[nt][0] = 0.f; c[nt][1] = 0.f; c[nt][2] = 0.f; c[nt][3] = 0.f;
        }
        uint32_t bufb = sbB + buf * BBYTES;
#pragma unroll
        for (int ks = 0; ks < 4; ks++) {
#pragma unroll
            for (int p = 0; p < OT / 16; p++) {
                uint32_t baddr = bufb + (uint32_t)(16 * p + rowq) * BROW +
                                 (uint32_t)(ks * 16 + colq) * 2;
                uint32_t b0, b1, b2, b3;
                ldmx4(b0, b1, b2, b3, baddr);
                mma16816(c[2 * p],     af[ks][0], af[ks][1], af[ks][2], af[ks][3], b0, b2);
                mma16816(c[2 * p + 1], af[ks][0], af[ks][1], af[ks][2], af[ks][3], b1, b3);
            }
        }
        int k = k0 + j;
        int mA = m0 + mw + g;
        int mB = mA + 8;
        if (QOUT) {
            uint8_t* qA = (uint8_t*)XWout + ((size_t)k * Nn + mA) * OT + 2 * t;
            uint8_t* qB = (uint8_t*)XWout + ((size_t)k * Nn + mB) * OT + 2 * t;
#pragma unroll
            for (int nt = 0; nt < OT / 8; nt++) {
                if (mA < Nn) *(uint16_t*)(qA + nt * 8) = f2q2(c[nt][0], c[nt][1]);
                if (mB < Nn) *(uint16_t*)(qB + nt * 8) = f2q2(c[nt][2], c[nt][3]);
            }
        } else {
            __half2* dA = (__half2*)XWout + ((size_t)k * Nn + mA) * (OT / 2) + t;
            __half2* dB = (__half2*)XWout + ((size_t)k * Nn + mB) * (OT / 2) + t;
#pragma unroll
            for (int nt = 0; nt < OT / 8; nt++) {
                if (mA < Nn) dA[nt * 4] = __floats2half2_rn(c[nt][0], c[nt][1]);
                if (mB < Nn) dB[nt * 4] = __floats2half2_rn(c[nt][2], c[nt][3]);
            }
        }
        __syncthreads();
    }
}

// ---------------- gather layer2: warp per edge, pair-split halves, fp8 XW ----------------
__global__ void gather_64(const int* __restrict__ edge, int E, const float* __restrict__ ps,
                          const uint8_t* __restrict__ XWq, int Nn, int aggoff, int degoff) {
    int gw = (blockIdx.x * blockDim.x + threadIdx.x) >> 5;
    if (gw >= E) return;
    int lane = threadIdx.x & 31;
    int half = lane >> 4, l16 = lane & 15;
    float g0[2], g1[2], g2[2]; int kb;
    load_pseudo(ps, gw, g0, g1, g2, kb);
    int src = edge[gw];
    int dst = edge[E + gw];
    float gh = g0[half];
    float a0 = 0.f, a1 = 0.f, a2 = 0.f, a3 = 0.f;
#pragma unroll
    for (int p = 0; p < 4; p++) {
        float basis = gh * g1[p & 1] * g2[p >> 1];
        int k = kb + 5 * (p & 1) + 25 * (p >> 1) + half;
        uint32_t u = ((const uint32_t*)(XWq + ((size_t)k * Nn + src) * 64))[l16];
        float2 v0 = q2f2((uint16_t)(u & 0xffffu));
        float2 v1 = q2f2((uint16_t)(u >> 16));
        a0 = fmaf(basis, v0.x, a0);
        a1 = fmaf(basis, v0.y, a1);
        a2 = fmaf(basis, v1.x, a2);
        a3 = fmaf(basis, v1.y, a3);
    }
    a0 += __shfl_xor_sync(0xffffffffu, a0, 16);
    a1 += __shfl_xor_sync(0xffffffffu, a1, 16);
    a2 += __shfl_xor_sync(0xffffffffu, a2, 16);
    a3 += __shfl_xor_sync(0xffffffffu, a3, 16);
    float* P = pool();
    if (half == 0)
        redAdd4(P + aggoff + dst * 64 + 4 * l16, a0, a1, a2, a3);
    if (lane == 0) atomicAdd(P + degoff + dst, 1.0f);
}

// ---------------- gather layer3: warp per edge, pair-split halves, f16 XW ----------------
__global__ void gather_128(const int* __restrict__ edge, int E, const float* __restrict__ ps,
                           const __half2* __restrict__ XWh, int Nn, int aggoff, int degoff) {
    int gw = (blockIdx.x * blockDim.x + threadIdx.x) >> 5;
    if (gw >= E) return;
    int lane = threadIdx.x & 31;
    int half = lane >> 4, l16 = lane & 15;
    float g0[2], g1[2], g2[2]; int kb;
    load_pseudo(ps, gw, g0, g1, g2, kb);
    int src = edge[gw];
    int dst = edge[E + gw];
    float gh = g0[half];
    float a[8];
#pragma unroll
    for (int i = 0; i < 8; i++) a[i] = 0.f;
#pragma unroll
    for (int p = 0; p < 4; p++) {
        float basis = gh * g1[p & 1] * g2[p >> 1];
        int k = kb + 5 * (p & 1) + 25 * (p >> 1) + half;
        uint4 u = *((const uint4*)(XWh + ((size_t)k * Nn + src) * 64) + l16);
        float2 v0 = __half22float2(*(const __half2*)&u.x);
        float2 v1 = __half22float2(*(const __half2*)&u.y);
        float2 v2 = __half22float2(*(const __half2*)&u.z);
        float2 v3 = __half22float2(*(const __half2*)&u.w);
        a[0] = fmaf(basis, v0.x, a[0]); a[1] = fmaf(basis, v0.y, a[1]);
        a[2] = fmaf(basis, v1.x, a[2]); a[3] = fmaf(basis, v1.y, a[3]);
        a[4] = fmaf(basis, v2.x, a[4]); a[5] = fmaf(basis, v2.y, a[5]);
        a[6] = fmaf(basis, v3.x, a[6]); a[7] = fmaf(basis, v3.y, a[7]);
    }
#pragma unroll
    for (int i = 0; i < 8; i++)
        a[i] += __shfl_xor_sync(0xffffffffu, a[i], 16);
    float* P = pool();
    if (half == 0) {
        redAdd4(P + aggoff + dst * 128 + 8 * l16,     a[0], a[1], a[2], a[3]);
        redAdd4(P + aggoff + dst * 128 + 8 * l16 + 4, a[4], a[5], a[6], a[7]);
    }
    if (lane == 0) atomicAdd(P + degoff + dst, 1.0f);
}

// ---------------- node update + fused seg-max into next H ----------------
__global__ void node_dense(int hoff, int aggoff, int degoff, const int* __restrict__ cl,
                           int outoff, const float* __restrict__ root,
                           const float* __restrict__ bias, int ntot, int shift) {
    int t = blockIdx.x * blockDim.x + threadIdx.x;
    if (t >= ntot) return;
    int n = t >> shift;
    int o = t & ((1 << shift) - 1);
    float* P = pool();
    const float* h = P + hoff + n * 64;
    float acc = bias[o] + P[aggoff + t] / fmaxf(P[degoff + n], 1.0f);
#pragma unroll 16
    for (int i = 0; i < 64; i++)
        acc = fmaf(fixf(h[i]), root[(i << shift) + o], acc);
    atomicMaxFloat(P + outoff + (cl[n] << shift) + o, eluf(acc));
}

// ---------------- final MLP + log_softmax ----------------
__global__ void fc_kernel(const float* __restrict__ w1, const float* __restrict__ b1,
                          const float* __restrict__ w2, const float* __restrict__ b2,
                          float* __restrict__ out) {
    __shared__ float xrow[1024];
    __shared__ float hrow[256];
    __shared__ float logits[10];
    __shared__ float red[2];
    int b = blockIdx.x;
    int t = threadIdx.x;
    float* P = pool();
    for (int i = t; i < 1024; i += 256) xrow[i] = fixf(P[O_H4 + b * 1024 + i]);
    __syncthreads();

    float a0 = b1[t], a1 = 0.f, a2 = 0.f, a3 = 0.f;
#pragma unroll 4
    for (int i = 0; i < 1024; i += 4) {
        a0 = fmaf(xrow[i + 0], w1[(i + 0) * 256 + t], a0);
        a1 = fmaf(xrow[i + 1], w1[(i + 1) * 256 + t], a1);
        a2 = fmaf(xrow[i + 2], w1[(i + 2) * 256 + t], a2);
        a3 = fmaf(xrow[i + 3], w1[(i + 3) * 256 + t], a3);
    }
    hrow[t] = eluf((a0 + a1) + (a2 + a3));
    __syncthreads();

    if (t < 10) {
        float a = b2[t];
#pragma unroll 8
        for (int i = 0; i < 256; i++)
            a = fmaf(hrow[i], w2[i * 10 + t], a);
        logits[t] = a;
    }
    __syncthreads();
    if (t == 0) {
        float m = logits[0];
        for (int j = 1; j < 10; j++) m = fmaxf(m, logits[j]);
        float s = 0.0f;
        for (int j = 0; j < 10; j++) s += expf(logits[j] - m);
        red[0] = m;
        red[1] = logf(s);
    }
    __syncthreads();
    if (t < 10) out[b * 10 + t] = logits[t] - red[0] - red[1];
}

// ---------------- host ----------------
extern "C" void kernel_launch(void* const* d_in, const int* in_sizes, int n_in,
                              void* d_out, int out_size) {
    const float* x0      = (const float*)d_in[0];
    const int*   cl0     = (const int*)  d_in[1];
    const int*   edge1   = (const int*)  d_in[2];
    const float* pseudo1 = (const float*)d_in[3];
    const float* W1      = (const float*)d_in[4];
    const float* root1   = (const float*)d_in[5];
    const float* b1      = (const float*)d_in[6];
    const int*   cl1     = (const int*)  d_in[7];
    const int*   edge2   = (const int*)  d_in[8];
    const float* pseudo2 = (const float*)d_in[9];
    const float* W2      = (const float*)d_in[10];
    const float* root2   = (const float*)d_in[11];
    const float* b2      = (const float*)d_in[12];
    const int*   cl2     = (const int*)  d_in[13];
    const int*   edge3   = (const int*)  d_in[14];
    const float* pseudo3 = (const float*)d_in[15];
    const float* W3      = (const float*)d_in[16];
    const float* root3   = (const float*)d_in[17];
    const float* b3      = (const float*)d_in[18];
    const int*   cl3     = (const int*)  d_in[19];
    const float* fc1w    = (const float*)d_in[20];
    const float* fc1b    = (const float*)d_in[21];
    const float* fc2w    = (const float*)d_in[22];
    const float* fc2b    = (const float*)d_in[23];
    float* out = (float*)d_out;

    const int TB = 256;

    uint8_t* xw2q; __half2* xw3h; __half2* w1h; __half2* w2h; __half2* w3h;
    cudaGetSymbolAddress((void**)&xw2q, g_xw2q4);
    cudaGetSymbolAddress((void**)&xw3h, g_xw3h4);
    cudaGetSymbolAddress((void**)&w1h, g_w1h4);
    cudaGetSymbolAddress((void**)&w2h, g_w2h4);
    cudaGetSymbolAddress((void**)&w3h, g_w3h4);

    const int SM64  = 18432 + 2 * 64 * 144;   // 36864
    const int SM128 = 18432 + 2 * 128 * 144;  // 55296
    const int SML1  = 32 * 136 * 2 + 64 * 136 * 2;  // 26112
    cudaFuncSetAttribute((const void*)gemm_mma<64, 5, true>,
                         cudaFuncAttributeMaxDynamicSharedMemorySize, SM64);
    cudaFuncSetAttribute((const void*)gemm_mma<128, 5, false>,
                         cudaFuncAttributeMaxDynamicSharedMemorySize, SM128);
    cudaFuncSetAttribute((const void*)l1_gemm_mma,
                         cudaFuncAttributeMaxDynamicSharedMemorySize, SML1);

    // 1: init + W conversion
    init_and_convert<<<1024, TB>>>(W1, W2, W3, w1h, w2h, w3h);
    // 2: seg_max(x0) -> H1
    segmax_x0_kernel<<<CDIV(cN0, TB), TB>>>(x0, cl0);
    // 3: layer-1 scatter (f16x2 atomics)
    l1_scatter<<<CDIV(cE1, TB), TB>>>(edge1, pseudo1);
    // 4: layer-1 mma GEMM + node update + seg-max -> H2 (profile slot)
    l1_gemm_mma<<<CDIV(cN1, 32), 256, SML1>>>(w1h, root1, b1, cl1);
    // 5: layer-2 tensor-core GEMM -> XW2 (fp8)
    {
        dim3 g(CDIV(cN2, 128), 25);
        gemm_mma<64, 5, true><<<g, 256, SM64>>>(O_H2, w2h, xw2q, cN2);
    }
    // 6: layer-2 gather (fp8)
    gather_64<<<CDIV(cE2 * 32, TB), TB>>>(edge2, cE2, pseudo2, xw2q, cN2, O_AGG2, O_DEG2);
    // 7: layer-2 node update + seg-max -> H3
    node_dense<<<CDIV(cN2 * 64, TB), TB>>>(O_H2, O_AGG2, O_DEG2, cl2, O_H3, root2, b2, cN2 * 64, 6);
    // 8: layer-3 tensor-core GEMM -> XW3 (f16)
    {
        dim3 g(CDIV(cN3, 128), 25);
        gemm_mma<128, 5, false><<<g, 256, SM128>>>(O_H3, w3h, xw3h, cN3);
    }
    // 9: layer-3 gather
    gather_128<<<CDIV(cE3 * 32, TB), TB>>>(edge3, cE3, pseudo3, xw3h, cN3, O_AGG3, O_DEG3);
    // 10: layer-3 node update + seg-max -> H4
    node_dense<<<CDIV(cN3 * 128, TB), TB>>>(O_H3, O_AGG3, O_DEG3, cl3, O_H4, root3, b3, cN3 * 128, 7);
    // 11: MLP head + log_softmax
    fc_kernel<<<cB, 256>>>(fc1w, fc1b, fc2w, fc2b, out);
}